// round 1
// baseline (speedup 1.0000x reference)
#include <cuda_runtime.h>
#include <math.h>

#define TOKENS 4096
#define DIM    1024
#define SEQ    2048
#define NH     16
#define NKV    4
#define HD     64
#define HIDDEN 3072
#define NE     4
#define RMS_EPS 1.1920928955078125e-07f

// ---------------- scratch (device globals; no allocation allowed) ----------
__device__ float g_xn [TOKENS * DIM];          // rmsnorm output (reused twice)
__device__ float g_q  [TOKENS * DIM];
__device__ float g_k  [TOKENS * NKV * HD];
__device__ float g_v  [TOKENS * NKV * HD];
__device__ float g_att[TOKENS * DIM];
__device__ float g_h  [TOKENS * HIDDEN];       // expert hidden (per-expert reuse)
__device__ int   g_cnt[NE];
__device__ int   g_idx[NE * TOKENS];
__device__ float g_wgt[NE * TOKENS];

// ---------------- tiny init ------------------------------------------------
__global__ void zero_cnt_kernel() {
    if (threadIdx.x < NE) g_cnt[threadIdx.x] = 0;
}

// ---------------- RMSNorm: one block per token ------------------------------
__global__ void rmsnorm_kernel(const float* __restrict__ x,
                               const float* __restrict__ g,
                               float* __restrict__ o) {
    int t = blockIdx.x;
    int tid = threadIdx.x;
    const float* xr = x + (size_t)t * DIM;
    float ss = 0.f;
    for (int i = tid; i < DIM; i += 256) { float v = xr[i]; ss += v * v; }
    #pragma unroll
    for (int o2 = 16; o2; o2 >>= 1) ss += __shfl_xor_sync(0xffffffffu, ss, o2);
    __shared__ float sw[8];
    if ((tid & 31) == 0) sw[tid >> 5] = ss;
    __syncthreads();
    if (tid < 8) {
        float v = sw[tid];
        #pragma unroll
        for (int o2 = 4; o2; o2 >>= 1) v += __shfl_xor_sync(0xffu, v, o2);
        if (tid == 0) sw[0] = v;
    }
    __syncthreads();
    float r = rsqrtf(sw[0] * (1.0f / DIM) + RMS_EPS);
    float* orow = o + (size_t)t * DIM;
    for (int i = tid; i < DIM; i += 256) orow[i] = xr[i] * r * g[i];
}

// ---------------- generic tiled SGEMM (128x128x8, 256 thr, 8x8/thread) -----
// epi: 0 = C=acc ; 1 = C=acc+R ; 2 = C=silu(C)*acc ; 3 = C[idx[r]] += acc*wgt[r]
// gatherA: A row r comes from gidx[r]
__global__ void __launch_bounds__(256, 2)
sgemm_kernel(const float* __restrict__ A, const float* __restrict__ B,
             float* __restrict__ C, const float* __restrict__ R,
             int M, int N, int K,
             const int* __restrict__ cnt,
             const int* __restrict__ gidx, const float* __restrict__ gwgt,
             int epi, int gatherA) {
    int Meff = cnt ? *cnt : M;
    int rowBase = blockIdx.y * 128;
    if (rowBase >= Meff) return;

    __shared__ float As[8][128];
    __shared__ float Bs[8][128];

    int tid = threadIdx.x;
    int nBase = blockIdx.x * 128;

    // A tile loader: each thread loads one float4 per K-step
    int arow = rowBase + (tid >> 1);
    bool aok = arow < Meff;
    long asrc = 0;
    if (aok) asrc = gatherA ? (long)gidx[arow] : (long)arow;
    const float* Arow = A + asrc * (size_t)K + ((tid & 1) << 2);
    int ak = (tid & 1) << 2;
    int am = tid >> 1;

    // B tile loader
    const float* Bp = B + (size_t)(tid >> 5) * N + nBase + ((tid & 31) << 2);

    int my = (tid >> 4) << 3;
    int mx = (tid & 15) << 3;

    float acc[8][8];
    #pragma unroll
    for (int i = 0; i < 8; i++)
        #pragma unroll
        for (int j = 0; j < 8; j++) acc[i][j] = 0.f;

    for (int kt = 0; kt < K; kt += 8) {
        float4 av = make_float4(0.f, 0.f, 0.f, 0.f);
        if (aok) av = *(const float4*)(Arow + kt);
        float4 bv = *(const float4*)(Bp + (size_t)kt * N);
        As[ak + 0][am] = av.x; As[ak + 1][am] = av.y;
        As[ak + 2][am] = av.z; As[ak + 3][am] = av.w;
        *(float4*)&Bs[tid >> 5][(tid & 31) << 2] = bv;
        __syncthreads();
        #pragma unroll
        for (int kk = 0; kk < 8; kk++) {
            float a[8], b[8];
            #pragma unroll
            for (int i = 0; i < 8; i++) { a[i] = As[kk][my + i]; b[i] = Bs[kk][mx + i]; }
            #pragma unroll
            for (int i = 0; i < 8; i++)
                #pragma unroll
                for (int j = 0; j < 8; j++) acc[i][j] = fmaf(a[i], b[j], acc[i][j]);
        }
        __syncthreads();
    }

    #pragma unroll
    for (int i = 0; i < 8; i++) {
        int r = rowBase + my + i;
        if (r >= Meff) break;
        if (epi == 3) {
            int tok = gidx[r];
            float w = gwgt[r];
            float* crow = C + (size_t)tok * N + nBase + mx;
            #pragma unroll
            for (int j = 0; j < 8; j++) crow[j] += acc[i][j] * w;
        } else {
            float* crow = C + (size_t)r * N + nBase + mx;
            if (epi == 0) {
                #pragma unroll
                for (int j = 0; j < 8; j++) crow[j] = acc[i][j];
            } else if (epi == 1) {
                const float* rr = R + (size_t)r * N + nBase + mx;
                #pragma unroll
                for (int j = 0; j < 8; j++) crow[j] = acc[i][j] + rr[j];
            } else { // epi == 2: silu(existing) * acc
                #pragma unroll
                for (int j = 0; j < 8; j++) {
                    float t1 = crow[j];
                    float s = t1 / (1.f + expf(-t1));
                    crow[j] = s * acc[i][j];
                }
            }
        }
    }
}

// ---------------- RoPE on q and k (in place) --------------------------------
__global__ void rope_kernel(float* __restrict__ q, float* __restrict__ k) {
    int id = blockIdx.x * blockDim.x + threadIdx.x;
    const int NQ = TOKENS * NH * 32;
    const int NK2 = TOKENS * NKV * 32;
    if (id >= NQ + NK2) return;
    float* base; int t, i;
    if (id < NQ) {
        t = id >> 9; int r = id & 511; int h = r >> 5; i = r & 31;
        base = q + ((size_t)t * NH + h) * HD;
    } else {
        int id2 = id - NQ;
        t = id2 >> 7; int r = id2 & 127; int h = r >> 5; i = r & 31;
        base = k + ((size_t)t * NKV + h) * HD;
    }
    int pos = t & (SEQ - 1);
    // inv_freq[i] = 10000^(-i/32) ; log2(10000)/32 = 0.4152410118609203
    float inv = exp2f(-(float)i * 0.4152410118609203f);
    float fr = (float)pos * inv;
    float sn, cs;
    sincosf(fr, &sn, &cs);
    float x1 = base[i], x2 = base[i + 32];
    base[i]      = x1 * cs - x2 * sn;
    base[i + 32] = x2 * cs + x1 * sn;
}

// ---------------- causal attention: one warp per query row ------------------
__global__ void attn_kernel(const float* __restrict__ q, const float* __restrict__ k,
                            const float* __restrict__ v, float* __restrict__ o) {
    int gw = (int)((blockIdx.x * (size_t)blockDim.x + threadIdx.x) >> 5);
    int lane = threadIdx.x & 31;
    if (gw >= 2 * NH * SEQ) return;
    int qi = gw & (SEQ - 1);
    int h  = (gw >> 11) & (NH - 1);
    int b  = gw >> 15;
    int hk = h >> 2;

    const float2* qp = (const float2*)(q + ((size_t)(b * SEQ + qi) * NH + h) * HD);
    float2 qv = qp[lane];
    const float scale = 0.125f;  // 1/sqrt(64)

    const size_t kvstride = (size_t)NKV * HD;
    const float* kb = k + (size_t)b * SEQ * kvstride + (size_t)hk * HD;
    const float* vb = v + (size_t)b * SEQ * kvstride + (size_t)hk * HD;

    float m = -3.0e38f, l = 0.f, ax = 0.f, ay = 0.f;
    for (int j = 0; j <= qi; j++) {
        float2 kv = ((const float2*)(kb + (size_t)j * kvstride))[lane];
        float s = qv.x * kv.x + qv.y * kv.y;
        #pragma unroll
        for (int o2 = 16; o2; o2 >>= 1) s += __shfl_xor_sync(0xffffffffu, s, o2);
        s *= scale;
        float mn = fmaxf(m, s);
        float corr = __expf(m - mn);
        float p = __expf(s - mn);
        float2 vv = ((const float2*)(vb + (size_t)j * kvstride))[lane];
        l  = l * corr + p;
        ax = ax * corr + p * vv.x;
        ay = ay * corr + p * vv.y;
        m = mn;
    }
    float invl = 1.f / l;
    float2* op = (float2*)(o + ((size_t)(b * SEQ + qi) * NH + h) * HD);
    op[lane] = make_float2(ax * invl, ay * invl);
}

// ---------------- MoE gating: one warp per token -----------------------------
__global__ void gate_kernel(const float* __restrict__ xn, const float* __restrict__ gate) {
    int gw = (int)((blockIdx.x * (size_t)blockDim.x + threadIdx.x) >> 5);
    int lane = threadIdx.x & 31;
    if (gw >= TOKENS) return;
    const float* xr = xn + (size_t)gw * DIM;
    float a0 = 0.f, a1 = 0.f, a2 = 0.f, a3 = 0.f;
    for (int i = lane; i < DIM; i += 32) {
        float xv = xr[i];
        const float* gr = gate + (size_t)i * NE;
        a0 += xv * gr[0]; a1 += xv * gr[1]; a2 += xv * gr[2]; a3 += xv * gr[3];
    }
    #pragma unroll
    for (int o2 = 16; o2; o2 >>= 1) {
        a0 += __shfl_xor_sync(0xffffffffu, a0, o2);
        a1 += __shfl_xor_sync(0xffffffffu, a1, o2);
        a2 += __shfl_xor_sync(0xffffffffu, a2, o2);
        a3 += __shfl_xor_sync(0xffffffffu, a3, o2);
    }
    if (lane == 0) {
        float p[NE] = {a0, a1, a2, a3};
        float mx = p[0];
        #pragma unroll
        for (int e = 1; e < NE; e++) mx = fmaxf(mx, p[e]);
        #pragma unroll
        for (int e = 0; e < NE; e++) p[e] = __expf(p[e] - mx);
        // top-2 on exponentials (monotone in logits); ties -> lower index first
        int e0 = 0;
        #pragma unroll
        for (int e = 1; e < NE; e++) if (p[e] > p[e0]) e0 = e;
        int e1 = -1;
        #pragma unroll
        for (int e = 0; e < NE; e++) if (e != e0 && (e1 < 0 || p[e] > p[e1])) e1 = e;
        float w0 = p[e0], w1 = p[e1];
        float ws = w0 + w1;
        w0 /= ws; w1 /= ws;
        int s0 = atomicAdd(&g_cnt[e0], 1);
        g_idx[e0 * TOKENS + s0] = gw; g_wgt[e0 * TOKENS + s0] = w0;
        int s1 = atomicAdd(&g_cnt[e1], 1);
        g_idx[e1 * TOKENS + s1] = gw; g_wgt[e1 * TOKENS + s1] = w1;
    }
}

// ---------------- launch ------------------------------------------------------
static inline void launch_gemm(const float* A, const float* B, float* C, const float* R,
                               int M, int N, int K,
                               const int* cnt, const int* gi, const float* gw,
                               int epi, int gat) {
    dim3 grid(N / 128, (M + 127) / 128);
    sgemm_kernel<<<grid, 256>>>(A, B, C, R, M, N, K, cnt, gi, gw, epi, gat);
}

extern "C" void kernel_launch(void* const* d_in, const int* in_sizes, int n_in,
                              void* d_out, int out_size) {
    const float* x    = (const float*)d_in[0];
    const float* g1   = (const float*)d_in[1];
    const float* g2   = (const float*)d_in[2];
    const float* wq   = (const float*)d_in[3];
    const float* wk   = (const float*)d_in[4];
    const float* wv   = (const float*)d_in[5];
    const float* wo   = (const float*)d_in[6];
    const float* gate = (const float*)d_in[7];
    const float* w1   = (const float*)d_in[8];
    const float* w2   = (const float*)d_in[9];
    const float* w3   = (const float*)d_in[10];
    float* out = (float*)d_out;

    float *xn, *q, *k, *v, *att, *h, *wgt;
    int *cnt, *idx;
    cudaGetSymbolAddress((void**)&xn,  g_xn);
    cudaGetSymbolAddress((void**)&q,   g_q);
    cudaGetSymbolAddress((void**)&k,   g_k);
    cudaGetSymbolAddress((void**)&v,   g_v);
    cudaGetSymbolAddress((void**)&att, g_att);
    cudaGetSymbolAddress((void**)&h,   g_h);
    cudaGetSymbolAddress((void**)&cnt, g_cnt);
    cudaGetSymbolAddress((void**)&idx, g_idx);
    cudaGetSymbolAddress((void**)&wgt, g_wgt);

    zero_cnt_kernel<<<1, 32>>>();

    // ---- attention branch ----
    rmsnorm_kernel<<<TOKENS, 256>>>(x, g1, xn);
    launch_gemm(xn, wq, q, nullptr, TOKENS, NH * HD,  DIM, nullptr, nullptr, nullptr, 0, 0);
    launch_gemm(xn, wk, k, nullptr, TOKENS, NKV * HD, DIM, nullptr, nullptr, nullptr, 0, 0);
    launch_gemm(xn, wv, v, nullptr, TOKENS, NKV * HD, DIM, nullptr, nullptr, nullptr, 0, 0);

    int ropeN = TOKENS * NH * 32 + TOKENS * NKV * 32;
    rope_kernel<<<(ropeN + 255) / 256, 256>>>(q, k);

    attn_kernel<<<(2 * NH * SEQ) / 8, 256>>>(q, k, v, att);

    // out = x + att @ wo
    launch_gemm(att, wo, out, x, TOKENS, DIM, DIM, nullptr, nullptr, nullptr, 1, 0);

    // ---- MoE branch ----
    rmsnorm_kernel<<<TOKENS, 256>>>(out, g2, xn);
    gate_kernel<<<TOKENS / 8, 256>>>(xn, gate);

    for (int e = 0; e < NE; e++) {
        const int*   ce = cnt + e;
        const int*   ie = idx + e * TOKENS;
        const float* we = wgt + e * TOKENS;
        // h = A@w1[e]
        launch_gemm(xn, w1 + (size_t)e * DIM * HIDDEN, h, nullptr,
                    TOKENS, HIDDEN, DIM, ce, ie, nullptr, 0, 1);
        // h = silu(h) * (A@w3[e])
        launch_gemm(xn, w3 + (size_t)e * DIM * HIDDEN, h, nullptr,
                    TOKENS, HIDDEN, DIM, ce, ie, nullptr, 2, 1);
        // out[tok] += (h @ w2[e]) * wgt
        launch_gemm(h, w2 + (size_t)e * HIDDEN * DIM, out, nullptr,
                    TOKENS, DIM, HIDDEN, ce, ie, we, 3, 0);
    }
}

// round 3
// speedup vs baseline: 2.1288x; 2.1288x over previous
#include <cuda_runtime.h>
#include <math.h>

#define TOKENS 4096
#define DIM    1024
#define SEQ    2048
#define NH     16
#define NKV    4
#define HD     64
#define HIDDEN 3072
#define NE     4
#define RMS_EPS 1.1920928955078125e-07f

// ---------------- scratch (device globals; no allocation allowed) ----------
__device__ float g_xn [TOKENS * DIM];
__device__ float g_q  [TOKENS * DIM];
__device__ float g_k  [TOKENS * NKV * HD];
__device__ float g_v  [TOKENS * NKV * HD];
__device__ float g_att[TOKENS * DIM];
__device__ float g_h  [TOKENS * HIDDEN];
__device__ int   g_cnt[NE];
__device__ int   g_idx[NE * TOKENS];
__device__ float g_wgt[NE * TOKENS];

__device__ __forceinline__ float tf32_rna(float x) {
    unsigned u;
    asm("cvt.rna.tf32.f32 %0, %1;" : "=r"(u) : "f"(x));
    return __uint_as_float(u);
}

__global__ void zero_cnt_kernel() {
    if (threadIdx.x < NE) g_cnt[threadIdx.x] = 0;
}

// ---------------- RMSNorm: one block per token (stores tf32-rounded) -------
__global__ void rmsnorm_kernel(const float* __restrict__ x,
                               const float* __restrict__ g,
                               float* __restrict__ o) {
    int t = blockIdx.x;
    int tid = threadIdx.x;
    const float* xr = x + (size_t)t * DIM;
    float ss = 0.f;
    for (int i = tid; i < DIM; i += 256) { float v = xr[i]; ss += v * v; }
    #pragma unroll
    for (int o2 = 16; o2; o2 >>= 1) ss += __shfl_xor_sync(0xffffffffu, ss, o2);
    __shared__ float sw[8];
    if ((tid & 31) == 0) sw[tid >> 5] = ss;
    __syncthreads();
    if (tid < 8) {
        float v = sw[tid];
        #pragma unroll
        for (int o2 = 4; o2; o2 >>= 1) v += __shfl_xor_sync(0xffu, v, o2);
        if (tid == 0) sw[0] = v;
    }
    __syncthreads();
    float r = rsqrtf(sw[0] * (1.0f / DIM) + RMS_EPS);
    float* orow = o + (size_t)t * DIM;
    for (int i = tid; i < DIM; i += 256) orow[i] = tf32_rna(xr[i] * r * g[i]);
}

// ---------------- tf32 tensor-core GEMM -------------------------------------
// 128x128x16 CTA tile, 256 threads = 8 warps, warp tile 64x32 (m16n8k8 mma).
// epi: 0 = C=acc ; 1 = C=acc+R ; 2 = C=tf32(silu(C)*acc) ; 3 = C[idx[r]] += acc*wgt[r]
#define BM 128
#define BN 128
#define BK 16
#define SA 20
#define SB 136

__device__ __forceinline__ void mma_tf32(float c[4], unsigned a0, unsigned a1,
                                         unsigned a2, unsigned a3,
                                         unsigned b0, unsigned b1) {
    asm volatile(
        "mma.sync.aligned.m16n8k8.row.col.f32.tf32.tf32.f32 "
        "{%0,%1,%2,%3}, {%4,%5,%6,%7}, {%8,%9}, {%0,%1,%2,%3};"
        : "+f"(c[0]), "+f"(c[1]), "+f"(c[2]), "+f"(c[3])
        : "r"(a0), "r"(a1), "r"(a2), "r"(a3), "r"(b0), "r"(b1));
}

__global__ void __launch_bounds__(256, 2)
mma_gemm_kernel(const float* __restrict__ A, const float* __restrict__ B,
                float* __restrict__ C, const float* __restrict__ R,
                int M, int N, int K,
                const int* __restrict__ cnt,
                const int* __restrict__ gidx, const float* __restrict__ gwgt,
                int epi, int gatherA) {
    int Meff = cnt ? *cnt : M;
    int rowBase = blockIdx.y * BM;
    if (rowBase >= Meff) return;

    __shared__ float As[BM][SA];
    __shared__ float Bs[BK][SB];

    int tid  = threadIdx.x;
    int lane = tid & 31;
    int wid  = tid >> 5;
    int wm   = wid & 1;   // 0..1 -> 64 rows each
    int wn   = wid >> 1;  // 0..3 -> 32 cols each
    int nBase = blockIdx.x * BN;

    float acc[4][4][4];
    #pragma unroll
    for (int i = 0; i < 4; i++)
        #pragma unroll
        for (int j = 0; j < 4; j++)
            #pragma unroll
            for (int q = 0; q < 4; q++) acc[i][j][q] = 0.f;

    // global loaders: 2 stages of 256 threads each cover a 128x16 A tile and
    // 16x128 B tile as float4s
    const float* aptr[2]; bool aok[2];
    const float* bptr[2];
    #pragma unroll
    for (int s = 0; s < 2; s++) {
        int fid = tid + s * 256;
        int row = rowBase + (fid >> 2);
        bool ok = row < Meff;
        long src = 0;
        if (ok) src = gatherA ? (long)gidx[row] : (long)row;
        aptr[s] = A + src * (size_t)K + ((fid & 3) << 2);
        aok[s] = ok;
        bptr[s] = B + (size_t)(fid >> 5) * N + nBase + ((fid & 31) << 2);
    }

    float4 a_st[2], b_st[2];
    #pragma unroll
    for (int s = 0; s < 2; s++) {
        a_st[s] = aok[s] ? *(const float4*)(aptr[s]) : make_float4(0.f, 0.f, 0.f, 0.f);
        b_st[s] = *(const float4*)(bptr[s]);
    }

    for (int kt = 0; kt < K; kt += BK) {
        #pragma unroll
        for (int s = 0; s < 2; s++) {
            int fid = tid + s * 256;
            *(float4*)&As[fid >> 2][(fid & 3) << 2] = a_st[s];
            *(float4*)&Bs[fid >> 5][(fid & 31) << 2] = b_st[s];
        }
        __syncthreads();
        if (kt + BK < K) {
            #pragma unroll
            for (int s = 0; s < 2; s++) {
                a_st[s] = aok[s] ? *(const float4*)(aptr[s] + kt + BK)
                                 : make_float4(0.f, 0.f, 0.f, 0.f);
                b_st[s] = *(const float4*)(bptr[s] + (size_t)(kt + BK) * N);
            }
        }
        int r = lane >> 2, c = lane & 3;
        #pragma unroll
        for (int ks = 0; ks < BK; ks += 8) {
            unsigned bf[4][2];
            #pragma unroll
            for (int j = 0; j < 4; j++) {
                int nC = wn * 32 + j * 8 + r;
                bf[j][0] = __float_as_uint(Bs[ks + c][nC]);
                bf[j][1] = __float_as_uint(Bs[ks + c + 4][nC]);
            }
            #pragma unroll
            for (int i = 0; i < 4; i++) {
                int mR = wm * 64 + i * 16 + r;
                unsigned a0 = __float_as_uint(As[mR][ks + c]);
                unsigned a1 = __float_as_uint(As[mR + 8][ks + c]);
                unsigned a2 = __float_as_uint(As[mR][ks + c + 4]);
                unsigned a3 = __float_as_uint(As[mR + 8][ks + c + 4]);
                #pragma unroll
                for (int j = 0; j < 4; j++)
                    mma_tf32(acc[i][j], a0, a1, a2, a3, bf[j][0], bf[j][1]);
            }
        }
        __syncthreads();
    }

    // epilogue
    int r = lane >> 2, c = lane & 3;
    #pragma unroll
    for (int i = 0; i < 4; i++) {
        int rbase = rowBase + wm * 64 + i * 16 + r;
        #pragma unroll
        for (int half = 0; half < 2; half++) {
            int rr = rbase + half * 8;
            if (rr >= Meff) continue;
            int tok = 0; float w = 0.f;
            if (epi == 3) { tok = gidx[rr]; w = gwgt[rr]; }
            #pragma unroll
            for (int j = 0; j < 4; j++) {
                int col = nBase + wn * 32 + j * 8 + (c << 1);
                float v0 = acc[i][j][half * 2];
                float v1 = acc[i][j][half * 2 + 1];
                if (epi == 0) {
                    *(float2*)(C + (size_t)rr * N + col) = make_float2(v0, v1);
                } else if (epi == 1) {
                    float2 rv = *(const float2*)(R + (size_t)rr * N + col);
                    *(float2*)(C + (size_t)rr * N + col) =
                        make_float2(v0 + rv.x, v1 + rv.y);
                } else if (epi == 2) {
                    float2 hv = *(float2*)(C + (size_t)rr * N + col);
                    float s0 = hv.x / (1.f + __expf(-hv.x));
                    float s1 = hv.y / (1.f + __expf(-hv.y));
                    *(float2*)(C + (size_t)rr * N + col) =
                        make_float2(tf32_rna(s0 * v0), tf32_rna(s1 * v1));
                } else {
                    float2* cp = (float2*)(C + (size_t)tok * N + col);
                    float2 cv = *cp;
                    cv.x += v0 * w; cv.y += v1 * w;
                    *cp = cv;
                }
            }
        }
    }
}

// ---------------- RoPE on q and k (in place) --------------------------------
__global__ void rope_kernel(float* __restrict__ q, float* __restrict__ k) {
    int id = blockIdx.x * blockDim.x + threadIdx.x;
    const int NQ = TOKENS * NH * 32;
    const int NK2 = TOKENS * NKV * 32;
    if (id >= NQ + NK2) return;
    float* base; int t, i;
    if (id < NQ) {
        t = id >> 9; int r = id & 511; int h = r >> 5; i = r & 31;
        base = q + ((size_t)t * NH + h) * HD;
    } else {
        int id2 = id - NQ;
        t = id2 >> 7; int r = id2 & 127; int h = r >> 5; i = r & 31;
        base = k + ((size_t)t * NKV + h) * HD;
    }
    int pos = t & (SEQ - 1);
    float inv = exp2f(-(float)i * 0.4152410118609203f);
    float fr = (float)pos * inv;
    float sn, cs;
    sincosf(fr, &sn, &cs);
    float x1 = base[i], x2 = base[i + 32];
    base[i]      = x1 * cs - x2 * sn;
    base[i + 32] = x2 * cs + x1 * sn;
}

// ---------------- causal attention: one warp per query row (2x unrolled) ----
__global__ void attn_kernel(const float* __restrict__ q, const float* __restrict__ k,
                            const float* __restrict__ v, float* __restrict__ o) {
    int gw = (int)((blockIdx.x * (size_t)blockDim.x + threadIdx.x) >> 5);
    int lane = threadIdx.x & 31;
    if (gw >= 2 * NH * SEQ) return;
    int qi = gw & (SEQ - 1);
    int h  = (gw >> 11) & (NH - 1);
    int b  = gw >> 15;
    int hk = h >> 2;

    const float2* qp = (const float2*)(q + ((size_t)(b * SEQ + qi) * NH + h) * HD);
    float2 qv = qp[lane];
    const float scale = 0.125f;

    const size_t kvstride = (size_t)NKV * HD;
    const float* kb = k + (size_t)b * SEQ * kvstride + (size_t)hk * HD;
    const float* vb = v + (size_t)b * SEQ * kvstride + (size_t)hk * HD;

    float m = -3.0e38f, l = 0.f, ax = 0.f, ay = 0.f;
    int j = 0;
    for (; j + 1 <= qi; j += 2) {
        float2 k0 = ((const float2*)(kb + (size_t)j * kvstride))[lane];
        float2 k1 = ((const float2*)(kb + (size_t)(j + 1) * kvstride))[lane];
        float s0 = qv.x * k0.x + qv.y * k0.y;
        float s1 = qv.x * k1.x + qv.y * k1.y;
        #pragma unroll
        for (int o2 = 16; o2; o2 >>= 1) {
            s0 += __shfl_xor_sync(0xffffffffu, s0, o2);
            s1 += __shfl_xor_sync(0xffffffffu, s1, o2);
        }
        s0 *= scale; s1 *= scale;
        float mn = fmaxf(m, fmaxf(s0, s1));
        float corr = __expf(m - mn);
        float p0 = __expf(s0 - mn);
        float p1 = __expf(s1 - mn);
        float2 v0 = ((const float2*)(vb + (size_t)j * kvstride))[lane];
        float2 v1 = ((const float2*)(vb + (size_t)(j + 1) * kvstride))[lane];
        l  = l * corr + p0 + p1;
        ax = ax * corr + p0 * v0.x + p1 * v1.x;
        ay = ay * corr + p0 * v0.y + p1 * v1.y;
        m = mn;
    }
    for (; j <= qi; j++) {
        float2 kv = ((const float2*)(kb + (size_t)j * kvstride))[lane];
        float s = qv.x * kv.x + qv.y * kv.y;
        #pragma unroll
        for (int o2 = 16; o2; o2 >>= 1) s += __shfl_xor_sync(0xffffffffu, s, o2);
        s *= scale;
        float mn = fmaxf(m, s);
        float corr = __expf(m - mn);
        float p = __expf(s - mn);
        float2 vv = ((const float2*)(vb + (size_t)j * kvstride))[lane];
        l  = l * corr + p;
        ax = ax * corr + p * vv.x;
        ay = ay * corr + p * vv.y;
        m = mn;
    }
    float invl = 1.f / l;
    float2* op = (float2*)(o + ((size_t)(b * SEQ + qi) * NH + h) * HD);
    op[lane] = make_float2(tf32_rna(ax * invl), tf32_rna(ay * invl));
}

// ---------------- MoE gating: one warp per token -----------------------------
__global__ void gate_kernel(const float* __restrict__ xn, const float* __restrict__ gate) {
    int gw = (int)((blockIdx.x * (size_t)blockDim.x + threadIdx.x) >> 5);
    int lane = threadIdx.x & 31;
    if (gw >= TOKENS) return;
    const float* xr = xn + (size_t)gw * DIM;
    float a0 = 0.f, a1 = 0.f, a2 = 0.f, a3 = 0.f;
    for (int i = lane; i < DIM; i += 32) {
        float xv = xr[i];
        const float* gr = gate + (size_t)i * NE;
        a0 += xv * gr[0]; a1 += xv * gr[1]; a2 += xv * gr[2]; a3 += xv * gr[3];
    }
    #pragma unroll
    for (int o2 = 16; o2; o2 >>= 1) {
        a0 += __shfl_xor_sync(0xffffffffu, a0, o2);
        a1 += __shfl_xor_sync(0xffffffffu, a1, o2);
        a2 += __shfl_xor_sync(0xffffffffu, a2, o2);
        a3 += __shfl_xor_sync(0xffffffffu, a3, o2);
    }
    if (lane == 0) {
        float p[NE] = {a0, a1, a2, a3};
        float mx = p[0];
        #pragma unroll
        for (int e = 1; e < NE; e++) mx = fmaxf(mx, p[e]);
        #pragma unroll
        for (int e = 0; e < NE; e++) p[e] = __expf(p[e] - mx);
        int e0 = 0;
        #pragma unroll
        for (int e = 1; e < NE; e++) if (p[e] > p[e0]) e0 = e;
        int e1 = -1;
        #pragma unroll
        for (int e = 0; e < NE; e++) if (e != e0 && (e1 < 0 || p[e] > p[e1])) e1 = e;
        float w0 = p[e0], w1 = p[e1];
        float ws = w0 + w1;
        w0 /= ws; w1 /= ws;
        int s0 = atomicAdd(&g_cnt[e0], 1);
        g_idx[e0 * TOKENS + s0] = gw; g_wgt[e0 * TOKENS + s0] = w0;
        int s1 = atomicAdd(&g_cnt[e1], 1);
        g_idx[e1 * TOKENS + s1] = gw; g_wgt[e1 * TOKENS + s1] = w1;
    }
}

// ---------------- launch ------------------------------------------------------
static inline void launch_gemm(const float* A, const float* B, float* C, const float* R,
                               int M, int N, int K,
                               const int* cnt, const int* gi, const float* gw,
                               int epi, int gat) {
    dim3 grid(N / BN, (M + BM - 1) / BM);
    mma_gemm_kernel<<<grid, 256>>>(A, B, C, R, M, N, K, cnt, gi, gw, epi, gat);
}

extern "C" void kernel_launch(void* const* d_in, const int* in_sizes, int n_in,
                              void* d_out, int out_size) {
    const float* x    = (const float*)d_in[0];
    const float* g1   = (const float*)d_in[1];
    const float* g2   = (const float*)d_in[2];
    const float* wq   = (const float*)d_in[3];
    const float* wk   = (const float*)d_in[4];
    const float* wv   = (const float*)d_in[5];
    const float* wo   = (const float*)d_in[6];
    const float* gate = (const float*)d_in[7];
    const float* w1   = (const float*)d_in[8];
    const float* w2   = (const float*)d_in[9];
    const float* w3   = (const float*)d_in[10];
    float* out = (float*)d_out;

    float *xn, *q, *k, *v, *att, *h, *wgt;
    int *cnt, *idx;
    cudaGetSymbolAddress((void**)&xn,  g_xn);
    cudaGetSymbolAddress((void**)&q,   g_q);
    cudaGetSymbolAddress((void**)&k,   g_k);
    cudaGetSymbolAddress((void**)&v,   g_v);
    cudaGetSymbolAddress((void**)&att, g_att);
    cudaGetSymbolAddress((void**)&h,   g_h);
    cudaGetSymbolAddress((void**)&cnt, g_cnt);
    cudaGetSymbolAddress((void**)&idx, g_idx);
    cudaGetSymbolAddress((void**)&wgt, g_wgt);

    zero_cnt_kernel<<<1, 32>>>();

    // ---- attention branch ----
    rmsnorm_kernel<<<TOKENS, 256>>>(x, g1, xn);
    launch_gemm(xn, wq, q, nullptr, TOKENS, NH * HD,  DIM, nullptr, nullptr, nullptr, 0, 0);
    launch_gemm(xn, wk, k, nullptr, TOKENS, NKV * HD, DIM, nullptr, nullptr, nullptr, 0, 0);
    launch_gemm(xn, wv, v, nullptr, TOKENS, NKV * HD, DIM, nullptr, nullptr, nullptr, 0, 0);

    int ropeN = TOKENS * NH * 32 + TOKENS * NKV * 32;
    rope_kernel<<<(ropeN + 255) / 256, 256>>>(q, k);

    attn_kernel<<<(2 * NH * SEQ) / 8, 256>>>(q, k, v, att);

    // out = x + att @ wo
    launch_gemm(att, wo, out, x, TOKENS, DIM, DIM, nullptr, nullptr, nullptr, 1, 0);

    // ---- MoE branch ----
    rmsnorm_kernel<<<TOKENS, 256>>>(out, g2, xn);
    gate_kernel<<<TOKENS / 8, 256>>>(xn, gate);

    for (int e = 0; e < NE; e++) {
        const int*   ce = cnt + e;
        const int*   ie = idx + e * TOKENS;
        const float* we = wgt + e * TOKENS;
        launch_gemm(xn, w1 + (size_t)e * DIM * HIDDEN, h, nullptr,
                    TOKENS, HIDDEN, DIM, ce, ie, nullptr, 0, 1);
        launch_gemm(xn, w3 + (size_t)e * DIM * HIDDEN, h, nullptr,
                    TOKENS, HIDDEN, DIM, ce, ie, nullptr, 2, 1);
        launch_gemm(h, w2 + (size_t)e * HIDDEN * DIM, out, nullptr,
                    TOKENS, DIM, HIDDEN, ce, ie, we, 3, 0);
    }
}

// round 5
// speedup vs baseline: 4.7453x; 2.2290x over previous
#include <cuda_runtime.h>
#include <math.h>

#define TOKENS 4096
#define DIM    1024
#define SEQ    2048
#define NH     16
#define NKV    4
#define HD     64
#define HIDDEN 3072
#define NE     4
#define RMS_EPS 1.1920928955078125e-07f

// ---------------- scratch (device globals; no allocation allowed) ----------
__device__ float g_xn [TOKENS * DIM];
__device__ float g_q  [TOKENS * DIM];
__device__ float g_k  [TOKENS * NKV * HD];
__device__ float g_v  [TOKENS * NKV * HD];
__device__ float g_att[TOKENS * DIM];
__device__ float g_h  [TOKENS * HIDDEN];
__device__ int   g_cnt[NE];
__device__ int   g_idx[NE * TOKENS];
__device__ float g_wgt[NE * TOKENS];

__device__ __forceinline__ float tf32_rna(float x) {
    unsigned u;
    asm("cvt.rna.tf32.f32 %0, %1;" : "=r"(u) : "f"(x));
    return __uint_as_float(u);
}

__global__ void zero_cnt_kernel() {
    if (threadIdx.x < NE) g_cnt[threadIdx.x] = 0;
}

// ---------------- RMSNorm: one block per token (stores tf32-rounded) -------
__global__ void rmsnorm_kernel(const float* __restrict__ x,
                               const float* __restrict__ g,
                               float* __restrict__ o) {
    int t = blockIdx.x;
    int tid = threadIdx.x;
    const float* xr = x + (size_t)t * DIM;
    float ss = 0.f;
    for (int i = tid; i < DIM; i += 256) { float v = xr[i]; ss += v * v; }
    #pragma unroll
    for (int o2 = 16; o2; o2 >>= 1) ss += __shfl_xor_sync(0xffffffffu, ss, o2);
    __shared__ float sw[8];
    if ((tid & 31) == 0) sw[tid >> 5] = ss;
    __syncthreads();
    if (tid < 8) {
        float v = sw[tid];
        #pragma unroll
        for (int o2 = 4; o2; o2 >>= 1) v += __shfl_xor_sync(0xffu, v, o2);
        if (tid == 0) sw[0] = v;
    }
    __syncthreads();
    float r = rsqrtf(sw[0] * (1.0f / DIM) + RMS_EPS);
    float* orow = o + (size_t)t * DIM;
    for (int i = tid; i < DIM; i += 256) orow[i] = tf32_rna(xr[i] * r * g[i]);
}

// ---------------- tf32 tensor-core GEMM -------------------------------------
#define BM 128
#define BN 128
#define BK 16
#define SA 20
#define SB 136

__device__ __forceinline__ void mma_tf32(float c[4], unsigned a0, unsigned a1,
                                         unsigned a2, unsigned a3,
                                         unsigned b0, unsigned b1) {
    asm volatile(
        "mma.sync.aligned.m16n8k8.row.col.f32.tf32.tf32.f32 "
        "{%0,%1,%2,%3}, {%4,%5,%6,%7}, {%8,%9}, {%0,%1,%2,%3};"
        : "+f"(c[0]), "+f"(c[1]), "+f"(c[2]), "+f"(c[3])
        : "r"(a0), "r"(a1), "r"(a2), "r"(a3), "r"(b0), "r"(b1));
}

// epi: 0 = C=acc ; 1 = C=acc+R ; 2 = C=tf32(silu(C)*acc) ; 3 = C[idx[r]] += acc*wgt[r]
__global__ void __launch_bounds__(256, 2)
mma_gemm_kernel(const float* __restrict__ A, const float* __restrict__ B,
                float* __restrict__ C, const float* __restrict__ R,
                int M, int N, int K,
                const int* __restrict__ cnt,
                const int* __restrict__ gidx, const float* __restrict__ gwgt,
                int epi, int gatherA,
                const float* __restrict__ B2, const float* __restrict__ B3,
                float* __restrict__ C2, float* __restrict__ C3, int qkv) {
    int Meff = cnt ? *cnt : M;
    int rowBase = blockIdx.y * BM;
    if (rowBase >= Meff) return;

    __shared__ float As[BM][SA];
    __shared__ float Bs[BK][SB];

    int tid  = threadIdx.x;
    int lane = tid & 31;
    int wid  = tid >> 5;
    int wm   = wid & 1;
    int wn   = wid >> 1;
    int nBase = blockIdx.x * BN;

    const float* Bq = B; float* Cq = C; int ld = N; int nLoc = nBase;
    if (qkv) {
        if (nBase >= 1280)      { Bq = B3; Cq = C3; ld = 256;  nLoc = nBase - 1280; }
        else if (nBase >= 1024) { Bq = B2; Cq = C2; ld = 256;  nLoc = nBase - 1024; }
        else                    {                   ld = 1024; }
    }

    float acc[4][4][4];
    #pragma unroll
    for (int i = 0; i < 4; i++)
        #pragma unroll
        for (int j = 0; j < 4; j++)
            #pragma unroll
            for (int q = 0; q < 4; q++) acc[i][j][q] = 0.f;

    const float* aptr[2]; bool aok[2];
    const float* bptr[2];
    #pragma unroll
    for (int s = 0; s < 2; s++) {
        int fid = tid + s * 256;
        int row = rowBase + (fid >> 2);
        bool ok = row < Meff;
        long src = 0;
        if (ok) src = gatherA ? (long)gidx[row] : (long)row;
        aptr[s] = A + src * (size_t)K + ((fid & 3) << 2);
        aok[s] = ok;
        bptr[s] = Bq + (size_t)(fid >> 5) * ld + nLoc + ((fid & 31) << 2);
    }

    float4 a_st[2], b_st[2];
    #pragma unroll
    for (int s = 0; s < 2; s++) {
        a_st[s] = aok[s] ? *(const float4*)(aptr[s]) : make_float4(0.f, 0.f, 0.f, 0.f);
        b_st[s] = *(const float4*)(bptr[s]);
    }

    for (int kt = 0; kt < K; kt += BK) {
        #pragma unroll
        for (int s = 0; s < 2; s++) {
            int fid = tid + s * 256;
            *(float4*)&As[fid >> 2][(fid & 3) << 2] = a_st[s];
            *(float4*)&Bs[fid >> 5][(fid & 31) << 2] = b_st[s];
        }
        __syncthreads();
        if (kt + BK < K) {
            #pragma unroll
            for (int s = 0; s < 2; s++) {
                a_st[s] = aok[s] ? *(const float4*)(aptr[s] + kt + BK)
                                 : make_float4(0.f, 0.f, 0.f, 0.f);
                b_st[s] = *(const float4*)(bptr[s] + (size_t)(kt + BK) * ld);
            }
        }
        int r = lane >> 2, c = lane & 3;
        #pragma unroll
        for (int ks = 0; ks < BK; ks += 8) {
            unsigned bf[4][2];
            #pragma unroll
            for (int j = 0; j < 4; j++) {
                int nC = wn * 32 + j * 8 + r;
                bf[j][0] = __float_as_uint(Bs[ks + c][nC]);
                bf[j][1] = __float_as_uint(Bs[ks + c + 4][nC]);
            }
            #pragma unroll
            for (int i = 0; i < 4; i++) {
                int mR = wm * 64 + i * 16 + r;
                unsigned a0 = __float_as_uint(As[mR][ks + c]);
                unsigned a1 = __float_as_uint(As[mR + 8][ks + c]);
                unsigned a2 = __float_as_uint(As[mR][ks + c + 4]);
                unsigned a3 = __float_as_uint(As[mR + 8][ks + c + 4]);
                #pragma unroll
                for (int j = 0; j < 4; j++)
                    mma_tf32(acc[i][j], a0, a1, a2, a3, bf[j][0], bf[j][1]);
            }
        }
        __syncthreads();
    }

    int r = lane >> 2, c = lane & 3;
    #pragma unroll
    for (int i = 0; i < 4; i++) {
        int rbase = rowBase + wm * 64 + i * 16 + r;
        #pragma unroll
        for (int half = 0; half < 2; half++) {
            int rr = rbase + half * 8;
            if (rr >= Meff) continue;
            int tok = 0; float w = 0.f;
            if (epi == 3) { tok = gidx[rr]; w = gwgt[rr]; }
            #pragma unroll
            for (int j = 0; j < 4; j++) {
                int col = nLoc + wn * 32 + j * 8 + (c << 1);
                float v0 = acc[i][j][half * 2];
                float v1 = acc[i][j][half * 2 + 1];
                if (epi == 0) {
                    *(float2*)(Cq + (size_t)rr * ld + col) = make_float2(v0, v1);
                } else if (epi == 1) {
                    float2 rv = *(const float2*)(R + (size_t)rr * ld + col);
                    *(float2*)(Cq + (size_t)rr * ld + col) =
                        make_float2(v0 + rv.x, v1 + rv.y);
                } else if (epi == 2) {
                    float2 hv = *(float2*)(Cq + (size_t)rr * ld + col);
                    float s0 = hv.x / (1.f + __expf(-hv.x));
                    float s1 = hv.y / (1.f + __expf(-hv.y));
                    *(float2*)(Cq + (size_t)rr * ld + col) =
                        make_float2(tf32_rna(s0 * v0), tf32_rna(s1 * v1));
                } else {
                    float2* cp = (float2*)(Cq + (size_t)tok * ld + col);
                    float2 cv = *cp;
                    cv.x += v0 * w; cv.y += v1 * w;
                    *cp = cv;
                }
            }
        }
    }
}

// ---------------- RoPE on q and k (in place) --------------------------------
__global__ void rope_kernel(float* __restrict__ q, float* __restrict__ k) {
    int id = blockIdx.x * blockDim.x + threadIdx.x;
    const int NQ = TOKENS * NH * 32;
    const int NK2 = TOKENS * NKV * 32;
    if (id >= NQ + NK2) return;
    float* base; int t, i;
    if (id < NQ) {
        t = id >> 9; int r = id & 511; int h = r >> 5; i = r & 31;
        base = q + ((size_t)t * NH + h) * HD;
    } else {
        int id2 = id - NQ;
        t = id2 >> 7; int r = id2 & 127; int h = r >> 5; i = r & 31;
        base = k + ((size_t)t * NKV + h) * HD;
    }
    int pos = t & (SEQ - 1);
    float inv = exp2f(-(float)i * 0.4152410118609203f);
    float fr = (float)pos * inv;
    float sn, cs;
    sincosf(fr, &sn, &cs);
    float x1 = base[i], x2 = base[i + 32];
    base[i]      = x1 * cs - x2 * sn;
    base[i + 32] = x2 * cs + x1 * sn;
}

// ---------------- flash attention: 64 q-rows x 64-key tiles, tf32 mma -------
// 4 warps / CTA; warp w owns q rows [16w,16w+16); Q frags in registers.
// KsPs holds the K tile during S=QK^T, then is reused to hold P for P@V.
__global__ void flash_attn_kernel(const float* __restrict__ q,
                                  const float* __restrict__ k,
                                  const float* __restrict__ v,
                                  float* __restrict__ att) {
    __shared__ float KsPs[64][68];
    __shared__ float Vs[64][68];

    int qt = (SEQ / 64 - 1) - blockIdx.x;   // long tiles launch first
    int h  = blockIdx.y;
    int b  = blockIdx.z;
    int hk = h >> 2;
    int qbase = qt * 64;

    int tid  = threadIdx.x;
    int lane = tid & 31;
    int w    = tid >> 5;
    int lr   = lane >> 2;
    int cq   = lane & 3;
    int row0 = w * 16 + lr;
    int row1 = row0 + 8;

    // Q fragments (pre-scaled by 1/sqrt(HD) = 0.125, exact power of 2)
    unsigned qa[8][4];
    {
        const float* q0 = q + ((size_t)(b * SEQ + qbase + row0) * NH + h) * HD;
        const float* q1 = q + ((size_t)(b * SEQ + qbase + row1) * NH + h) * HD;
        #pragma unroll
        for (int ks8 = 0; ks8 < 8; ks8++) {
            int kk = ks8 * 8;
            qa[ks8][0] = __float_as_uint(q0[kk + cq] * 0.125f);
            qa[ks8][1] = __float_as_uint(q1[kk + cq] * 0.125f);
            qa[ks8][2] = __float_as_uint(q0[kk + cq + 4] * 0.125f);
            qa[ks8][3] = __float_as_uint(q1[kk + cq + 4] * 0.125f);
        }
    }

    float oacc[8][4];
    #pragma unroll
    for (int nf = 0; nf < 8; nf++)
        #pragma unroll
        for (int t2 = 0; t2 < 4; t2++) oacc[nf][t2] = 0.f;
    float m0 = -3.0e38f, m1 = -3.0e38f, l0 = 0.f, l1 = 0.f;

    const size_t kvstride = (size_t)NKV * HD;
    const float* kb = k + ((size_t)(b * SEQ) * NKV + hk) * HD;
    const float* vb = v + ((size_t)(b * SEQ) * NKV + hk) * HD;

    for (int kt = 0; kt <= qt; kt++) {
        __syncthreads();   // previous iteration's P/V reads complete
        int kbase = kt * 64;
        #pragma unroll
        for (int it = 0; it < 8; it++) {
            int idx  = tid + it * 128;      // 0..1023 float4 slots
            int rrow = idx >> 4;
            int ccol = (idx & 15) << 2;
            const float* ksrc = kb + (size_t)(kbase + rrow) * kvstride + ccol;
            const float* vsrc = vb + (size_t)(kbase + rrow) * kvstride + ccol;
            *(float4*)&KsPs[rrow][ccol] = *(const float4*)ksrc;
            *(float4*)&Vs[rrow][ccol]   = *(const float4*)vsrc;
        }
        __syncthreads();

        // S = Q @ K^T  (scores already scaled via Q)
        float s[8][4];
        #pragma unroll
        for (int nf = 0; nf < 8; nf++)
            #pragma unroll
            for (int t2 = 0; t2 < 4; t2++) s[nf][t2] = 0.f;
        #pragma unroll
        for (int ks8 = 0; ks8 < 8; ks8++) {
            int kk = ks8 * 8;
            #pragma unroll
            for (int nf = 0; nf < 8; nf++) {
                unsigned b0 = __float_as_uint(KsPs[nf * 8 + lr][kk + cq]);
                unsigned b1 = __float_as_uint(KsPs[nf * 8 + lr][kk + cq + 4]);
                mma_tf32(s[nf], qa[ks8][0], qa[ks8][1], qa[ks8][2], qa[ks8][3], b0, b1);
            }
        }
        __syncthreads();   // all K reads done; KsPs becomes P storage

        // causal mask on the diagonal tile
        if (kt == qt) {
            #pragma unroll
            for (int nf = 0; nf < 8; nf++) {
                int c0 = nf * 8 + cq * 2;
                if (c0     > row0) s[nf][0] = -3.0e38f;
                if (c0 + 1 > row0) s[nf][1] = -3.0e38f;
                if (c0     > row1) s[nf][2] = -3.0e38f;
                if (c0 + 1 > row1) s[nf][3] = -3.0e38f;
            }
        }

        // online softmax
        float rm0 = -3.0e38f, rm1 = -3.0e38f;
        #pragma unroll
        for (int nf = 0; nf < 8; nf++) {
            rm0 = fmaxf(rm0, fmaxf(s[nf][0], s[nf][1]));
            rm1 = fmaxf(rm1, fmaxf(s[nf][2], s[nf][3]));
        }
        rm0 = fmaxf(rm0, __shfl_xor_sync(0xffffffffu, rm0, 1));
        rm0 = fmaxf(rm0, __shfl_xor_sync(0xffffffffu, rm0, 2));
        rm1 = fmaxf(rm1, __shfl_xor_sync(0xffffffffu, rm1, 1));
        rm1 = fmaxf(rm1, __shfl_xor_sync(0xffffffffu, rm1, 2));
        float mn0 = fmaxf(m0, rm0), mn1 = fmaxf(m1, rm1);
        float sc0 = __expf(m0 - mn0), sc1 = __expf(m1 - mn1);
        m0 = mn0; m1 = mn1;
        l0 *= sc0; l1 *= sc1;
        #pragma unroll
        for (int nf = 0; nf < 8; nf++) {
            float p0 = __expf(s[nf][0] - mn0);
            float p1 = __expf(s[nf][1] - mn0);
            float p2 = __expf(s[nf][2] - mn1);
            float p3 = __expf(s[nf][3] - mn1);
            l0 += p0 + p1; l1 += p2 + p3;
            int c0 = nf * 8 + cq * 2;
            *(float2*)&KsPs[row0][c0] = make_float2(p0, p1);
            *(float2*)&KsPs[row1][c0] = make_float2(p2, p3);
            oacc[nf][0] *= sc0; oacc[nf][1] *= sc0;
            oacc[nf][2] *= sc1; oacc[nf][3] *= sc1;
        }
        __syncthreads();   // P visible to all warps

        // O += P @ V
        #pragma unroll
        for (int ks8 = 0; ks8 < 8; ks8++) {
            int kk = ks8 * 8;
            unsigned a0 = __float_as_uint(KsPs[row0][kk + cq]);
            unsigned a1 = __float_as_uint(KsPs[row1][kk + cq]);
            unsigned a2 = __float_as_uint(KsPs[row0][kk + cq + 4]);
            unsigned a3 = __float_as_uint(KsPs[row1][kk + cq + 4]);
            #pragma unroll
            for (int nf = 0; nf < 8; nf++) {
                unsigned b0 = __float_as_uint(Vs[kk + cq][nf * 8 + lr]);
                unsigned b1 = __float_as_uint(Vs[kk + cq + 4][nf * 8 + lr]);
                mma_tf32(oacc[nf], a0, a1, a2, a3, b0, b1);
            }
        }
    }

    // finalize: reduce l over quad, normalize, store
    l0 += __shfl_xor_sync(0xffffffffu, l0, 1);
    l0 += __shfl_xor_sync(0xffffffffu, l0, 2);
    l1 += __shfl_xor_sync(0xffffffffu, l1, 1);
    l1 += __shfl_xor_sync(0xffffffffu, l1, 2);
    float i0 = 1.f / l0, i1 = 1.f / l1;
    float* o0 = att + ((size_t)(b * SEQ + qbase + row0) * NH + h) * HD;
    float* o1 = att + ((size_t)(b * SEQ + qbase + row1) * NH + h) * HD;
    #pragma unroll
    for (int nf = 0; nf < 8; nf++) {
        int c0 = nf * 8 + cq * 2;
        *(float2*)(o0 + c0) = make_float2(tf32_rna(oacc[nf][0] * i0),
                                          tf32_rna(oacc[nf][1] * i0));
        *(float2*)(o1 + c0) = make_float2(tf32_rna(oacc[nf][2] * i1),
                                          tf32_rna(oacc[nf][3] * i1));
    }
}

// ---------------- MoE gating: one warp per token -----------------------------
__global__ void gate_kernel(const float* __restrict__ xn, const float* __restrict__ gate) {
    int gw = (int)((blockIdx.x * (size_t)blockDim.x + threadIdx.x) >> 5);
    int lane = threadIdx.x & 31;
    if (gw >= TOKENS) return;
    const float* xr = xn + (size_t)gw * DIM;
    float a0 = 0.f, a1 = 0.f, a2 = 0.f, a3 = 0.f;
    for (int i = lane; i < DIM; i += 32) {
        float xv = xr[i];
        const float* gr = gate + (size_t)i * NE;
        a0 += xv * gr[0]; a1 += xv * gr[1]; a2 += xv * gr[2]; a3 += xv * gr[3];
    }
    #pragma unroll
    for (int o2 = 16; o2; o2 >>= 1) {
        a0 += __shfl_xor_sync(0xffffffffu, a0, o2);
        a1 += __shfl_xor_sync(0xffffffffu, a1, o2);
        a2 += __shfl_xor_sync(0xffffffffu, a2, o2);
        a3 += __shfl_xor_sync(0xffffffffu, a3, o2);
    }
    if (lane == 0) {
        float p[NE] = {a0, a1, a2, a3};
        float mx = p[0];
        #pragma unroll
        for (int e = 1; e < NE; e++) mx = fmaxf(mx, p[e]);
        #pragma unroll
        for (int e = 0; e < NE; e++) p[e] = __expf(p[e] - mx);
        int e0 = 0;
        #pragma unroll
        for (int e = 1; e < NE; e++) if (p[e] > p[e0]) e0 = e;
        int e1 = -1;
        #pragma unroll
        for (int e = 0; e < NE; e++) if (e != e0 && (e1 < 0 || p[e] > p[e1])) e1 = e;
        float w0 = p[e0], w1 = p[e1];
        float ws = w0 + w1;
        w0 /= ws; w1 /= ws;
        int s0 = atomicAdd(&g_cnt[e0], 1);
        g_idx[e0 * TOKENS + s0] = gw; g_wgt[e0 * TOKENS + s0] = w0;
        int s1 = atomicAdd(&g_cnt[e1], 1);
        g_idx[e1 * TOKENS + s1] = gw; g_wgt[e1 * TOKENS + s1] = w1;
    }
}

// ---------------- launch ------------------------------------------------------
static inline void launch_gemm(const float* A, const float* B, float* C, const float* R,
                               int M, int N, int K,
                               const int* cnt, const int* gi, const float* gw,
                               int epi, int gat) {
    dim3 grid(N / BN, (M + BM - 1) / BM);
    mma_gemm_kernel<<<grid, 256>>>(A, B, C, R, M, N, K, cnt, gi, gw, epi, gat,
                                   nullptr, nullptr, nullptr, nullptr, 0);
}

extern "C" void kernel_launch(void* const* d_in, const int* in_sizes, int n_in,
                              void* d_out, int out_size) {
    const float* x    = (const float*)d_in[0];
    const float* g1   = (const float*)d_in[1];
    const float* g2   = (const float*)d_in[2];
    const float* wq   = (const float*)d_in[3];
    const float* wk   = (const float*)d_in[4];
    const float* wv   = (const float*)d_in[5];
    const float* wo   = (const float*)d_in[6];
    const float* gate = (const float*)d_in[7];
    const float* w1   = (const float*)d_in[8];
    const float* w2   = (const float*)d_in[9];
    const float* w3   = (const float*)d_in[10];
    float* out = (float*)d_out;

    float *xn, *q, *k, *v, *att, *h, *wgt;
    int *cnt, *idx;
    cudaGetSymbolAddress((void**)&xn,  g_xn);
    cudaGetSymbolAddress((void**)&q,   g_q);
    cudaGetSymbolAddress((void**)&k,   g_k);
    cudaGetSymbolAddress((void**)&v,   g_v);
    cudaGetSymbolAddress((void**)&att, g_att);
    cudaGetSymbolAddress((void**)&h,   g_h);
    cudaGetSymbolAddress((void**)&cnt, g_cnt);
    cudaGetSymbolAddress((void**)&idx, g_idx);
    cudaGetSymbolAddress((void**)&wgt, g_wgt);

    zero_cnt_kernel<<<1, 32>>>();

    // ---- attention branch ----
    rmsnorm_kernel<<<TOKENS, 256>>>(x, g1, xn);

    // fused q/k/v projection: virtual N = 1536 (1024 q | 256 k | 256 v)
    {
        dim3 grid(1536 / BN, TOKENS / BM);
        mma_gemm_kernel<<<grid, 256>>>(xn, wq, q, nullptr, TOKENS, 1536, DIM,
                                       nullptr, nullptr, nullptr, 0, 0,
                                       wk, wv, k, v, 1);
    }

    int ropeN = TOKENS * NH * 32 + TOKENS * NKV * 32;
    rope_kernel<<<(ropeN + 255) / 256, 256>>>(q, k);

    {
        dim3 grid(SEQ / 64, NH, 2);
        flash_attn_kernel<<<grid, 128>>>(q, k, v, att);
    }

    // out = x + att @ wo
    launch_gemm(att, wo, out, x, TOKENS, DIM, DIM, nullptr, nullptr, nullptr, 1, 0);

    // ---- MoE branch ----
    rmsnorm_kernel<<<TOKENS, 256>>>(out, g2, xn);
    gate_kernel<<<TOKENS / 8, 256>>>(xn, gate);

    for (int e = 0; e < NE; e++) {
        const int*   ce = cnt + e;
        const int*   ie = idx + e * TOKENS;
        const float* we = wgt + e * TOKENS;
        launch_gemm(xn, w1 + (size_t)e * DIM * HIDDEN, h, nullptr,
                    TOKENS, HIDDEN, DIM, ce, ie, nullptr, 0, 1);
        launch_gemm(xn, w3 + (size_t)e * DIM * HIDDEN, h, nullptr,
                    TOKENS, HIDDEN, DIM, ce, ie, nullptr, 2, 1);
        launch_gemm(h, w2 + (size_t)e * HIDDEN * DIM, out, nullptr,
                    TOKENS, DIM, HIDDEN, ce, ie, we, 3, 0);
    }
}

// round 7
// speedup vs baseline: 5.9959x; 1.2635x over previous
#include <cuda_runtime.h>
#include <math.h>

#define TOKENS 4096
#define DIM    1024
#define SEQ    2048
#define NH     16
#define NKV    4
#define HD     64
#define HIDDEN 3072
#define NE     4
#define RMS_EPS 1.1920928955078125e-07f

// ---------------- scratch (device globals; no allocation allowed) ----------
__device__ float g_xn [TOKENS * DIM];
__device__ float g_q  [TOKENS * DIM];
__device__ float g_k  [TOKENS * NKV * HD];
__device__ float g_v  [TOKENS * NKV * HD];
__device__ float g_att[TOKENS * DIM];
__device__ float g_h  [NE * TOKENS * HIDDEN];   // per-expert hidden
__device__ int   g_cnt[NE];
__device__ int   g_idx[NE * TOKENS];
__device__ float g_wgt[NE * TOKENS];

__device__ __forceinline__ float tf32_rna(float x) {
    unsigned u;
    asm("cvt.rna.tf32.f32 %0, %1;" : "=r"(u) : "f"(x));
    return __uint_as_float(u);
}

__device__ __forceinline__ unsigned smem_u32(const void* p) {
    return (unsigned)__cvta_generic_to_shared(p);
}
__device__ __forceinline__ void cp16(unsigned dst, const void* src, int sz) {
    asm volatile("cp.async.cg.shared.global [%0], [%1], 16, %2;"
                 :: "r"(dst), "l"(src), "r"(sz));
}
__device__ __forceinline__ void cp_commit() {
    asm volatile("cp.async.commit_group;");
}
template<int N> __device__ __forceinline__ void cp_wait() {
    asm volatile("cp.async.wait_group %0;" :: "n"(N));
}

__global__ void zero_cnt_kernel() {
    if (threadIdx.x < NE) g_cnt[threadIdx.x] = 0;
}

// ---------------- RMSNorm: one block per token (stores tf32-rounded) -------
__global__ void rmsnorm_kernel(const float* __restrict__ x,
                               const float* __restrict__ g,
                               float* __restrict__ o) {
    int t = blockIdx.x;
    int tid = threadIdx.x;
    const float* xr = x + (size_t)t * DIM;
    float ss = 0.f;
    for (int i = tid; i < DIM; i += 256) { float v = xr[i]; ss += v * v; }
    #pragma unroll
    for (int o2 = 16; o2; o2 >>= 1) ss += __shfl_xor_sync(0xffffffffu, ss, o2);
    __shared__ float sw[8];
    if ((tid & 31) == 0) sw[tid >> 5] = ss;
    __syncthreads();
    if (tid < 8) {
        float v = sw[tid];
        #pragma unroll
        for (int o2 = 4; o2; o2 >>= 1) v += __shfl_xor_sync(0xffu, v, o2);
        if (tid == 0) sw[0] = v;
    }
    __syncthreads();
    float r = rsqrtf(sw[0] * (1.0f / DIM) + RMS_EPS);
    float* orow = o + (size_t)t * DIM;
    for (int i = tid; i < DIM; i += 256) orow[i] = tf32_rna(xr[i] * r * g[i]);
}

// ---------------- tf32 tensor-core GEMM, cp.async 2-stage pipeline ----------
#define BM 128
#define BN 128
#define BK 16
#define SA 20
#define SB 136
#define A_STAGE_B (BM * SA * 4)
#define B_STAGE_B (BK * SB * 4)

__device__ __forceinline__ void mma_tf32(float c[4], unsigned a0, unsigned a1,
                                         unsigned a2, unsigned a3,
                                         unsigned b0, unsigned b1) {
    asm volatile(
        "mma.sync.aligned.m16n8k8.row.col.f32.tf32.tf32.f32 "
        "{%0,%1,%2,%3}, {%4,%5,%6,%7}, {%8,%9}, {%0,%1,%2,%3};"
        : "+f"(c[0]), "+f"(c[1]), "+f"(c[2]), "+f"(c[3])
        : "r"(a0), "r"(a1), "r"(a2), "r"(a3), "r"(b0), "r"(b1));
}

// epi: 0 = C=acc ; 1 = C=acc+R ; 2 = C=tf32(silu(C)*acc) ; 3 = atomicAdd(C[idx[r]], acc*wgt[r])
// blockIdx.z = expert slice: offsets cnt/gidx/gwgt and strides A/B/C.
__global__ void __launch_bounds__(256, 2)
mma_gemm_kernel(const float* __restrict__ A, const float* __restrict__ B,
                float* __restrict__ C, const float* __restrict__ R,
                int M, int N, int K,
                const int* __restrict__ cnt,
                const int* __restrict__ gidx, const float* __restrict__ gwgt,
                int epi, int gatherA,
                const float* __restrict__ B2, const float* __restrict__ B3,
                float* __restrict__ C2, float* __restrict__ C3, int qkv,
                long aStride, long bStride, long cStride) {
    int ez = blockIdx.z;
    if (cnt)  cnt  += ez;
    if (gidx) gidx += (size_t)ez * TOKENS;
    if (gwgt) gwgt += (size_t)ez * TOKENS;
    A += (size_t)ez * aStride;
    B += (size_t)ez * bStride;
    C += (size_t)ez * cStride;

    int Meff = cnt ? *cnt : M;
    int rowBase = blockIdx.y * BM;
    if (rowBase >= Meff) return;

    __shared__ float As[2][BM][SA];
    __shared__ float Bs[2][BK][SB];

    int tid  = threadIdx.x;
    int lane = tid & 31;
    int wid  = tid >> 5;
    int wm   = wid & 1;
    int wn   = wid >> 1;
    int nBase = blockIdx.x * BN;

    const float* Bq = B; float* Cq = C; int ld = N; int nLoc = nBase;
    if (qkv) {
        if (nBase >= 1280)      { Bq = B3; Cq = C3; ld = 256;  nLoc = nBase - 1280; }
        else if (nBase >= 1024) { Bq = B2; Cq = C2; ld = 256;  nLoc = nBase - 1024; }
        else                    {                   ld = 1024; }
    }

    float acc[4][4][4];
    #pragma unroll
    for (int i = 0; i < 4; i++)
        #pragma unroll
        for (int j = 0; j < 4; j++)
            #pragma unroll
            for (int q = 0; q < 4; q++) acc[i][j][q] = 0.f;

    // copy assignments: 2 float4 slots per thread for A and for B
    const float* aSrc[2]; int aSz[2]; unsigned aDst[2];
    const float* bSrc[2]; unsigned bDst[2];
    #pragma unroll
    for (int s = 0; s < 2; s++) {
        int fid = tid + s * 256;
        int row = rowBase + (fid >> 2);
        bool ok = row < Meff;
        long src = 0;
        if (ok) src = gatherA ? (long)gidx[row] : (long)row;
        aSrc[s] = A + src * (size_t)K + ((fid & 3) << 2);
        aSz[s]  = ok ? 16 : 0;
        aDst[s] = smem_u32(&As[0][fid >> 2][(fid & 3) << 2]);
        bSrc[s] = Bq + (size_t)(fid >> 5) * ld + nLoc + ((fid & 31) << 2);
        bDst[s] = smem_u32(&Bs[0][fid >> 5][(fid & 31) << 2]);
    }

    int nIter = K / BK;
    // prologue: stages 0 and 1
    #pragma unroll
    for (int s = 0; s < 2; s++) {
        cp16(aDst[s], aSrc[s], aSz[s]);
        cp16(bDst[s], bSrc[s], 16);
    }
    cp_commit();
    if (nIter > 1) {
        #pragma unroll
        for (int s = 0; s < 2; s++) {
            cp16(aDst[s] + A_STAGE_B, aSrc[s] + BK, aSz[s]);
            cp16(bDst[s] + B_STAGE_B, bSrc[s] + (size_t)BK * ld, 16);
        }
        cp_commit();
    }

    int r = lane >> 2, c = lane & 3;
    for (int it = 0; it < nIter; it++) {
        int cur = it & 1;
        if (it + 1 < nIter) cp_wait<1>(); else cp_wait<0>();
        __syncthreads();

        #pragma unroll
        for (int ks = 0; ks < BK; ks += 8) {
            unsigned bf[4][2];
            #pragma unroll
            for (int j = 0; j < 4; j++) {
                int nC = wn * 32 + j * 8 + r;
                bf[j][0] = __float_as_uint(Bs[cur][ks + c][nC]);
                bf[j][1] = __float_as_uint(Bs[cur][ks + c + 4][nC]);
            }
            #pragma unroll
            for (int i = 0; i < 4; i++) {
                int mR = wm * 64 + i * 16 + r;
                unsigned a0 = __float_as_uint(As[cur][mR][ks + c]);
                unsigned a1 = __float_as_uint(As[cur][mR + 8][ks + c]);
                unsigned a2 = __float_as_uint(As[cur][mR][ks + c + 4]);
                unsigned a3 = __float_as_uint(As[cur][mR + 8][ks + c + 4]);
                #pragma unroll
                for (int j = 0; j < 4; j++)
                    mma_tf32(acc[i][j], a0, a1, a2, a3, bf[j][0], bf[j][1]);
            }
        }
        __syncthreads();
        if (it + 2 < nIter) {
            int kt = (it + 2) * BK;
            #pragma unroll
            for (int s = 0; s < 2; s++) {
                cp16(aDst[s] + cur * A_STAGE_B, aSrc[s] + kt, aSz[s]);
                cp16(bDst[s] + cur * B_STAGE_B, bSrc[s] + (size_t)kt * ld, 16);
            }
            cp_commit();
        }
    }

    // epilogue
    #pragma unroll
    for (int i = 0; i < 4; i++) {
        int rbase = rowBase + wm * 64 + i * 16 + r;
        #pragma unroll
        for (int half = 0; half < 2; half++) {
            int rr = rbase + half * 8;
            if (rr >= Meff) continue;
            int tok = 0; float w = 0.f;
            if (epi == 3) { tok = gidx[rr]; w = gwgt[rr]; }
            #pragma unroll
            for (int j = 0; j < 4; j++) {
                int col = nLoc + wn * 32 + j * 8 + (c << 1);
                float v0 = acc[i][j][half * 2];
                float v1 = acc[i][j][half * 2 + 1];
                if (epi == 0) {
                    *(float2*)(Cq + (size_t)rr * ld + col) = make_float2(v0, v1);
                } else if (epi == 1) {
                    float2 rv = *(const float2*)(R + (size_t)rr * ld + col);
                    *(float2*)(Cq + (size_t)rr * ld + col) =
                        make_float2(v0 + rv.x, v1 + rv.y);
                } else if (epi == 2) {
                    float2 hv = *(float2*)(Cq + (size_t)rr * ld + col);
                    float s0 = hv.x / (1.f + __expf(-hv.x));
                    float s1 = hv.y / (1.f + __expf(-hv.y));
                    *(float2*)(Cq + (size_t)rr * ld + col) =
                        make_float2(tf32_rna(s0 * v0), tf32_rna(s1 * v1));
                } else {
                    float* cp = Cq + (size_t)tok * ld + col;
                    atomicAdd(cp,     v0 * w);
                    atomicAdd(cp + 1, v1 * w);
                }
            }
        }
    }
}

// ---------------- RoPE on q and k (in place) --------------------------------
__global__ void rope_kernel(float* __restrict__ q, float* __restrict__ k) {
    int id = blockIdx.x * blockDim.x + threadIdx.x;
    const int NQ = TOKENS * NH * 32;
    const int NK2 = TOKENS * NKV * 32;
    if (id >= NQ + NK2) return;
    float* base; int t, i;
    if (id < NQ) {
        t = id >> 9; int r = id & 511; int h = r >> 5; i = r & 31;
        base = q + ((size_t)t * NH + h) * HD;
    } else {
        int id2 = id - NQ;
        t = id2 >> 7; int r = id2 & 127; int h = r >> 5; i = r & 31;
        base = k + ((size_t)t * NKV + h) * HD;
    }
    int pos = t & (SEQ - 1);
    float inv = exp2f(-(float)i * 0.4152410118609203f);
    float fr = (float)pos * inv;
    float sn, cs;
    sincosf(fr, &sn, &cs);
    float x1 = base[i], x2 = base[i + 32];
    base[i]      = x1 * cs - x2 * sn;
    base[i + 32] = x2 * cs + x1 * sn;
}

// ---------------- flash attention: 64 q-rows, cp.async double-buffered ------
// dynamic smem layout (floats): K0 | K1 | V0 | V1 | P   each 64x68
#define FTILE   (64 * 68)
#define FTILE_B (FTILE * 4)
__global__ void flash_attn_kernel(const float* __restrict__ q,
                                  const float* __restrict__ k,
                                  const float* __restrict__ v,
                                  float* __restrict__ att) {
    extern __shared__ float fs[];
    float* Pb = fs + 4 * FTILE;

    int qt = (SEQ / 64 - 1) - blockIdx.x;   // long tiles launch first
    int h  = blockIdx.y;
    int b  = blockIdx.z;
    int hk = h >> 2;
    int qbase = qt * 64;

    int tid  = threadIdx.x;
    int lane = tid & 31;
    int w    = tid >> 5;
    int lr   = lane >> 2;
    int cq   = lane & 3;
    int row0 = w * 16 + lr;
    int row1 = row0 + 8;

    const size_t kvstride = (size_t)NKV * HD;
    const float* kb = k + ((size_t)(b * SEQ) * NKV + hk) * HD;
    const float* vb = v + ((size_t)(b * SEQ) * NKV + hk) * HD;

    // copy slots: 8 float4 each for K and V per tile
    unsigned kDst[8]; const float* kSrc[8]; const float* vSrc[8];
    #pragma unroll
    for (int it = 0; it < 8; it++) {
        int idx = tid + it * 128;
        int rrow = idx >> 4;
        int ccol = (idx & 15) << 2;
        kDst[it] = smem_u32(fs + rrow * 68 + ccol);
        kSrc[it] = kb + (size_t)rrow * kvstride + ccol;
        vSrc[it] = vb + (size_t)rrow * kvstride + ccol;
    }

    // Q fragments (pre-scaled by 1/sqrt(HD) = 0.125)
    unsigned qa[8][4];
    {
        const float* q0 = q + ((size_t)(b * SEQ + qbase + row0) * NH + h) * HD;
        const float* q1 = q + ((size_t)(b * SEQ + qbase + row1) * NH + h) * HD;
        #pragma unroll
        for (int ks8 = 0; ks8 < 8; ks8++) {
            int kk = ks8 * 8;
            qa[ks8][0] = __float_as_uint(q0[kk + cq] * 0.125f);
            qa[ks8][1] = __float_as_uint(q1[kk + cq] * 0.125f);
            qa[ks8][2] = __float_as_uint(q0[kk + cq + 4] * 0.125f);
            qa[ks8][3] = __float_as_uint(q1[kk + cq + 4] * 0.125f);
        }
    }

    float oacc[8][4];
    #pragma unroll
    for (int nf = 0; nf < 8; nf++)
        #pragma unroll
        for (int t2 = 0; t2 < 4; t2++) oacc[nf][t2] = 0.f;
    float m0 = -3.0e38f, m1 = -3.0e38f, l0 = 0.f, l1 = 0.f;

    // prefetch tile 0 into buffer 0
    #pragma unroll
    for (int it = 0; it < 8; it++) {
        cp16(kDst[it], kSrc[it], 16);
        cp16(kDst[it] + 2 * FTILE_B, vSrc[it], 16);
    }
    cp_commit();

    for (int kt = 0; kt <= qt; kt++) {
        int cur = kt & 1;
        __syncthreads();   // release buf cur^1 (+P) from previous iteration
        if (kt < qt) {
            size_t off = (size_t)(kt + 1) * 64 * kvstride;
            int nb = cur ^ 1;
            #pragma unroll
            for (int it = 0; it < 8; it++) {
                cp16(kDst[it] + nb * FTILE_B,       kSrc[it] + off, 16);
                cp16(kDst[it] + (2 + nb) * FTILE_B, vSrc[it] + off, 16);
            }
            cp_commit();
            cp_wait<1>();
        } else {
            cp_wait<0>();
        }
        __syncthreads();   // current tile visible CTA-wide

        const float* Ksf = fs + cur * FTILE;
        const float* Vsf = fs + (2 + cur) * FTILE;

        // S = Q @ K^T (scores pre-scaled via Q)
        float s[8][4];
        #pragma unroll
        for (int nf = 0; nf < 8; nf++)
            #pragma unroll
            for (int t2 = 0; t2 < 4; t2++) s[nf][t2] = 0.f;
        #pragma unroll
        for (int ks8 = 0; ks8 < 8; ks8++) {
            int kk = ks8 * 8;
            #pragma unroll
            for (int nf = 0; nf < 8; nf++) {
                unsigned b0 = __float_as_uint(Ksf[(nf * 8 + lr) * 68 + kk + cq]);
                unsigned b1 = __float_as_uint(Ksf[(nf * 8 + lr) * 68 + kk + cq + 4]);
                mma_tf32(s[nf], qa[ks8][0], qa[ks8][1], qa[ks8][2], qa[ks8][3], b0, b1);
            }
        }

        // causal mask on the diagonal tile
        if (kt == qt) {
            #pragma unroll
            for (int nf = 0; nf < 8; nf++) {
                int c0 = nf * 8 + cq * 2;
                if (c0     > row0) s[nf][0] = -3.0e38f;
                if (c0 + 1 > row0) s[nf][1] = -3.0e38f;
                if (c0     > row1) s[nf][2] = -3.0e38f;
                if (c0 + 1 > row1) s[nf][3] = -3.0e38f;
            }
        }

        // online softmax
        float rm0 = -3.0e38f, rm1 = -3.0e38f;
        #pragma unroll
        for (int nf = 0; nf < 8; nf++) {
            rm0 = fmaxf(rm0, fmaxf(s[nf][0], s[nf][1]));
            rm1 = fmaxf(rm1, fmaxf(s[nf][2], s[nf][3]));
        }
        rm0 = fmaxf(rm0, __shfl_xor_sync(0xffffffffu, rm0, 1));
        rm0 = fmaxf(rm0, __shfl_xor_sync(0xffffffffu, rm0, 2));
        rm1 = fmaxf(rm1, __shfl_xor_sync(0xffffffffu, rm1, 1));
        rm1 = fmaxf(rm1, __shfl_xor_sync(0xffffffffu, rm1, 2));
        float mn0 = fmaxf(m0, rm0), mn1 = fmaxf(m1, rm1);
        float sc0 = __expf(m0 - mn0), sc1 = __expf(m1 - mn1);
        m0 = mn0; m1 = mn1;
        l0 *= sc0; l1 *= sc1;
        #pragma unroll
        for (int nf = 0; nf < 8; nf++) {
            float p0 = __expf(s[nf][0] - mn0);
            float p1 = __expf(s[nf][1] - mn0);
            float p2 = __expf(s[nf][2] - mn1);
            float p3 = __expf(s[nf][3] - mn1);
            l0 += p0 + p1; l1 += p2 + p3;
            int c0 = nf * 8 + cq * 2;
            *(float2*)&Pb[row0 * 68 + c0] = make_float2(p0, p1);
            *(float2*)&Pb[row1 * 68 + c0] = make_float2(p2, p3);
            oacc[nf][0] *= sc0; oacc[nf][1] *= sc0;
            oacc[nf][2] *= sc1; oacc[nf][3] *= sc1;
        }
        __syncthreads();   // P visible to all warps

        // O += P @ V
        #pragma unroll
        for (int ks8 = 0; ks8 < 8; ks8++) {
            int kk = ks8 * 8;
            unsigned a0 = __float_as_uint(Pb[row0 * 68 + kk + cq]);
            unsigned a1 = __float_as_uint(Pb[row1 * 68 + kk + cq]);
            unsigned a2 = __float_as_uint(Pb[row0 * 68 + kk + cq + 4]);
            unsigned a3 = __float_as_uint(Pb[row1 * 68 + kk + cq + 4]);
            #pragma unroll
            for (int nf = 0; nf < 8; nf++) {
                unsigned b0 = __float_as_uint(Vsf[(kk + cq) * 68 + nf * 8 + lr]);
                unsigned b1 = __float_as_uint(Vsf[(kk + cq + 4) * 68 + nf * 8 + lr]);
                mma_tf32(oacc[nf], a0, a1, a2, a3, b0, b1);
            }
        }
    }

    // finalize
    l0 += __shfl_xor_sync(0xffffffffu, l0, 1);
    l0 += __shfl_xor_sync(0xffffffffu, l0, 2);
    l1 += __shfl_xor_sync(0xffffffffu, l1, 1);
    l1 += __shfl_xor_sync(0xffffffffu, l1, 2);
    float i0 = 1.f / l0, i1 = 1.f / l1;
    float* o0 = att + ((size_t)(b * SEQ + qbase + row0) * NH + h) * HD;
    float* o1 = att + ((size_t)(b * SEQ + qbase + row1) * NH + h) * HD;
    #pragma unroll
    for (int nf = 0; nf < 8; nf++) {
        int c0 = nf * 8 + cq * 2;
        *(float2*)(o0 + c0) = make_float2(tf32_rna(oacc[nf][0] * i0),
                                          tf32_rna(oacc[nf][1] * i0));
        *(float2*)(o1 + c0) = make_float2(tf32_rna(oacc[nf][2] * i1),
                                          tf32_rna(oacc[nf][3] * i1));
    }
}

// ---------------- MoE gating: one warp per token -----------------------------
__global__ void gate_kernel(const float* __restrict__ xn, const float* __restrict__ gate) {
    int gw = (int)((blockIdx.x * (size_t)blockDim.x + threadIdx.x) >> 5);
    int lane = threadIdx.x & 31;
    if (gw >= TOKENS) return;
    const float* xr = xn + (size_t)gw * DIM;
    float a0 = 0.f, a1 = 0.f, a2 = 0.f, a3 = 0.f;
    for (int i = lane; i < DIM; i += 32) {
        float xv = xr[i];
        const float* gr = gate + (size_t)i * NE;
        a0 += xv * gr[0]; a1 += xv * gr[1]; a2 += xv * gr[2]; a3 += xv * gr[3];
    }
    #pragma unroll
    for (int o2 = 16; o2; o2 >>= 1) {
        a0 += __shfl_xor_sync(0xffffffffu, a0, o2);
        a1 += __shfl_xor_sync(0xffffffffu, a1, o2);
        a2 += __shfl_xor_sync(0xffffffffu, a2, o2);
        a3 += __shfl_xor_sync(0xffffffffu, a3, o2);
    }
    if (lane == 0) {
        float p[NE] = {a0, a1, a2, a3};
        float mx = p[0];
        #pragma unroll
        for (int e = 1; e < NE; e++) mx = fmaxf(mx, p[e]);
        #pragma unroll
        for (int e = 0; e < NE; e++) p[e] = __expf(p[e] - mx);
        int e0 = 0;
        #pragma unroll
        for (int e = 1; e < NE; e++) if (p[e] > p[e0]) e0 = e;
        int e1 = -1;
        #pragma unroll
        for (int e = 0; e < NE; e++) if (e != e0 && (e1 < 0 || p[e] > p[e1])) e1 = e;
        float w0 = p[e0], w1 = p[e1];
        float ws = w0 + w1;
        w0 /= ws; w1 /= ws;
        int s0 = atomicAdd(&g_cnt[e0], 1);
        g_idx[e0 * TOKENS + s0] = gw; g_wgt[e0 * TOKENS + s0] = w0;
        int s1 = atomicAdd(&g_cnt[e1], 1);
        g_idx[e1 * TOKENS + s1] = gw; g_wgt[e1 * TOKENS + s1] = w1;
    }
}

// ---------------- launch ------------------------------------------------------
static inline void launch_gemm(const float* A, const float* B, float* C, const float* R,
                               int M, int N, int K,
                               const int* cnt, const int* gi, const float* gw,
                               int epi, int gat, int nz,
                               long aS, long bS, long cS) {
    dim3 grid(N / BN, (M + BM - 1) / BM, nz);
    mma_gemm_kernel<<<grid, 256>>>(A, B, C, R, M, N, K, cnt, gi, gw, epi, gat,
                                   nullptr, nullptr, nullptr, nullptr, 0,
                                   aS, bS, cS);
}

extern "C" void kernel_launch(void* const* d_in, const int* in_sizes, int n_in,
                              void* d_out, int out_size) {
    const float* x    = (const float*)d_in[0];
    const float* g1   = (const float*)d_in[1];
    const float* g2   = (const float*)d_in[2];
    const float* wq   = (const float*)d_in[3];
    const float* wk   = (const float*)d_in[4];
    const float* wv   = (const float*)d_in[5];
    const float* wo   = (const float*)d_in[6];
    const float* gate = (const float*)d_in[7];
    const float* w1   = (const float*)d_in[8];
    const float* w2   = (const float*)d_in[9];
    const float* w3   = (const float*)d_in[10];
    float* out = (float*)d_out;

    float *xn, *q, *k, *v, *att, *h, *wgt;
    int *cnt, *idx;
    cudaGetSymbolAddress((void**)&xn,  g_xn);
    cudaGetSymbolAddress((void**)&q,   g_q);
    cudaGetSymbolAddress((void**)&k,   g_k);
    cudaGetSymbolAddress((void**)&v,   g_v);
    cudaGetSymbolAddress((void**)&att, g_att);
    cudaGetSymbolAddress((void**)&h,   g_h);
    cudaGetSymbolAddress((void**)&cnt, g_cnt);
    cudaGetSymbolAddress((void**)&idx, g_idx);
    cudaGetSymbolAddress((void**)&wgt, g_wgt);

    // unconditional (no static guards allowed); idempotent host-side call
    cudaFuncSetAttribute(flash_attn_kernel,
                         cudaFuncAttributeMaxDynamicSharedMemorySize,
                         5 * FTILE_B);

    zero_cnt_kernel<<<1, 32>>>();

    // ---- attention branch ----
    rmsnorm_kernel<<<TOKENS, 256>>>(x, g1, xn);

    // fused q/k/v projection: virtual N = 1536 (1024 q | 256 k | 256 v)
    {
        dim3 grid(1536 / BN, TOKENS / BM, 1);
        mma_gemm_kernel<<<grid, 256>>>(xn, wq, q, nullptr, TOKENS, 1536, DIM,
                                       nullptr, nullptr, nullptr, 0, 0,
                                       wk, wv, k, v, 1, 0, 0, 0);
    }

    int ropeN = TOKENS * NH * 32 + TOKENS * NKV * 32;
    rope_kernel<<<(ropeN + 255) / 256, 256>>>(q, k);

    {
        dim3 grid(SEQ / 64, NH, 2);
        flash_attn_kernel<<<grid, 128, 5 * FTILE_B>>>(q, k, v, att);
    }

    // out = x + att @ wo
    launch_gemm(att, wo, out, x, TOKENS, DIM, DIM, nullptr, nullptr, nullptr,
                1, 0, 1, 0, 0, 0);

    // ---- MoE branch ----
    rmsnorm_kernel<<<TOKENS, 256>>>(out, g2, xn);
    gate_kernel<<<TOKENS / 8, 256>>>(xn, gate);

    // all experts in one launch each (gridDim.z = NE)
    // h[e] = gather(xn)@w1[e]
    launch_gemm(xn, w1, h, nullptr, TOKENS, HIDDEN, DIM, cnt, idx, nullptr,
                0, 1, NE, 0, (long)DIM * HIDDEN, (long)TOKENS * HIDDEN);
    // h[e] = silu(h[e]) * (gather(xn)@w3[e])
    launch_gemm(xn, w3, h, nullptr, TOKENS, HIDDEN, DIM, cnt, idx, nullptr,
                2, 1, NE, 0, (long)DIM * HIDDEN, (long)TOKENS * HIDDEN);
    // out[tok] += (h[e]@w2[e]) * wgt   (atomic scatter across experts)
    launch_gemm(h, w2, out, nullptr, TOKENS, DIM, HIDDEN, cnt, idx, wgt,
                3, 0, NE, (long)TOKENS * HIDDEN, (long)HIDDEN * DIM, 0);
}

// round 8
// speedup vs baseline: 6.4396x; 1.0740x over previous
#include <cuda_runtime.h>
#include <math.h>

#define TOKENS 4096
#define DIM    1024
#define SEQ    2048
#define NH     16
#define NKV    4
#define HD     64
#define HIDDEN 3072
#define NE     4
#define RMS_EPS 1.1920928955078125e-07f

// ---------------- scratch (device globals; no allocation allowed) ----------
__device__ float g_xn [TOKENS * DIM];
__device__ float g_q  [TOKENS * DIM];
__device__ float g_k  [TOKENS * NKV * HD];
__device__ float g_v  [TOKENS * NKV * HD];
__device__ float g_att[TOKENS * DIM];
__device__ float g_h  [NE * TOKENS * HIDDEN];   // per-expert hidden
__device__ int   g_cnt[NE];
__device__ int   g_idx[NE * TOKENS];
__device__ float g_wgt[NE * TOKENS];

__device__ __forceinline__ float tf32_rna(float x) {
    unsigned u;
    asm("cvt.rna.tf32.f32 %0, %1;" : "=r"(u) : "f"(x));
    return __uint_as_float(u);
}

__device__ __forceinline__ unsigned smem_u32(const void* p) {
    return (unsigned)__cvta_generic_to_shared(p);
}
__device__ __forceinline__ void cp16(unsigned dst, const void* src, int sz) {
    asm volatile("cp.async.cg.shared.global [%0], [%1], 16, %2;"
                 :: "r"(dst), "l"(src), "r"(sz));
}
__device__ __forceinline__ void cp_commit() {
    asm volatile("cp.async.commit_group;");
}
template<int N> __device__ __forceinline__ void cp_wait() {
    asm volatile("cp.async.wait_group %0;" :: "n"(N));
}
__device__ __forceinline__ void ldsm_x4(unsigned& r0, unsigned& r1,
                                        unsigned& r2, unsigned& r3, unsigned addr) {
    asm volatile("ldmatrix.sync.aligned.m8n8.x4.shared.b16 {%0,%1,%2,%3}, [%4];"
                 : "=r"(r0), "=r"(r1), "=r"(r2), "=r"(r3) : "r"(addr));
}

__global__ void zero_cnt_kernel() {
    if (threadIdx.x < NE) g_cnt[threadIdx.x] = 0;
}

// ---------------- RMSNorm: one block per token (stores tf32-rounded) -------
__global__ void rmsnorm_kernel(const float* __restrict__ x,
                               const float* __restrict__ g,
                               float* __restrict__ o) {
    int t = blockIdx.x;
    int tid = threadIdx.x;
    const float* xr = x + (size_t)t * DIM;
    float ss = 0.f;
    for (int i = tid; i < DIM; i += 256) { float v = xr[i]; ss += v * v; }
    #pragma unroll
    for (int o2 = 16; o2; o2 >>= 1) ss += __shfl_xor_sync(0xffffffffu, ss, o2);
    __shared__ float sw[8];
    if ((tid & 31) == 0) sw[tid >> 5] = ss;
    __syncthreads();
    if (tid < 8) {
        float v = sw[tid];
        #pragma unroll
        for (int o2 = 4; o2; o2 >>= 1) v += __shfl_xor_sync(0xffu, v, o2);
        if (tid == 0) sw[0] = v;
    }
    __syncthreads();
    float r = rsqrtf(sw[0] * (1.0f / DIM) + RMS_EPS);
    float* orow = o + (size_t)t * DIM;
    for (int i = tid; i < DIM; i += 256) orow[i] = tf32_rna(xr[i] * r * g[i]);
}

// ---------------- tf32 tensor-core GEMM, cp.async + ldmatrix A --------------
#define BM 128
#define BN 128
#define BK 16
#define SA 20
#define SB 136
#define A_STAGE_B (BM * SA * 4)
#define B_STAGE_B (BK * SB * 4)

__device__ __forceinline__ void mma_tf32(float c[4], unsigned a0, unsigned a1,
                                         unsigned a2, unsigned a3,
                                         unsigned b0, unsigned b1) {
    asm volatile(
        "mma.sync.aligned.m16n8k8.row.col.f32.tf32.tf32.f32 "
        "{%0,%1,%2,%3}, {%4,%5,%6,%7}, {%8,%9}, {%0,%1,%2,%3};"
        : "+f"(c[0]), "+f"(c[1]), "+f"(c[2]), "+f"(c[3])
        : "r"(a0), "r"(a1), "r"(a2), "r"(a3), "r"(b0), "r"(b1));
}

// epi: 0 = C=acc ; 1 = C=acc+R ; 2 = C=tf32(silu(C)*acc) ; 3 = atomicAdd(C[idx[r]], acc*wgt[r])
__global__ void __launch_bounds__(256, 2)
mma_gemm_kernel(const float* __restrict__ A, const float* __restrict__ B,
                float* __restrict__ C, const float* __restrict__ R,
                int M, int N, int K,
                const int* __restrict__ cnt,
                const int* __restrict__ gidx, const float* __restrict__ gwgt,
                int epi, int gatherA,
                const float* __restrict__ B2, const float* __restrict__ B3,
                float* __restrict__ C2, float* __restrict__ C3, int qkv,
                long aStride, long bStride, long cStride) {
    int ez = blockIdx.z;
    if (cnt)  cnt  += ez;
    if (gidx) gidx += (size_t)ez * TOKENS;
    if (gwgt) gwgt += (size_t)ez * TOKENS;
    A += (size_t)ez * aStride;
    B += (size_t)ez * bStride;
    C += (size_t)ez * cStride;

    int Meff = cnt ? *cnt : M;
    int rowBase = blockIdx.y * BM;
    if (rowBase >= Meff) return;

    __shared__ __align__(16) float As[2][BM][SA];
    __shared__ __align__(16) float Bs[2][BK][SB];

    int tid  = threadIdx.x;
    int lane = tid & 31;
    int wid  = tid >> 5;
    int wm   = wid & 1;
    int wn   = wid >> 1;
    int nBase = blockIdx.x * BN;

    const float* Bq = B; float* Cq = C; int ld = N; int nLoc = nBase;
    if (qkv) {
        if (nBase >= 1280)      { Bq = B3; Cq = C3; ld = 256;  nLoc = nBase - 1280; }
        else if (nBase >= 1024) { Bq = B2; Cq = C2; ld = 256;  nLoc = nBase - 1024; }
        else                    {                   ld = 1024; }
    }

    float acc[4][4][4];
    #pragma unroll
    for (int i = 0; i < 4; i++)
        #pragma unroll
        for (int j = 0; j < 4; j++)
            #pragma unroll
            for (int q = 0; q < 4; q++) acc[i][j][q] = 0.f;

    // copy assignments: 2 float4 slots per thread for A and for B
    const float* aSrc[2]; int aSz[2]; unsigned aDst[2];
    const float* bSrc[2]; unsigned bDst[2];
    #pragma unroll
    for (int s = 0; s < 2; s++) {
        int fid = tid + s * 256;
        int row = rowBase + (fid >> 2);
        bool ok = row < Meff;
        long src = 0;
        if (ok) src = gatherA ? (long)gidx[row] : (long)row;
        aSrc[s] = A + src * (size_t)K + ((fid & 3) << 2);
        aSz[s]  = ok ? 16 : 0;
        aDst[s] = smem_u32(&As[0][fid >> 2][(fid & 3) << 2]);
        bSrc[s] = Bq + (size_t)(fid >> 5) * ld + nLoc + ((fid & 31) << 2);
        bDst[s] = smem_u32(&Bs[0][fid >> 5][(fid & 31) << 2]);
    }

    int nIter = K / BK;
    #pragma unroll
    for (int s = 0; s < 2; s++) {
        cp16(aDst[s], aSrc[s], aSz[s]);
        cp16(bDst[s], bSrc[s], 16);
    }
    cp_commit();
    if (nIter > 1) {
        #pragma unroll
        for (int s = 0; s < 2; s++) {
            cp16(aDst[s] + A_STAGE_B, aSrc[s] + BK, aSz[s]);
            cp16(bDst[s] + B_STAGE_B, bSrc[s] + (size_t)BK * ld, 16);
        }
        cp_commit();
    }

    int r = lane >> 2, c = lane & 3;
    // ldmatrix per-lane A address: tiles (m0-7,k0-3),(m8-15,k0-3),(m0-7,k4-7),(m8-15,k4-7)
    int rowA = (lane & 7) + ((lane >> 3) & 1) * 8;
    int colA = (lane >> 4) * 4;
    unsigned aLane = smem_u32(&As[0][wm * 64 + rowA][colA]);

    for (int it = 0; it < nIter; it++) {
        int cur = it & 1;
        if (it + 1 < nIter) cp_wait<1>(); else cp_wait<0>();
        __syncthreads();

        #pragma unroll
        for (int ks = 0; ks < BK; ks += 8) {
            unsigned bf[4][2];
            #pragma unroll
            for (int j = 0; j < 4; j++) {
                int nC = wn * 32 + j * 8 + r;
                bf[j][0] = __float_as_uint(Bs[cur][ks + c][nC]);
                bf[j][1] = __float_as_uint(Bs[cur][ks + c + 4][nC]);
            }
            #pragma unroll
            for (int i = 0; i < 4; i++) {
                unsigned a0, a1, a2, a3;
                ldsm_x4(a0, a1, a2, a3,
                        aLane + cur * A_STAGE_B + (i * 16 * SA + ks) * 4);
                #pragma unroll
                for (int j = 0; j < 4; j++)
                    mma_tf32(acc[i][j], a0, a1, a2, a3, bf[j][0], bf[j][1]);
            }
        }
        __syncthreads();
        if (it + 2 < nIter) {
            int kt = (it + 2) * BK;
            #pragma unroll
            for (int s = 0; s < 2; s++) {
                cp16(aDst[s] + cur * A_STAGE_B, aSrc[s] + kt, aSz[s]);
                cp16(bDst[s] + cur * B_STAGE_B, bSrc[s] + (size_t)kt * ld, 16);
            }
            cp_commit();
        }
    }

    // epilogue
    #pragma unroll
    for (int i = 0; i < 4; i++) {
        int rbase = rowBase + wm * 64 + i * 16 + r;
        #pragma unroll
        for (int half = 0; half < 2; half++) {
            int rr = rbase + half * 8;
            if (rr >= Meff) continue;
            int tok = 0; float w = 0.f;
            if (epi == 3) { tok = gidx[rr]; w = gwgt[rr]; }
            #pragma unroll
            for (int j = 0; j < 4; j++) {
                int col = nLoc + wn * 32 + j * 8 + (c << 1);
                float v0 = acc[i][j][half * 2];
                float v1 = acc[i][j][half * 2 + 1];
                if (epi == 0) {
                    *(float2*)(Cq + (size_t)rr * ld + col) = make_float2(v0, v1);
                } else if (epi == 1) {
                    float2 rv = *(const float2*)(R + (size_t)rr * ld + col);
                    *(float2*)(Cq + (size_t)rr * ld + col) =
                        make_float2(v0 + rv.x, v1 + rv.y);
                } else if (epi == 2) {
                    float2 hv = *(float2*)(Cq + (size_t)rr * ld + col);
                    float s0 = hv.x / (1.f + __expf(-hv.x));
                    float s1 = hv.y / (1.f + __expf(-hv.y));
                    *(float2*)(Cq + (size_t)rr * ld + col) =
                        make_float2(tf32_rna(s0 * v0), tf32_rna(s1 * v1));
                } else {
                    float* cp = Cq + (size_t)tok * ld + col;
                    atomicAdd(cp,     v0 * w);
                    atomicAdd(cp + 1, v1 * w);
                }
            }
        }
    }
}

// ---------------- RoPE on q and k (in place) --------------------------------
__global__ void rope_kernel(float* __restrict__ q, float* __restrict__ k) {
    int id = blockIdx.x * blockDim.x + threadIdx.x;
    const int NQ = TOKENS * NH * 32;
    const int NK2 = TOKENS * NKV * 32;
    if (id >= NQ + NK2) return;
    float* base; int t, i;
    if (id < NQ) {
        t = id >> 9; int r = id & 511; int h = r >> 5; i = r & 31;
        base = q + ((size_t)t * NH + h) * HD;
    } else {
        int id2 = id - NQ;
        t = id2 >> 7; int r = id2 & 127; int h = r >> 5; i = r & 31;
        base = k + ((size_t)t * NKV + h) * HD;
    }
    int pos = t & (SEQ - 1);
    float inv = exp2f(-(float)i * 0.4152410118609203f);
    float fr = (float)pos * inv;
    float sn, cs;
    sincosf(fr, &sn, &cs);
    float x1 = base[i], x2 = base[i + 32];
    base[i]      = x1 * cs - x2 * sn;
    base[i + 32] = x2 * cs + x1 * sn;
}

// ---------------- flash attention: 128 q-rows x 64-key tiles, 8 warps -------
// dyn smem (floats): K0,K1 (64x68) | V0,V1 (64x72) | P (128x68)
#define KST 68
#define VST 72
#define KTILE_F (64 * KST)
#define VTILE_F (64 * VST)
#define KTILE_B (KTILE_F * 4)
#define VTILE_B (VTILE_F * 4)
#define OFF_V_F (2 * KTILE_F)
#define OFF_P_F (2 * KTILE_F + 2 * VTILE_F)
#define FLASH_SMEM_B ((OFF_P_F + 128 * KST) * 4)

__global__ void __launch_bounds__(256, 1)
flash_attn_kernel(const float* __restrict__ q,
                  const float* __restrict__ k,
                  const float* __restrict__ v,
                  float* __restrict__ att) {
    extern __shared__ float fs[];
    float* Pb = fs + OFF_P_F;

    int qi = (SEQ / 128 - 1) - blockIdx.x;   // long tiles launch first
    int h  = blockIdx.y;
    int b  = blockIdx.z;
    int hk = h >> 2;
    int qbase = qi * 128;

    int tid  = threadIdx.x;
    int lane = tid & 31;
    int w    = tid >> 5;
    int lr   = lane >> 2;
    int cq   = lane & 3;
    int row0 = w * 16 + lr;
    int row1 = row0 + 8;

    unsigned fsBase = smem_u32(fs);
    // P (A-style) ldmatrix lane address
    int rowA = (lane & 7) + ((lane >> 3) & 1) * 8;
    int colA = (lane >> 4) * 4;
    unsigned pLane = fsBase + (unsigned)((OFF_P_F + (w * 16 + rowA) * KST + colA) * 4);
    // K (B-style, two n8 tiles per x4) ldmatrix lane address
    int rowK = (lane & 7) + ((lane >> 4) & 1) * 8;
    int colK = ((lane >> 3) & 1) * 4;
    unsigned kLane = fsBase + (unsigned)((rowK * KST + colK) * 4);

    const size_t kvstride = (size_t)NKV * HD;
    const float* kb = k + ((size_t)(b * SEQ) * NKV + hk) * HD;
    const float* vb = v + ((size_t)(b * SEQ) * NKV + hk) * HD;

    // cp.async slots: 4 float4 per thread for each of K and V
    unsigned kDst[4], vDst[4]; const float* kSrc[4]; const float* vSrc[4];
    #pragma unroll
    for (int it = 0; it < 4; it++) {
        int idx = tid + it * 256;
        int rrow = idx >> 4;
        int ccol = (idx & 15) << 2;
        kDst[it] = fsBase + (unsigned)((rrow * KST + ccol) * 4);
        vDst[it] = fsBase + (unsigned)((OFF_V_F + rrow * VST + ccol) * 4);
        kSrc[it] = kb + (size_t)rrow * kvstride + ccol;
        vSrc[it] = vb + (size_t)rrow * kvstride + ccol;
    }

    // Q fragments (pre-scaled by 1/sqrt(HD) = 0.125)
    unsigned qa[8][4];
    {
        const float* q0 = q + ((size_t)(b * SEQ + qbase + row0) * NH + h) * HD;
        const float* q1 = q + ((size_t)(b * SEQ + qbase + row1) * NH + h) * HD;
        #pragma unroll
        for (int ks8 = 0; ks8 < 8; ks8++) {
            int kk = ks8 * 8;
            qa[ks8][0] = __float_as_uint(q0[kk + cq] * 0.125f);
            qa[ks8][1] = __float_as_uint(q1[kk + cq] * 0.125f);
            qa[ks8][2] = __float_as_uint(q0[kk + cq + 4] * 0.125f);
            qa[ks8][3] = __float_as_uint(q1[kk + cq + 4] * 0.125f);
        }
    }

    float oacc[8][4];
    #pragma unroll
    for (int nf = 0; nf < 8; nf++)
        #pragma unroll
        for (int t2 = 0; t2 < 4; t2++) oacc[nf][t2] = 0.f;
    float m0 = -3.0e38f, m1 = -3.0e38f, l0 = 0.f, l1 = 0.f;

    int nkt = 2 * qi + 2;

    // prefetch tile 0 into buffer 0
    #pragma unroll
    for (int it = 0; it < 4; it++) {
        cp16(kDst[it], kSrc[it], 16);
        cp16(vDst[it], vSrc[it], 16);
    }
    cp_commit();

    for (int kt = 0; kt < nkt; kt++) {
        int cur = kt & 1;
        __syncthreads();   // all reads of buffer cur^1 finished
        if (kt + 1 < nkt) {
            size_t off = (size_t)(kt + 1) * 64 * kvstride;
            int nb = cur ^ 1;
            #pragma unroll
            for (int it = 0; it < 4; it++) {
                cp16(kDst[it] + nb * KTILE_B, kSrc[it] + off, 16);
                cp16(vDst[it] + nb * VTILE_B, vSrc[it] + off, 16);
            }
            cp_commit();
            cp_wait<1>();
        } else {
            cp_wait<0>();
        }
        __syncthreads();   // current tile visible CTA-wide

        const float* Vsf = fs + OFF_V_F + cur * VTILE_F;

        // S = Q @ K^T  (K B-frags via ldmatrix: 2 n8 tiles per x4)
        float s[8][4];
        #pragma unroll
        for (int nf = 0; nf < 8; nf++)
            #pragma unroll
            for (int t2 = 0; t2 < 4; t2++) s[nf][t2] = 0.f;
        #pragma unroll
        for (int ks8 = 0; ks8 < 8; ks8++) {
            int kk = ks8 * 8;
            #pragma unroll
            for (int nfp = 0; nfp < 4; nfp++) {
                unsigned kb0, kb1, kb2, kb3;
                ldsm_x4(kb0, kb1, kb2, kb3,
                        kLane + cur * KTILE_B + (unsigned)((nfp * 16 * KST + kk) * 4));
                mma_tf32(s[2 * nfp],     qa[ks8][0], qa[ks8][1], qa[ks8][2], qa[ks8][3], kb0, kb1);
                mma_tf32(s[2 * nfp + 1], qa[ks8][0], qa[ks8][1], qa[ks8][2], qa[ks8][3], kb2, kb3);
            }
        }

        // causal mask on the (up to two) diagonal tiles
        if (kt + 2 >= nkt) {
            int dk = kt * 64 - qbase;
            #pragma unroll
            for (int nf = 0; nf < 8; nf++) {
                int c0 = nf * 8 + cq * 2 + dk;
                if (c0     > row0) s[nf][0] = -3.0e38f;
                if (c0 + 1 > row0) s[nf][1] = -3.0e38f;
                if (c0     > row1) s[nf][2] = -3.0e38f;
                if (c0 + 1 > row1) s[nf][3] = -3.0e38f;
            }
        }

        // online softmax
        float rm0 = -3.0e38f, rm1 = -3.0e38f;
        #pragma unroll
        for (int nf = 0; nf < 8; nf++) {
            rm0 = fmaxf(rm0, fmaxf(s[nf][0], s[nf][1]));
            rm1 = fmaxf(rm1, fmaxf(s[nf][2], s[nf][3]));
        }
        rm0 = fmaxf(rm0, __shfl_xor_sync(0xffffffffu, rm0, 1));
        rm0 = fmaxf(rm0, __shfl_xor_sync(0xffffffffu, rm0, 2));
        rm1 = fmaxf(rm1, __shfl_xor_sync(0xffffffffu, rm1, 1));
        rm1 = fmaxf(rm1, __shfl_xor_sync(0xffffffffu, rm1, 2));
        float mn0 = fmaxf(m0, rm0), mn1 = fmaxf(m1, rm1);
        float sc0 = __expf(m0 - mn0), sc1 = __expf(m1 - mn1);
        m0 = mn0; m1 = mn1;
        l0 *= sc0; l1 *= sc1;
        #pragma unroll
        for (int nf = 0; nf < 8; nf++) {
            float p0 = __expf(s[nf][0] - mn0);
            float p1 = __expf(s[nf][1] - mn0);
            float p2 = __expf(s[nf][2] - mn1);
            float p3 = __expf(s[nf][3] - mn1);
            l0 += p0 + p1; l1 += p2 + p3;
            int c0 = nf * 8 + cq * 2;
            *(float2*)&Pb[row0 * KST + c0] = make_float2(p0, p1);
            *(float2*)&Pb[row1 * KST + c0] = make_float2(p2, p3);
            oacc[nf][0] *= sc0; oacc[nf][1] *= sc0;
            oacc[nf][2] *= sc1; oacc[nf][3] *= sc1;
        }
        __syncwarp();      // P rows are warp-private

        // O += P @ V   (P A-frags via ldmatrix; V stride 72 = conflict-free)
        #pragma unroll
        for (int ks8 = 0; ks8 < 8; ks8++) {
            int kk = ks8 * 8;
            unsigned a0, a1, a2, a3;
            ldsm_x4(a0, a1, a2, a3, pLane + (unsigned)(kk * 4));
            #pragma unroll
            for (int nf = 0; nf < 8; nf++) {
                unsigned b0 = __float_as_uint(Vsf[(kk + cq) * VST + nf * 8 + lr]);
                unsigned b1 = __float_as_uint(Vsf[(kk + cq + 4) * VST + nf * 8 + lr]);
                mma_tf32(oacc[nf], a0, a1, a2, a3, b0, b1);
            }
        }
    }

    // finalize
    l0 += __shfl_xor_sync(0xffffffffu, l0, 1);
    l0 += __shfl_xor_sync(0xffffffffu, l0, 2);
    l1 += __shfl_xor_sync(0xffffffffu, l1, 1);
    l1 += __shfl_xor_sync(0xffffffffu, l1, 2);
    float i0 = 1.f / l0, i1 = 1.f / l1;
    float* o0 = att + ((size_t)(b * SEQ + qbase + row0) * NH + h) * HD;
    float* o1 = att + ((size_t)(b * SEQ + qbase + row1) * NH + h) * HD;
    #pragma unroll
    for (int nf = 0; nf < 8; nf++) {
        int c0 = nf * 8 + cq * 2;
        *(float2*)(o0 + c0) = make_float2(tf32_rna(oacc[nf][0] * i0),
                                          tf32_rna(oacc[nf][1] * i0));
        *(float2*)(o1 + c0) = make_float2(tf32_rna(oacc[nf][2] * i1),
                                          tf32_rna(oacc[nf][3] * i1));
    }
}

// ---------------- MoE gating: one warp per token -----------------------------
__global__ void gate_kernel(const float* __restrict__ xn, const float* __restrict__ gate) {
    int gw = (int)((blockIdx.x * (size_t)blockDim.x + threadIdx.x) >> 5);
    int lane = threadIdx.x & 31;
    if (gw >= TOKENS) return;
    const float* xr = xn + (size_t)gw * DIM;
    float a0 = 0.f, a1 = 0.f, a2 = 0.f, a3 = 0.f;
    for (int i = lane; i < DIM; i += 32) {
        float xv = xr[i];
        const float* gr = gate + (size_t)i * NE;
        a0 += xv * gr[0]; a1 += xv * gr[1]; a2 += xv * gr[2]; a3 += xv * gr[3];
    }
    #pragma unroll
    for (int o2 = 16; o2; o2 >>= 1) {
        a0 += __shfl_xor_sync(0xffffffffu, a0, o2);
        a1 += __shfl_xor_sync(0xffffffffu, a1, o2);
        a2 += __shfl_xor_sync(0xffffffffu, a2, o2);
        a3 += __shfl_xor_sync(0xffffffffu, a3, o2);
    }
    if (lane == 0) {
        float p[NE] = {a0, a1, a2, a3};
        float mx = p[0];
        #pragma unroll
        for (int e = 1; e < NE; e++) mx = fmaxf(mx, p[e]);
        #pragma unroll
        for (int e = 0; e < NE; e++) p[e] = __expf(p[e] - mx);
        int e0 = 0;
        #pragma unroll
        for (int e = 1; e < NE; e++) if (p[e] > p[e0]) e0 = e;
        int e1 = -1;
        #pragma unroll
        for (int e = 0; e < NE; e++) if (e != e0 && (e1 < 0 || p[e] > p[e1])) e1 = e;
        float w0 = p[e0], w1 = p[e1];
        float ws = w0 + w1;
        w0 /= ws; w1 /= ws;
        int s0 = atomicAdd(&g_cnt[e0], 1);
        g_idx[e0 * TOKENS + s0] = gw; g_wgt[e0 * TOKENS + s0] = w0;
        int s1 = atomicAdd(&g_cnt[e1], 1);
        g_idx[e1 * TOKENS + s1] = gw; g_wgt[e1 * TOKENS + s1] = w1;
    }
}

// ---------------- launch ------------------------------------------------------
static inline void launch_gemm(const float* A, const float* B, float* C, const float* R,
                               int M, int N, int K,
                               const int* cnt, const int* gi, const float* gw,
                               int epi, int gat, int nz,
                               long aS, long bS, long cS) {
    dim3 grid(N / BN, (M + BM - 1) / BM, nz);
    mma_gemm_kernel<<<grid, 256>>>(A, B, C, R, M, N, K, cnt, gi, gw, epi, gat,
                                   nullptr, nullptr, nullptr, nullptr, 0,
                                   aS, bS, cS);
}

extern "C" void kernel_launch(void* const* d_in, const int* in_sizes, int n_in,
                              void* d_out, int out_size) {
    const float* x    = (const float*)d_in[0];
    const float* g1   = (const float*)d_in[1];
    const float* g2   = (const float*)d_in[2];
    const float* wq   = (const float*)d_in[3];
    const float* wk   = (const float*)d_in[4];
    const float* wv   = (const float*)d_in[5];
    const float* wo   = (const float*)d_in[6];
    const float* gate = (const float*)d_in[7];
    const float* w1   = (const float*)d_in[8];
    const float* w2   = (const float*)d_in[9];
    const float* w3   = (const float*)d_in[10];
    float* out = (float*)d_out;

    float *xn, *q, *k, *v, *att, *h, *wgt;
    int *cnt, *idx;
    cudaGetSymbolAddress((void**)&xn,  g_xn);
    cudaGetSymbolAddress((void**)&q,   g_q);
    cudaGetSymbolAddress((void**)&k,   g_k);
    cudaGetSymbolAddress((void**)&v,   g_v);
    cudaGetSymbolAddress((void**)&att, g_att);
    cudaGetSymbolAddress((void**)&h,   g_h);
    cudaGetSymbolAddress((void**)&cnt, g_cnt);
    cudaGetSymbolAddress((void**)&idx, g_idx);
    cudaGetSymbolAddress((void**)&wgt, g_wgt);

    // unconditional (no static guards allowed); idempotent host-side call
    cudaFuncSetAttribute(flash_attn_kernel,
                         cudaFuncAttributeMaxDynamicSharedMemorySize,
                         FLASH_SMEM_B);

    zero_cnt_kernel<<<1, 32>>>();

    // ---- attention branch ----
    rmsnorm_kernel<<<TOKENS, 256>>>(x, g1, xn);

    // fused q/k/v projection: virtual N = 1536 (1024 q | 256 k | 256 v)
    {
        dim3 grid(1536 / BN, TOKENS / BM, 1);
        mma_gemm_kernel<<<grid, 256>>>(xn, wq, q, nullptr, TOKENS, 1536, DIM,
                                       nullptr, nullptr, nullptr, 0, 0,
                                       wk, wv, k, v, 1, 0, 0, 0);
    }

    int ropeN = TOKENS * NH * 32 + TOKENS * NKV * 32;
    rope_kernel<<<(ropeN + 255) / 256, 256>>>(q, k);

    {
        dim3 grid(SEQ / 128, NH, 2);
        flash_attn_kernel<<<grid, 256, FLASH_SMEM_B>>>(q, k, v, att);
    }

    // out = x + att @ wo
    launch_gemm(att, wo, out, x, TOKENS, DIM, DIM, nullptr, nullptr, nullptr,
                1, 0, 1, 0, 0, 0);

    // ---- MoE branch ----
    rmsnorm_kernel<<<TOKENS, 256>>>(out, g2, xn);
    gate_kernel<<<TOKENS / 8, 256>>>(xn, gate);

    // all experts in one launch each (gridDim.z = NE)
    launch_gemm(xn, w1, h, nullptr, TOKENS, HIDDEN, DIM, cnt, idx, nullptr,
                0, 1, NE, 0, (long)DIM * HIDDEN, (long)TOKENS * HIDDEN);
    launch_gemm(xn, w3, h, nullptr, TOKENS, HIDDEN, DIM, cnt, idx, nullptr,
                2, 1, NE, 0, (long)DIM * HIDDEN, (long)TOKENS * HIDDEN);
    launch_gemm(h, w2, out, nullptr, TOKENS, DIM, HIDDEN, cnt, idx, wgt,
                3, 0, NE, (long)TOKENS * HIDDEN, (long)HIDDEN * DIM, 0);
}

// round 9
// speedup vs baseline: 6.8955x; 1.0708x over previous
#include <cuda_runtime.h>
#include <math.h>

#define TOKENS 4096
#define DIM    1024
#define SEQ    2048
#define NH     16
#define NKV    4
#define HD     64
#define HIDDEN 3072
#define NE     4
#define RMS_EPS 1.1920928955078125e-07f

// ---------------- scratch (device globals; no allocation allowed) ----------
__device__ float g_xn [TOKENS * DIM];
__device__ float g_q  [TOKENS * DIM];
__device__ float g_k  [TOKENS * NKV * HD];
__device__ float g_v  [TOKENS * NKV * HD];
__device__ float g_att[TOKENS * DIM];
__device__ float g_h  [NE * TOKENS * HIDDEN];   // per-expert hidden
__device__ int   g_cnt[NE];
__device__ int   g_idx[NE * TOKENS];
__device__ float g_wgt[NE * TOKENS];

__device__ __forceinline__ float tf32_rna(float x) {
    unsigned u;
    asm("cvt.rna.tf32.f32 %0, %1;" : "=r"(u) : "f"(x));
    return __uint_as_float(u);
}

__device__ __forceinline__ unsigned smem_u32(const void* p) {
    return (unsigned)__cvta_generic_to_shared(p);
}
__device__ __forceinline__ void cp16(unsigned dst, const void* src, int sz) {
    asm volatile("cp.async.cg.shared.global [%0], [%1], 16, %2;"
                 :: "r"(dst), "l"(src), "r"(sz));
}
__device__ __forceinline__ void cp_commit() {
    asm volatile("cp.async.commit_group;");
}
template<int N> __device__ __forceinline__ void cp_wait() {
    asm volatile("cp.async.wait_group %0;" :: "n"(N));
}
__device__ __forceinline__ void ldsm_x4(unsigned& r0, unsigned& r1,
                                        unsigned& r2, unsigned& r3, unsigned addr) {
    asm volatile("ldmatrix.sync.aligned.m8n8.x4.shared.b16 {%0,%1,%2,%3}, [%4];"
                 : "=r"(r0), "=r"(r1), "=r"(r2), "=r"(r3) : "r"(addr));
}

// ---------------- RMSNorm (+optional fused MoE gate, +optional cnt zero) ----
__global__ void rmsnorm_kernel(const float* __restrict__ x,
                               const float* __restrict__ g,
                               float* __restrict__ o,
                               const float* __restrict__ gate,
                               int zcnt) {
    int t = blockIdx.x;
    int tid = threadIdx.x;
    if (zcnt && t == 0 && tid < NE) g_cnt[tid] = 0;
    const float* xr = x + (size_t)t * DIM;
    float ss = 0.f;
    for (int i = tid; i < DIM; i += 256) { float v = xr[i]; ss += v * v; }
    #pragma unroll
    for (int o2 = 16; o2; o2 >>= 1) ss += __shfl_xor_sync(0xffffffffu, ss, o2);
    __shared__ float sw[8];
    __shared__ float sg[8][NE];
    if ((tid & 31) == 0) sw[tid >> 5] = ss;
    __syncthreads();
    if (tid < 8) {
        float v = sw[tid];
        #pragma unroll
        for (int o2 = 4; o2; o2 >>= 1) v += __shfl_xor_sync(0xffu, v, o2);
        if (tid == 0) sw[0] = v;
    }
    __syncthreads();
    float r = rsqrtf(sw[0] * (1.0f / DIM) + RMS_EPS);
    float* orow = o + (size_t)t * DIM;
    if (!gate) {
        for (int i = tid; i < DIM; i += 256) orow[i] = tf32_rna(xr[i] * r * g[i]);
        return;
    }
    // fused gating: accumulate logits while storing
    float a0 = 0.f, a1 = 0.f, a2 = 0.f, a3 = 0.f;
    for (int i = tid; i < DIM; i += 256) {
        float val = tf32_rna(xr[i] * r * g[i]);
        orow[i] = val;
        const float* gr = gate + (size_t)i * NE;
        a0 += val * gr[0]; a1 += val * gr[1];
        a2 += val * gr[2]; a3 += val * gr[3];
    }
    #pragma unroll
    for (int o2 = 16; o2; o2 >>= 1) {
        a0 += __shfl_xor_sync(0xffffffffu, a0, o2);
        a1 += __shfl_xor_sync(0xffffffffu, a1, o2);
        a2 += __shfl_xor_sync(0xffffffffu, a2, o2);
        a3 += __shfl_xor_sync(0xffffffffu, a3, o2);
    }
    int lane = tid & 31;
    if (lane == 0) {
        int w = tid >> 5;
        sg[w][0] = a0; sg[w][1] = a1; sg[w][2] = a2; sg[w][3] = a3;
    }
    __syncthreads();
    if (tid == 0) {
        float p[NE];
        #pragma unroll
        for (int e = 0; e < NE; e++) {
            float s = 0.f;
            #pragma unroll
            for (int w = 0; w < 8; w++) s += sg[w][e];
            p[e] = s;
        }
        float mx = p[0];
        #pragma unroll
        for (int e = 1; e < NE; e++) mx = fmaxf(mx, p[e]);
        #pragma unroll
        for (int e = 0; e < NE; e++) p[e] = __expf(p[e] - mx);
        int e0 = 0;
        #pragma unroll
        for (int e = 1; e < NE; e++) if (p[e] > p[e0]) e0 = e;
        int e1 = -1;
        #pragma unroll
        for (int e = 0; e < NE; e++) if (e != e0 && (e1 < 0 || p[e] > p[e1])) e1 = e;
        float w0 = p[e0], w1 = p[e1];
        float ws = w0 + w1;
        w0 /= ws; w1 /= ws;
        int s0 = atomicAdd(&g_cnt[e0], 1);
        g_idx[e0 * TOKENS + s0] = t; g_wgt[e0 * TOKENS + s0] = w0;
        int s1 = atomicAdd(&g_cnt[e1], 1);
        g_idx[e1 * TOKENS + s1] = t; g_wgt[e1 * TOKENS + s1] = w1;
    }
}

// ---------------- tf32 tensor-core GEMM, cp.async, BK=32, dynamic smem ------
#define BM 128
#define BN 128
#define BK 32
#define SA 36
#define SB 136
#define A_STAGE_F (BM * SA)
#define B_STAGE_F (BK * SB)
#define A_STAGE_B (A_STAGE_F * 4)
#define B_STAGE_B (B_STAGE_F * 4)
#define GEMM_SMEM_B ((2 * A_STAGE_F + 2 * B_STAGE_F) * 4)

__device__ __forceinline__ void mma_tf32(float c[4], unsigned a0, unsigned a1,
                                         unsigned a2, unsigned a3,
                                         unsigned b0, unsigned b1) {
    asm volatile(
        "mma.sync.aligned.m16n8k8.row.col.f32.tf32.tf32.f32 "
        "{%0,%1,%2,%3}, {%4,%5,%6,%7}, {%8,%9}, {%0,%1,%2,%3};"
        : "+f"(c[0]), "+f"(c[1]), "+f"(c[2]), "+f"(c[3])
        : "r"(a0), "r"(a1), "r"(a2), "r"(a3), "r"(b0), "r"(b1));
}

// epi: 0 = C=acc ; 1 = C=acc+R ; 2 = C=tf32(silu(C)*acc) ; 3 = atomicAdd(C[idx[r]], acc*wgt[r])
__global__ void __launch_bounds__(256, 2)
mma_gemm_kernel(const float* __restrict__ A, const float* __restrict__ B,
                float* __restrict__ C, const float* __restrict__ R,
                int M, int N, int K,
                const int* __restrict__ cnt,
                const int* __restrict__ gidx, const float* __restrict__ gwgt,
                int epi, int gatherA,
                const float* __restrict__ B2, const float* __restrict__ B3,
                float* __restrict__ C2, float* __restrict__ C3, int qkv,
                long aStride, long bStride, long cStride) {
    int ez = blockIdx.z;
    if (cnt)  cnt  += ez;
    if (gidx) gidx += (size_t)ez * TOKENS;
    if (gwgt) gwgt += (size_t)ez * TOKENS;
    A += (size_t)ez * aStride;
    B += (size_t)ez * bStride;
    C += (size_t)ez * cStride;

    int Meff = cnt ? *cnt : M;
    int rowBase = blockIdx.y * BM;
    if (rowBase >= Meff) return;

    extern __shared__ __align__(16) float gsm[];
    float* As = gsm;                        // [2][BM][SA]
    float* Bs = gsm + 2 * A_STAGE_F;        // [2][BK][SB]

    int tid  = threadIdx.x;
    int lane = tid & 31;
    int wid  = tid >> 5;
    int wm   = wid & 1;
    int wn   = wid >> 1;
    int nBase = blockIdx.x * BN;

    const float* Bq = B; float* Cq = C; int ld = N; int nLoc = nBase;
    if (qkv) {
        if (nBase >= 1280)      { Bq = B3; Cq = C3; ld = 256;  nLoc = nBase - 1280; }
        else if (nBase >= 1024) { Bq = B2; Cq = C2; ld = 256;  nLoc = nBase - 1024; }
        else                    {                   ld = 1024; }
    }

    float acc[4][4][4];
    #pragma unroll
    for (int i = 0; i < 4; i++)
        #pragma unroll
        for (int j = 0; j < 4; j++)
            #pragma unroll
            for (int q = 0; q < 4; q++) acc[i][j][q] = 0.f;

    // copy assignments: 4 float4 slots per thread for A and for B
    const float* aSrc[4]; int aSz[4]; unsigned aDst[4];
    const float* bSrc[4]; unsigned bDst[4];
    #pragma unroll
    for (int s = 0; s < 4; s++) {
        int fid = tid + s * 256;            // 0..1023
        int arow = fid >> 3;                // 128 rows, 8 float4 each
        int acol = (fid & 7) << 2;
        int row = rowBase + arow;
        bool ok = row < Meff;
        long src = 0;
        if (ok) src = gatherA ? (long)gidx[row] : (long)row;
        aSrc[s] = A + src * (size_t)K + acol;
        aSz[s]  = ok ? 16 : 0;
        aDst[s] = smem_u32(As + arow * SA + acol);
        int brow = fid >> 5;                // 32 rows, 32 float4 each
        int bcol = (fid & 31) << 2;
        bSrc[s] = Bq + (size_t)brow * ld + nLoc + bcol;
        bDst[s] = smem_u32(Bs + brow * SB + bcol);
    }

    int nIter = K / BK;
    #pragma unroll
    for (int s = 0; s < 4; s++) {
        cp16(aDst[s], aSrc[s], aSz[s]);
        cp16(bDst[s], bSrc[s], 16);
    }
    cp_commit();
    if (nIter > 1) {
        #pragma unroll
        for (int s = 0; s < 4; s++) {
            cp16(aDst[s] + A_STAGE_B, aSrc[s] + BK, aSz[s]);
            cp16(bDst[s] + B_STAGE_B, bSrc[s] + (size_t)BK * ld, 16);
        }
        cp_commit();
    }

    int r = lane >> 2, c = lane & 3;
    // ldmatrix per-lane A address
    int rowA = (lane & 7) + ((lane >> 3) & 1) * 8;
    int colA = (lane >> 4) * 4;
    unsigned aLane = smem_u32(As + (wm * 64 + rowA) * SA + colA);

    for (int it = 0; it < nIter; it++) {
        int cur = it & 1;
        if (it + 1 < nIter) cp_wait<1>(); else cp_wait<0>();
        __syncthreads();

        #pragma unroll
        for (int ks = 0; ks < BK; ks += 8) {
            unsigned bf[4][2];
            #pragma unroll
            for (int j = 0; j < 4; j++) {
                int nC = wn * 32 + j * 8 + r;
                bf[j][0] = __float_as_uint(Bs[cur * B_STAGE_F + (ks + c) * SB + nC]);
                bf[j][1] = __float_as_uint(Bs[cur * B_STAGE_F + (ks + c + 4) * SB + nC]);
            }
            #pragma unroll
            for (int i = 0; i < 4; i++) {
                unsigned a0, a1, a2, a3;
                ldsm_x4(a0, a1, a2, a3,
                        aLane + cur * A_STAGE_B + (unsigned)((i * 16 * SA + ks) * 4));
                #pragma unroll
                for (int j = 0; j < 4; j++)
                    mma_tf32(acc[i][j], a0, a1, a2, a3, bf[j][0], bf[j][1]);
            }
        }
        __syncthreads();
        if (it + 2 < nIter) {
            int kt = (it + 2) * BK;
            #pragma unroll
            for (int s = 0; s < 4; s++) {
                cp16(aDst[s] + cur * A_STAGE_B, aSrc[s] + kt, aSz[s]);
                cp16(bDst[s] + cur * B_STAGE_B, bSrc[s] + (size_t)kt * ld, 16);
            }
            cp_commit();
        }
    }

    // epilogue
    #pragma unroll
    for (int i = 0; i < 4; i++) {
        int rbase = rowBase + wm * 64 + i * 16 + r;
        #pragma unroll
        for (int half = 0; half < 2; half++) {
            int rr = rbase + half * 8;
            if (rr >= Meff) continue;
            int tok = 0; float w = 0.f;
            if (epi == 3) { tok = gidx[rr]; w = gwgt[rr]; }
            #pragma unroll
            for (int j = 0; j < 4; j++) {
                int col = nLoc + wn * 32 + j * 8 + (c << 1);
                float v0 = acc[i][j][half * 2];
                float v1 = acc[i][j][half * 2 + 1];
                if (epi == 0) {
                    *(float2*)(Cq + (size_t)rr * ld + col) = make_float2(v0, v1);
                } else if (epi == 1) {
                    float2 rv = *(const float2*)(R + (size_t)rr * ld + col);
                    *(float2*)(Cq + (size_t)rr * ld + col) =
                        make_float2(v0 + rv.x, v1 + rv.y);
                } else if (epi == 2) {
                    float2 hv = *(float2*)(Cq + (size_t)rr * ld + col);
                    float s0 = hv.x / (1.f + __expf(-hv.x));
                    float s1 = hv.y / (1.f + __expf(-hv.y));
                    *(float2*)(Cq + (size_t)rr * ld + col) =
                        make_float2(tf32_rna(s0 * v0), tf32_rna(s1 * v1));
                } else {
                    float* cp = Cq + (size_t)tok * ld + col;
                    atomicAdd(cp,     v0 * w);
                    atomicAdd(cp + 1, v1 * w);
                }
            }
        }
    }
}

// ---------------- RoPE on q and k (in place) --------------------------------
__global__ void rope_kernel(float* __restrict__ q, float* __restrict__ k) {
    int id = blockIdx.x * blockDim.x + threadIdx.x;
    const int NQ = TOKENS * NH * 32;
    const int NK2 = TOKENS * NKV * 32;
    if (id >= NQ + NK2) return;
    float* base; int t, i;
    if (id < NQ) {
        t = id >> 9; int r = id & 511; int h = r >> 5; i = r & 31;
        base = q + ((size_t)t * NH + h) * HD;
    } else {
        int id2 = id - NQ;
        t = id2 >> 7; int r = id2 & 127; int h = r >> 5; i = r & 31;
        base = k + ((size_t)t * NKV + h) * HD;
    }
    int pos = t & (SEQ - 1);
    float inv = exp2f(-(float)i * 0.4152410118609203f);
    float fr = (float)pos * inv;
    float sn, cs;
    sincosf(fr, &sn, &cs);
    float x1 = base[i], x2 = base[i + 32];
    base[i]      = x1 * cs - x2 * sn;
    base[i + 32] = x2 * cs + x1 * sn;
}

// ---------------- flash attention: 128 q-rows x 64-key tiles, 8 warps -------
#define KST 68
#define VST 72
#define KTILE_F (64 * KST)
#define VTILE_F (64 * VST)
#define KTILE_B (KTILE_F * 4)
#define VTILE_B (VTILE_F * 4)
#define OFF_V_F (2 * KTILE_F)
#define OFF_P_F (2 * KTILE_F + 2 * VTILE_F)
#define FLASH_SMEM_B ((OFF_P_F + 128 * KST) * 4)

__global__ void __launch_bounds__(256, 1)
flash_attn_kernel(const float* __restrict__ q,
                  const float* __restrict__ k,
                  const float* __restrict__ v,
                  float* __restrict__ att) {
    extern __shared__ float fs[];
    float* Pb = fs + OFF_P_F;

    int qi = (SEQ / 128 - 1) - blockIdx.x;   // long tiles launch first
    int h  = blockIdx.y;
    int b  = blockIdx.z;
    int hk = h >> 2;
    int qbase = qi * 128;

    int tid  = threadIdx.x;
    int lane = tid & 31;
    int w    = tid >> 5;
    int lr   = lane >> 2;
    int cq   = lane & 3;
    int row0 = w * 16 + lr;
    int row1 = row0 + 8;

    unsigned fsBase = smem_u32(fs);
    int rowA = (lane & 7) + ((lane >> 3) & 1) * 8;
    int colA = (lane >> 4) * 4;
    unsigned pLane = fsBase + (unsigned)((OFF_P_F + (w * 16 + rowA) * KST + colA) * 4);
    int rowK = (lane & 7) + ((lane >> 4) & 1) * 8;
    int colK = ((lane >> 3) & 1) * 4;
    unsigned kLane = fsBase + (unsigned)((rowK * KST + colK) * 4);

    const size_t kvstride = (size_t)NKV * HD;
    const float* kb = k + ((size_t)(b * SEQ) * NKV + hk) * HD;
    const float* vb = v + ((size_t)(b * SEQ) * NKV + hk) * HD;

    unsigned kDst[4], vDst[4]; const float* kSrc[4]; const float* vSrc[4];
    #pragma unroll
    for (int it = 0; it < 4; it++) {
        int idx = tid + it * 256;
        int rrow = idx >> 4;
        int ccol = (idx & 15) << 2;
        kDst[it] = fsBase + (unsigned)((rrow * KST + ccol) * 4);
        vDst[it] = fsBase + (unsigned)((OFF_V_F + rrow * VST + ccol) * 4);
        kSrc[it] = kb + (size_t)rrow * kvstride + ccol;
        vSrc[it] = vb + (size_t)rrow * kvstride + ccol;
    }

    unsigned qa[8][4];
    {
        const float* q0 = q + ((size_t)(b * SEQ + qbase + row0) * NH + h) * HD;
        const float* q1 = q + ((size_t)(b * SEQ + qbase + row1) * NH + h) * HD;
        #pragma unroll
        for (int ks8 = 0; ks8 < 8; ks8++) {
            int kk = ks8 * 8;
            qa[ks8][0] = __float_as_uint(q0[kk + cq] * 0.125f);
            qa[ks8][1] = __float_as_uint(q1[kk + cq] * 0.125f);
            qa[ks8][2] = __float_as_uint(q0[kk + cq + 4] * 0.125f);
            qa[ks8][3] = __float_as_uint(q1[kk + cq + 4] * 0.125f);
        }
    }

    float oacc[8][4];
    #pragma unroll
    for (int nf = 0; nf < 8; nf++)
        #pragma unroll
        for (int t2 = 0; t2 < 4; t2++) oacc[nf][t2] = 0.f;
    float m0 = -3.0e38f, m1 = -3.0e38f, l0 = 0.f, l1 = 0.f;

    int nkt = 2 * qi + 2;

    #pragma unroll
    for (int it = 0; it < 4; it++) {
        cp16(kDst[it], kSrc[it], 16);
        cp16(vDst[it], vSrc[it], 16);
    }
    cp_commit();

    for (int kt = 0; kt < nkt; kt++) {
        int cur = kt & 1;
        __syncthreads();
        if (kt + 1 < nkt) {
            size_t off = (size_t)(kt + 1) * 64 * kvstride;
            int nb = cur ^ 1;
            #pragma unroll
            for (int it = 0; it < 4; it++) {
                cp16(kDst[it] + nb * KTILE_B, kSrc[it] + off, 16);
                cp16(vDst[it] + nb * VTILE_B, vSrc[it] + off, 16);
            }
            cp_commit();
            cp_wait<1>();
        } else {
            cp_wait<0>();
        }
        __syncthreads();

        const float* Vsf = fs + OFF_V_F + cur * VTILE_F;

        float s[8][4];
        #pragma unroll
        for (int nf = 0; nf < 8; nf++)
            #pragma unroll
            for (int t2 = 0; t2 < 4; t2++) s[nf][t2] = 0.f;
        #pragma unroll
        for (int ks8 = 0; ks8 < 8; ks8++) {
            int kk = ks8 * 8;
            #pragma unroll
            for (int nfp = 0; nfp < 4; nfp++) {
                unsigned kb0, kb1, kb2, kb3;
                ldsm_x4(kb0, kb1, kb2, kb3,
                        kLane + cur * KTILE_B + (unsigned)((nfp * 16 * KST + kk) * 4));
                mma_tf32(s[2 * nfp],     qa[ks8][0], qa[ks8][1], qa[ks8][2], qa[ks8][3], kb0, kb1);
                mma_tf32(s[2 * nfp + 1], qa[ks8][0], qa[ks8][1], qa[ks8][2], qa[ks8][3], kb2, kb3);
            }
        }

        if (kt + 2 >= nkt) {
            int dk = kt * 64 - qbase;
            #pragma unroll
            for (int nf = 0; nf < 8; nf++) {
                int c0 = nf * 8 + cq * 2 + dk;
                if (c0     > row0) s[nf][0] = -3.0e38f;
                if (c0 + 1 > row0) s[nf][1] = -3.0e38f;
                if (c0     > row1) s[nf][2] = -3.0e38f;
                if (c0 + 1 > row1) s[nf][3] = -3.0e38f;
            }
        }

        float rm0 = -3.0e38f, rm1 = -3.0e38f;
        #pragma unroll
        for (int nf = 0; nf < 8; nf++) {
            rm0 = fmaxf(rm0, fmaxf(s[nf][0], s[nf][1]));
            rm1 = fmaxf(rm1, fmaxf(s[nf][2], s[nf][3]));
        }
        rm0 = fmaxf(rm0, __shfl_xor_sync(0xffffffffu, rm0, 1));
        rm0 = fmaxf(rm0, __shfl_xor_sync(0xffffffffu, rm0, 2));
        rm1 = fmaxf(rm1, __shfl_xor_sync(0xffffffffu, rm1, 1));
        rm1 = fmaxf(rm1, __shfl_xor_sync(0xffffffffu, rm1, 2));
        float mn0 = fmaxf(m0, rm0), mn1 = fmaxf(m1, rm1);
        float sc0 = __expf(m0 - mn0), sc1 = __expf(m1 - mn1);
        m0 = mn0; m1 = mn1;
        l0 *= sc0; l1 *= sc1;
        #pragma unroll
        for (int nf = 0; nf < 8; nf++) {
            float p0 = __expf(s[nf][0] - mn0);
            float p1 = __expf(s[nf][1] - mn0);
            float p2 = __expf(s[nf][2] - mn1);
            float p3 = __expf(s[nf][3] - mn1);
            l0 += p0 + p1; l1 += p2 + p3;
            int c0 = nf * 8 + cq * 2;
            *(float2*)&Pb[row0 * KST + c0] = make_float2(p0, p1);
            *(float2*)&Pb[row1 * KST + c0] = make_float2(p2, p3);
            oacc[nf][0] *= sc0; oacc[nf][1] *= sc0;
            oacc[nf][2] *= sc1; oacc[nf][3] *= sc1;
        }
        __syncwarp();

        #pragma unroll
        for (int ks8 = 0; ks8 < 8; ks8++) {
            int kk = ks8 * 8;
            unsigned a0, a1, a2, a3;
            ldsm_x4(a0, a1, a2, a3, pLane + (unsigned)(kk * 4));
            #pragma unroll
            for (int nf = 0; nf < 8; nf++) {
                unsigned b0 = __float_as_uint(Vsf[(kk + cq) * VST + nf * 8 + lr]);
                unsigned b1 = __float_as_uint(Vsf[(kk + cq + 4) * VST + nf * 8 + lr]);
                mma_tf32(oacc[nf], a0, a1, a2, a3, b0, b1);
            }
        }
    }

    l0 += __shfl_xor_sync(0xffffffffu, l0, 1);
    l0 += __shfl_xor_sync(0xffffffffu, l0, 2);
    l1 += __shfl_xor_sync(0xffffffffu, l1, 1);
    l1 += __shfl_xor_sync(0xffffffffu, l1, 2);
    float i0 = 1.f / l0, i1 = 1.f / l1;
    float* o0 = att + ((size_t)(b * SEQ + qbase + row0) * NH + h) * HD;
    float* o1 = att + ((size_t)(b * SEQ + qbase + row1) * NH + h) * HD;
    #pragma unroll
    for (int nf = 0; nf < 8; nf++) {
        int c0 = nf * 8 + cq * 2;
        *(float2*)(o0 + c0) = make_float2(tf32_rna(oacc[nf][0] * i0),
                                          tf32_rna(oacc[nf][1] * i0));
        *(float2*)(o1 + c0) = make_float2(tf32_rna(oacc[nf][2] * i1),
                                          tf32_rna(oacc[nf][3] * i1));
    }
}

// ---------------- launch ------------------------------------------------------
static inline void launch_gemm(const float* A, const float* B, float* C, const float* R,
                               int M, int N, int K,
                               const int* cnt, const int* gi, const float* gw,
                               int epi, int gat, int nz,
                               long aS, long bS, long cS) {
    dim3 grid(N / BN, (M + BM - 1) / BM, nz);
    mma_gemm_kernel<<<grid, 256, GEMM_SMEM_B>>>(A, B, C, R, M, N, K, cnt, gi, gw,
                                                epi, gat,
                                                nullptr, nullptr, nullptr, nullptr, 0,
                                                aS, bS, cS);
}

extern "C" void kernel_launch(void* const* d_in, const int* in_sizes, int n_in,
                              void* d_out, int out_size) {
    const float* x    = (const float*)d_in[0];
    const float* g1   = (const float*)d_in[1];
    const float* g2   = (const float*)d_in[2];
    const float* wq   = (const float*)d_in[3];
    const float* wk   = (const float*)d_in[4];
    const float* wv   = (const float*)d_in[5];
    const float* wo   = (const float*)d_in[6];
    const float* gate = (const float*)d_in[7];
    const float* w1   = (const float*)d_in[8];
    const float* w2   = (const float*)d_in[9];
    const float* w3   = (const float*)d_in[10];
    float* out = (float*)d_out;

    float *xn, *q, *k, *v, *att, *h, *wgt;
    int *cnt, *idx;
    cudaGetSymbolAddress((void**)&xn,  g_xn);
    cudaGetSymbolAddress((void**)&q,   g_q);
    cudaGetSymbolAddress((void**)&k,   g_k);
    cudaGetSymbolAddress((void**)&v,   g_v);
    cudaGetSymbolAddress((void**)&att, g_att);
    cudaGetSymbolAddress((void**)&h,   g_h);
    cudaGetSymbolAddress((void**)&cnt, g_cnt);
    cudaGetSymbolAddress((void**)&idx, g_idx);
    cudaGetSymbolAddress((void**)&wgt, g_wgt);

    // unconditional (no static guards allowed); idempotent host-side calls
    cudaFuncSetAttribute(flash_attn_kernel,
                         cudaFuncAttributeMaxDynamicSharedMemorySize,
                         FLASH_SMEM_B);
    cudaFuncSetAttribute(mma_gemm_kernel,
                         cudaFuncAttributeMaxDynamicSharedMemorySize,
                         GEMM_SMEM_B);

    // ---- attention branch ----
    rmsnorm_kernel<<<TOKENS, 256>>>(x, g1, xn, nullptr, 1);   // also zeroes g_cnt

    // fused q/k/v projection: virtual N = 1536 (1024 q | 256 k | 256 v)
    {
        dim3 grid(1536 / BN, TOKENS / BM, 1);
        mma_gemm_kernel<<<grid, 256, GEMM_SMEM_B>>>(xn, wq, q, nullptr, TOKENS, 1536, DIM,
                                                    nullptr, nullptr, nullptr, 0, 0,
                                                    wk, wv, k, v, 1, 0, 0, 0);
    }

    int ropeN = TOKENS * NH * 32 + TOKENS * NKV * 32;
    rope_kernel<<<(ropeN + 255) / 256, 256>>>(q, k);

    {
        dim3 grid(SEQ / 128, NH, 2);
        flash_attn_kernel<<<grid, 256, FLASH_SMEM_B>>>(q, k, v, att);
    }

    // out = x + att @ wo
    launch_gemm(att, wo, out, x, TOKENS, DIM, DIM, nullptr, nullptr, nullptr,
                1, 0, 1, 0, 0, 0);

    // ---- MoE branch (rmsnorm2 has gating fused) ----
    rmsnorm_kernel<<<TOKENS, 256>>>(out, g2, xn, gate, 0);

    // all experts in one launch each (gridDim.z = NE)
    launch_gemm(xn, w1, h, nullptr, TOKENS, HIDDEN, DIM, cnt, idx, nullptr,
                0, 1, NE, 0, (long)DIM * HIDDEN, (long)TOKENS * HIDDEN);
    launch_gemm(xn, w3, h, nullptr, TOKENS, HIDDEN, DIM, cnt, idx, nullptr,
                2, 1, NE, 0, (long)DIM * HIDDEN, (long)TOKENS * HIDDEN);
    launch_gemm(h, w2, out, nullptr, TOKENS, DIM, HIDDEN, cnt, idx, wgt,
                3, 0, NE, (long)TOKENS * HIDDEN, (long)HIDDEN * DIM, 0);
}

// round 10
// speedup vs baseline: 6.8960x; 1.0001x over previous
#include <cuda_runtime.h>
#include <math.h>

#define TOKENS 4096
#define DIM    1024
#define SEQ    2048
#define NH     16
#define NKV    4
#define HD     64
#define HIDDEN 3072
#define NE     4
#define RMS_EPS 1.1920928955078125e-07f

// ---------------- scratch (device globals; no allocation allowed) ----------
__device__ float g_xn [TOKENS * DIM];
__device__ float g_q  [TOKENS * DIM];
__device__ float g_k  [TOKENS * NKV * HD];
__device__ float g_v  [TOKENS * NKV * HD];
__device__ float g_att[TOKENS * DIM];
__device__ float g_h  [NE * TOKENS * HIDDEN];   // per-expert hidden
__device__ int   g_cnt[NE];
__device__ int   g_idx[NE * TOKENS];
__device__ float g_wgt[NE * TOKENS];

__device__ __forceinline__ float tf32_rna(float x) {
    unsigned u;
    asm("cvt.rna.tf32.f32 %0, %1;" : "=r"(u) : "f"(x));
    return __uint_as_float(u);
}

__device__ __forceinline__ unsigned smem_u32(const void* p) {
    return (unsigned)__cvta_generic_to_shared(p);
}
__device__ __forceinline__ void cp16(unsigned dst, const void* src, int sz) {
    asm volatile("cp.async.cg.shared.global [%0], [%1], 16, %2;"
                 :: "r"(dst), "l"(src), "r"(sz));
}
__device__ __forceinline__ void cp_commit() {
    asm volatile("cp.async.commit_group;");
}
template<int N> __device__ __forceinline__ void cp_wait() {
    asm volatile("cp.async.wait_group %0;" :: "n"(N));
}
__device__ __forceinline__ void ldsm_x4(unsigned& r0, unsigned& r1,
                                        unsigned& r2, unsigned& r3, unsigned addr) {
    asm volatile("ldmatrix.sync.aligned.m8n8.x4.shared.b16 {%0,%1,%2,%3}, [%4];"
                 : "=r"(r0), "=r"(r1), "=r"(r2), "=r"(r3) : "r"(addr));
}

// ---------------- RMSNorm (+optional fused MoE gate, +optional cnt zero) ----
__global__ void rmsnorm_kernel(const float* __restrict__ x,
                               const float* __restrict__ g,
                               float* __restrict__ o,
                               const float* __restrict__ gate,
                               int zcnt) {
    int t = blockIdx.x;
    int tid = threadIdx.x;
    if (zcnt && t == 0 && tid < NE) g_cnt[tid] = 0;
    const float* xr = x + (size_t)t * DIM;
    float ss = 0.f;
    for (int i = tid; i < DIM; i += 256) { float v = xr[i]; ss += v * v; }
    #pragma unroll
    for (int o2 = 16; o2; o2 >>= 1) ss += __shfl_xor_sync(0xffffffffu, ss, o2);
    __shared__ float sw[8];
    __shared__ float sg[8][NE];
    if ((tid & 31) == 0) sw[tid >> 5] = ss;
    __syncthreads();
    if (tid < 8) {
        float v = sw[tid];
        #pragma unroll
        for (int o2 = 4; o2; o2 >>= 1) v += __shfl_xor_sync(0xffu, v, o2);
        if (tid == 0) sw[0] = v;
    }
    __syncthreads();
    float r = rsqrtf(sw[0] * (1.0f / DIM) + RMS_EPS);
    float* orow = o + (size_t)t * DIM;
    if (!gate) {
        for (int i = tid; i < DIM; i += 256) orow[i] = tf32_rna(xr[i] * r * g[i]);
        return;
    }
    // fused gating: accumulate logits while storing
    float a0 = 0.f, a1 = 0.f, a2 = 0.f, a3 = 0.f;
    for (int i = tid; i < DIM; i += 256) {
        float val = tf32_rna(xr[i] * r * g[i]);
        orow[i] = val;
        const float* gr = gate + (size_t)i * NE;
        a0 += val * gr[0]; a1 += val * gr[1];
        a2 += val * gr[2]; a3 += val * gr[3];
    }
    #pragma unroll
    for (int o2 = 16; o2; o2 >>= 1) {
        a0 += __shfl_xor_sync(0xffffffffu, a0, o2);
        a1 += __shfl_xor_sync(0xffffffffu, a1, o2);
        a2 += __shfl_xor_sync(0xffffffffu, a2, o2);
        a3 += __shfl_xor_sync(0xffffffffu, a3, o2);
    }
    int lane = tid & 31;
    if (lane == 0) {
        int w = tid >> 5;
        sg[w][0] = a0; sg[w][1] = a1; sg[w][2] = a2; sg[w][3] = a3;
    }
    __syncthreads();
    if (tid == 0) {
        float p[NE];
        #pragma unroll
        for (int e = 0; e < NE; e++) {
            float s = 0.f;
            #pragma unroll
            for (int w = 0; w < 8; w++) s += sg[w][e];
            p[e] = s;
        }
        float mx = p[0];
        #pragma unroll
        for (int e = 1; e < NE; e++) mx = fmaxf(mx, p[e]);
        #pragma unroll
        for (int e = 0; e < NE; e++) p[e] = __expf(p[e] - mx);
        int e0 = 0;
        #pragma unroll
        for (int e = 1; e < NE; e++) if (p[e] > p[e0]) e0 = e;
        int e1 = -1;
        #pragma unroll
        for (int e = 0; e < NE; e++) if (e != e0 && (e1 < 0 || p[e] > p[e1])) e1 = e;
        float w0 = p[e0], w1 = p[e1];
        float ws = w0 + w1;
        w0 /= ws; w1 /= ws;
        int s0 = atomicAdd(&g_cnt[e0], 1);
        g_idx[e0 * TOKENS + s0] = t; g_wgt[e0 * TOKENS + s0] = w0;
        int s1 = atomicAdd(&g_cnt[e1], 1);
        g_idx[e1 * TOKENS + s1] = t; g_wgt[e1 * TOKENS + s1] = w1;
    }
}

// ---------------- tf32 tensor-core GEMM, cp.async, BK=32, dynamic smem ------
#define BM 128
#define BN 128
#define BK 32
#define SA 36
#define SB 136
#define A_STAGE_F (BM * SA)
#define B_STAGE_F (BK * SB)
#define A_STAGE_B (A_STAGE_F * 4)
#define B_STAGE_B (B_STAGE_F * 4)
#define GEMM_SMEM_B ((2 * A_STAGE_F + 2 * B_STAGE_F) * 4)

__device__ __forceinline__ void mma_tf32(float c[4], unsigned a0, unsigned a1,
                                         unsigned a2, unsigned a3,
                                         unsigned b0, unsigned b1) {
    asm volatile(
        "mma.sync.aligned.m16n8k8.row.col.f32.tf32.tf32.f32 "
        "{%0,%1,%2,%3}, {%4,%5,%6,%7}, {%8,%9}, {%0,%1,%2,%3};"
        : "+f"(c[0]), "+f"(c[1]), "+f"(c[2]), "+f"(c[3])
        : "r"(a0), "r"(a1), "r"(a2), "r"(a3), "r"(b0), "r"(b1));
}

// epi: 0 = C=acc ; 1 = C=acc+R ; 2 = C=tf32(silu(C)*acc) ; 3 = atomicAdd(C[idx[r]], acc*wgt[r])
__global__ void __launch_bounds__(256, 2)
mma_gemm_kernel(const float* __restrict__ A, const float* __restrict__ B,
                float* __restrict__ C, const float* __restrict__ R,
                int M, int N, int K,
                const int* __restrict__ cnt,
                const int* __restrict__ gidx, const float* __restrict__ gwgt,
                int epi, int gatherA,
                const float* __restrict__ B2, const float* __restrict__ B3,
                float* __restrict__ C2, float* __restrict__ C3, int qkv,
                long aStride, long bStride, long cStride) {
    int ez = blockIdx.z;
    if (cnt)  cnt  += ez;
    if (gidx) gidx += (size_t)ez * TOKENS;
    if (gwgt) gwgt += (size_t)ez * TOKENS;
    A += (size_t)ez * aStride;
    B += (size_t)ez * bStride;
    C += (size_t)ez * cStride;

    int Meff = cnt ? *cnt : M;
    int rowBase = blockIdx.y * BM;
    if (rowBase >= Meff) return;

    extern __shared__ __align__(16) float gsm[];
    float* As = gsm;                        // [2][BM][SA]
    float* Bs = gsm + 2 * A_STAGE_F;        // [2][BK][SB]

    int tid  = threadIdx.x;
    int lane = tid & 31;
    int wid  = tid >> 5;
    int wm   = wid & 1;
    int wn   = wid >> 1;
    int nBase = blockIdx.x * BN;

    const float* Bq = B; float* Cq = C; int ld = N; int nLoc = nBase;
    if (qkv) {
        if (nBase >= 1280)      { Bq = B3; Cq = C3; ld = 256;  nLoc = nBase - 1280; }
        else if (nBase >= 1024) { Bq = B2; Cq = C2; ld = 256;  nLoc = nBase - 1024; }
        else                    {                   ld = 1024; }
    }

    float acc[4][4][4];
    #pragma unroll
    for (int i = 0; i < 4; i++)
        #pragma unroll
        for (int j = 0; j < 4; j++)
            #pragma unroll
            for (int q = 0; q < 4; q++) acc[i][j][q] = 0.f;

    // copy assignments: 4 float4 slots per thread for A and for B
    const float* aSrc[4]; int aSz[4]; unsigned aDst[4];
    const float* bSrc[4]; unsigned bDst[4];
    #pragma unroll
    for (int s = 0; s < 4; s++) {
        int fid = tid + s * 256;            // 0..1023
        int arow = fid >> 3;                // 128 rows, 8 float4 each
        int acol = (fid & 7) << 2;
        int row = rowBase + arow;
        bool ok = row < Meff;
        long src = 0;
        if (ok) src = gatherA ? (long)gidx[row] : (long)row;
        aSrc[s] = A + src * (size_t)K + acol;
        aSz[s]  = ok ? 16 : 0;
        aDst[s] = smem_u32(As + arow * SA + acol);
        int brow = fid >> 5;                // 32 rows, 32 float4 each
        int bcol = (fid & 31) << 2;
        bSrc[s] = Bq + (size_t)brow * ld + nLoc + bcol;
        bDst[s] = smem_u32(Bs + brow * SB + bcol);
    }

    int nIter = K / BK;
    #pragma unroll
    for (int s = 0; s < 4; s++) {
        cp16(aDst[s], aSrc[s], aSz[s]);
        cp16(bDst[s], bSrc[s], 16);
    }
    cp_commit();
    if (nIter > 1) {
        #pragma unroll
        for (int s = 0; s < 4; s++) {
            cp16(aDst[s] + A_STAGE_B, aSrc[s] + BK, aSz[s]);
            cp16(bDst[s] + B_STAGE_B, bSrc[s] + (size_t)BK * ld, 16);
        }
        cp_commit();
    }

    int r = lane >> 2, c = lane & 3;
    // ldmatrix per-lane A address
    int rowA = (lane & 7) + ((lane >> 3) & 1) * 8;
    int colA = (lane >> 4) * 4;
    unsigned aLane = smem_u32(As + (wm * 64 + rowA) * SA + colA);

    for (int it = 0; it < nIter; it++) {
        int cur = it & 1;
        if (it + 1 < nIter) cp_wait<1>(); else cp_wait<0>();
        __syncthreads();

        #pragma unroll
        for (int ks = 0; ks < BK; ks += 8) {
            unsigned bf[4][2];
            #pragma unroll
            for (int j = 0; j < 4; j++) {
                int nC = wn * 32 + j * 8 + r;
                bf[j][0] = __float_as_uint(Bs[cur * B_STAGE_F + (ks + c) * SB + nC]);
                bf[j][1] = __float_as_uint(Bs[cur * B_STAGE_F + (ks + c + 4) * SB + nC]);
            }
            #pragma unroll
            for (int i = 0; i < 4; i++) {
                unsigned a0, a1, a2, a3;
                ldsm_x4(a0, a1, a2, a3,
                        aLane + cur * A_STAGE_B + (unsigned)((i * 16 * SA + ks) * 4));
                #pragma unroll
                for (int j = 0; j < 4; j++)
                    mma_tf32(acc[i][j], a0, a1, a2, a3, bf[j][0], bf[j][1]);
            }
        }
        __syncthreads();
        if (it + 2 < nIter) {
            int kt = (it + 2) * BK;
            #pragma unroll
            for (int s = 0; s < 4; s++) {
                cp16(aDst[s] + cur * A_STAGE_B, aSrc[s] + kt, aSz[s]);
                cp16(bDst[s] + cur * B_STAGE_B, bSrc[s] + (size_t)kt * ld, 16);
            }
            cp_commit();
        }
    }

    // epilogue
    #pragma unroll
    for (int i = 0; i < 4; i++) {
        int rbase = rowBase + wm * 64 + i * 16 + r;
        #pragma unroll
        for (int half = 0; half < 2; half++) {
            int rr = rbase + half * 8;
            if (rr >= Meff) continue;
            int tok = 0; float w = 0.f;
            if (epi == 3) { tok = gidx[rr]; w = gwgt[rr]; }
            #pragma unroll
            for (int j = 0; j < 4; j++) {
                int col = nLoc + wn * 32 + j * 8 + (c << 1);
                float v0 = acc[i][j][half * 2];
                float v1 = acc[i][j][half * 2 + 1];
                if (epi == 0) {
                    *(float2*)(Cq + (size_t)rr * ld + col) = make_float2(v0, v1);
                } else if (epi == 1) {
                    float2 rv = *(const float2*)(R + (size_t)rr * ld + col);
                    *(float2*)(Cq + (size_t)rr * ld + col) =
                        make_float2(v0 + rv.x, v1 + rv.y);
                } else if (epi == 2) {
                    float2 hv = *(float2*)(Cq + (size_t)rr * ld + col);
                    float s0 = hv.x / (1.f + __expf(-hv.x));
                    float s1 = hv.y / (1.f + __expf(-hv.y));
                    *(float2*)(Cq + (size_t)rr * ld + col) =
                        make_float2(tf32_rna(s0 * v0), tf32_rna(s1 * v1));
                } else {
                    float* cp = Cq + (size_t)tok * ld + col;
                    atomicAdd(cp,     v0 * w);
                    atomicAdd(cp + 1, v1 * w);
                }
            }
        }
    }
}

// ---------------- RoPE on q and k (in place) --------------------------------
__global__ void rope_kernel(float* __restrict__ q, float* __restrict__ k) {
    int id = blockIdx.x * blockDim.x + threadIdx.x;
    const int NQ = TOKENS * NH * 32;
    const int NK2 = TOKENS * NKV * 32;
    if (id >= NQ + NK2) return;
    float* base; int t, i;
    if (id < NQ) {
        t = id >> 9; int r = id & 511; int h = r >> 5; i = r & 31;
        base = q + ((size_t)t * NH + h) * HD;
    } else {
        int id2 = id - NQ;
        t = id2 >> 7; int r = id2 & 127; int h = r >> 5; i = r & 31;
        base = k + ((size_t)t * NKV + h) * HD;
    }
    int pos = t & (SEQ - 1);
    float inv = exp2f(-(float)i * 0.4152410118609203f);
    float fr = (float)pos * inv;
    float sn, cs;
    sincosf(fr, &sn, &cs);
    float x1 = base[i], x2 = base[i + 32];
    base[i]      = x1 * cs - x2 * sn;
    base[i + 32] = x2 * cs + x1 * sn;
}

// ---------------- flash attention: 128 q-rows x 64-key tiles, 8 warps -------
#define KST 68
#define VST 72
#define KTILE_F (64 * KST)
#define VTILE_F (64 * VST)
#define KTILE_B (KTILE_F * 4)
#define VTILE_B (VTILE_F * 4)
#define OFF_V_F (2 * KTILE_F)
#define OFF_P_F (2 * KTILE_F + 2 * VTILE_F)
#define FLASH_SMEM_B ((OFF_P_F + 128 * KST) * 4)

__global__ void __launch_bounds__(256, 1)
flash_attn_kernel(const float* __restrict__ q,
                  const float* __restrict__ k,
                  const float* __restrict__ v,
                  float* __restrict__ att) {
    extern __shared__ float fs[];
    float* Pb = fs + OFF_P_F;

    int qi = (SEQ / 128 - 1) - blockIdx.x;   // long tiles launch first
    int h  = blockIdx.y;
    int b  = blockIdx.z;
    int hk = h >> 2;
    int qbase = qi * 128;

    int tid  = threadIdx.x;
    int lane = tid & 31;
    int w    = tid >> 5;
    int lr   = lane >> 2;
    int cq   = lane & 3;
    int row0 = w * 16 + lr;
    int row1 = row0 + 8;

    unsigned fsBase = smem_u32(fs);
    int rowA = (lane & 7) + ((lane >> 3) & 1) * 8;
    int colA = (lane >> 4) * 4;
    unsigned pLane = fsBase + (unsigned)((OFF_P_F + (w * 16 + rowA) * KST + colA) * 4);
    int rowK = (lane & 7) + ((lane >> 4) & 1) * 8;
    int colK = ((lane >> 3) & 1) * 4;
    unsigned kLane = fsBase + (unsigned)((rowK * KST + colK) * 4);

    const size_t kvstride = (size_t)NKV * HD;
    const float* kb = k + ((size_t)(b * SEQ) * NKV + hk) * HD;
    const float* vb = v + ((size_t)(b * SEQ) * NKV + hk) * HD;

    unsigned kDst[4], vDst[4]; const float* kSrc[4]; const float* vSrc[4];
    #pragma unroll
    for (int it = 0; it < 4; it++) {
        int idx = tid + it * 256;
        int rrow = idx >> 4;
        int ccol = (idx & 15) << 2;
        kDst[it] = fsBase + (unsigned)((rrow * KST + ccol) * 4);
        vDst[it] = fsBase + (unsigned)((OFF_V_F + rrow * VST + ccol) * 4);
        kSrc[it] = kb + (size_t)rrow * kvstride + ccol;
        vSrc[it] = vb + (size_t)rrow * kvstride + ccol;
    }

    unsigned qa[8][4];
    {
        const float* q0 = q + ((size_t)(b * SEQ + qbase + row0) * NH + h) * HD;
        const float* q1 = q + ((size_t)(b * SEQ + qbase + row1) * NH + h) * HD;
        #pragma unroll
        for (int ks8 = 0; ks8 < 8; ks8++) {
            int kk = ks8 * 8;
            qa[ks8][0] = __float_as_uint(q0[kk + cq] * 0.125f);
            qa[ks8][1] = __float_as_uint(q1[kk + cq] * 0.125f);
            qa[ks8][2] = __float_as_uint(q0[kk + cq + 4] * 0.125f);
            qa[ks8][3] = __float_as_uint(q1[kk + cq + 4] * 0.125f);
        }
    }

    float oacc[8][4];
    #pragma unroll
    for (int nf = 0; nf < 8; nf++)
        #pragma unroll
        for (int t2 = 0; t2 < 4; t2++) oacc[nf][t2] = 0.f;
    float m0 = -3.0e38f, m1 = -3.0e38f, l0 = 0.f, l1 = 0.f;

    int nkt = 2 * qi + 2;

    #pragma unroll
    for (int it = 0; it < 4; it++) {
        cp16(kDst[it], kSrc[it], 16);
        cp16(vDst[it], vSrc[it], 16);
    }
    cp_commit();

    for (int kt = 0; kt < nkt; kt++) {
        int cur = kt & 1;
        __syncthreads();
        if (kt + 1 < nkt) {
            size_t off = (size_t)(kt + 1) * 64 * kvstride;
            int nb = cur ^ 1;
            #pragma unroll
            for (int it = 0; it < 4; it++) {
                cp16(kDst[it] + nb * KTILE_B, kSrc[it] + off, 16);
                cp16(vDst[it] + nb * VTILE_B, vSrc[it] + off, 16);
            }
            cp_commit();
            cp_wait<1>();
        } else {
            cp_wait<0>();
        }
        __syncthreads();

        const float* Vsf = fs + OFF_V_F + cur * VTILE_F;

        float s[8][4];
        #pragma unroll
        for (int nf = 0; nf < 8; nf++)
            #pragma unroll
            for (int t2 = 0; t2 < 4; t2++) s[nf][t2] = 0.f;
        #pragma unroll
        for (int ks8 = 0; ks8 < 8; ks8++) {
            int kk = ks8 * 8;
            #pragma unroll
            for (int nfp = 0; nfp < 4; nfp++) {
                unsigned kb0, kb1, kb2, kb3;
                ldsm_x4(kb0, kb1, kb2, kb3,
                        kLane + cur * KTILE_B + (unsigned)((nfp * 16 * KST + kk) * 4));
                mma_tf32(s[2 * nfp],     qa[ks8][0], qa[ks8][1], qa[ks8][2], qa[ks8][3], kb0, kb1);
                mma_tf32(s[2 * nfp + 1], qa[ks8][0], qa[ks8][1], qa[ks8][2], qa[ks8][3], kb2, kb3);
            }
        }

        if (kt + 2 >= nkt) {
            int dk = kt * 64 - qbase;
            #pragma unroll
            for (int nf = 0; nf < 8; nf++) {
                int c0 = nf * 8 + cq * 2 + dk;
                if (c0     > row0) s[nf][0] = -3.0e38f;
                if (c0 + 1 > row0) s[nf][1] = -3.0e38f;
                if (c0     > row1) s[nf][2] = -3.0e38f;
                if (c0 + 1 > row1) s[nf][3] = -3.0e38f;
            }
        }

        float rm0 = -3.0e38f, rm1 = -3.0e38f;
        #pragma unroll
        for (int nf = 0; nf < 8; nf++) {
            rm0 = fmaxf(rm0, fmaxf(s[nf][0], s[nf][1]));
            rm1 = fmaxf(rm1, fmaxf(s[nf][2], s[nf][3]));
        }
        rm0 = fmaxf(rm0, __shfl_xor_sync(0xffffffffu, rm0, 1));
        rm0 = fmaxf(rm0, __shfl_xor_sync(0xffffffffu, rm0, 2));
        rm1 = fmaxf(rm1, __shfl_xor_sync(0xffffffffu, rm1, 1));
        rm1 = fmaxf(rm1, __shfl_xor_sync(0xffffffffu, rm1, 2));
        float mn0 = fmaxf(m0, rm0), mn1 = fmaxf(m1, rm1);
        float sc0 = __expf(m0 - mn0), sc1 = __expf(m1 - mn1);
        m0 = mn0; m1 = mn1;
        l0 *= sc0; l1 *= sc1;
        #pragma unroll
        for (int nf = 0; nf < 8; nf++) {
            float p0 = __expf(s[nf][0] - mn0);
            float p1 = __expf(s[nf][1] - mn0);
            float p2 = __expf(s[nf][2] - mn1);
            float p3 = __expf(s[nf][3] - mn1);
            l0 += p0 + p1; l1 += p2 + p3;
            int c0 = nf * 8 + cq * 2;
            *(float2*)&Pb[row0 * KST + c0] = make_float2(p0, p1);
            *(float2*)&Pb[row1 * KST + c0] = make_float2(p2, p3);
            oacc[nf][0] *= sc0; oacc[nf][1] *= sc0;
            oacc[nf][2] *= sc1; oacc[nf][3] *= sc1;
        }
        __syncwarp();

        #pragma unroll
        for (int ks8 = 0; ks8 < 8; ks8++) {
            int kk = ks8 * 8;
            unsigned a0, a1, a2, a3;
            ldsm_x4(a0, a1, a2, a3, pLane + (unsigned)(kk * 4));
            #pragma unroll
            for (int nf = 0; nf < 8; nf++) {
                unsigned b0 = __float_as_uint(Vsf[(kk + cq) * VST + nf * 8 + lr]);
                unsigned b1 = __float_as_uint(Vsf[(kk + cq + 4) * VST + nf * 8 + lr]);
                mma_tf32(oacc[nf], a0, a1, a2, a3, b0, b1);
            }
        }
    }

    l0 += __shfl_xor_sync(0xffffffffu, l0, 1);
    l0 += __shfl_xor_sync(0xffffffffu, l0, 2);
    l1 += __shfl_xor_sync(0xffffffffu, l1, 1);
    l1 += __shfl_xor_sync(0xffffffffu, l1, 2);
    float i0 = 1.f / l0, i1 = 1.f / l1;
    float* o0 = att + ((size_t)(b * SEQ + qbase + row0) * NH + h) * HD;
    float* o1 = att + ((size_t)(b * SEQ + qbase + row1) * NH + h) * HD;
    #pragma unroll
    for (int nf = 0; nf < 8; nf++) {
        int c0 = nf * 8 + cq * 2;
        *(float2*)(o0 + c0) = make_float2(tf32_rna(oacc[nf][0] * i0),
                                          tf32_rna(oacc[nf][1] * i0));
        *(float2*)(o1 + c0) = make_float2(tf32_rna(oacc[nf][2] * i1),
                                          tf32_rna(oacc[nf][3] * i1));
    }
}

// ---------------- launch ------------------------------------------------------
static inline void launch_gemm(const float* A, const float* B, float* C, const float* R,
                               int M, int N, int K,
                               const int* cnt, const int* gi, const float* gw,
                               int epi, int gat, int nz,
                               long aS, long bS, long cS) {
    dim3 grid(N / BN, (M + BM - 1) / BM, nz);
    mma_gemm_kernel<<<grid, 256, GEMM_SMEM_B>>>(A, B, C, R, M, N, K, cnt, gi, gw,
                                                epi, gat,
                                                nullptr, nullptr, nullptr, nullptr, 0,
                                                aS, bS, cS);
}

extern "C" void kernel_launch(void* const* d_in, const int* in_sizes, int n_in,
                              void* d_out, int out_size) {
    const float* x    = (const float*)d_in[0];
    const float* g1   = (const float*)d_in[1];
    const float* g2   = (const float*)d_in[2];
    const float* wq   = (const float*)d_in[3];
    const float* wk   = (const float*)d_in[4];
    const float* wv   = (const float*)d_in[5];
    const float* wo   = (const float*)d_in[6];
    const float* gate = (const float*)d_in[7];
    const float* w1   = (const float*)d_in[8];
    const float* w2   = (const float*)d_in[9];
    const float* w3   = (const float*)d_in[10];
    float* out = (float*)d_out;

    float *xn, *q, *k, *v, *att, *h, *wgt;
    int *cnt, *idx;
    cudaGetSymbolAddress((void**)&xn,  g_xn);
    cudaGetSymbolAddress((void**)&q,   g_q);
    cudaGetSymbolAddress((void**)&k,   g_k);
    cudaGetSymbolAddress((void**)&v,   g_v);
    cudaGetSymbolAddress((void**)&att, g_att);
    cudaGetSymbolAddress((void**)&h,   g_h);
    cudaGetSymbolAddress((void**)&cnt, g_cnt);
    cudaGetSymbolAddress((void**)&idx, g_idx);
    cudaGetSymbolAddress((void**)&wgt, g_wgt);

    // unconditional (no static guards allowed); idempotent host-side calls
    cudaFuncSetAttribute(flash_attn_kernel,
                         cudaFuncAttributeMaxDynamicSharedMemorySize,
                         FLASH_SMEM_B);
    cudaFuncSetAttribute(mma_gemm_kernel,
                         cudaFuncAttributeMaxDynamicSharedMemorySize,
                         GEMM_SMEM_B);

    // ---- attention branch ----
    rmsnorm_kernel<<<TOKENS, 256>>>(x, g1, xn, nullptr, 1);   // also zeroes g_cnt

    // fused q/k/v projection: virtual N = 1536 (1024 q | 256 k | 256 v)
    {
        dim3 grid(1536 / BN, TOKENS / BM, 1);
        mma_gemm_kernel<<<grid, 256, GEMM_SMEM_B>>>(xn, wq, q, nullptr, TOKENS, 1536, DIM,
                                                    nullptr, nullptr, nullptr, 0, 0,
                                                    wk, wv, k, v, 1, 0, 0, 0);
    }

    int ropeN = TOKENS * NH * 32 + TOKENS * NKV * 32;
    rope_kernel<<<(ropeN + 255) / 256, 256>>>(q, k);

    {
        dim3 grid(SEQ / 128, NH, 2);
        flash_attn_kernel<<<grid, 256, FLASH_SMEM_B>>>(q, k, v, att);
    }

    // out = x + att @ wo
    launch_gemm(att, wo, out, x, TOKENS, DIM, DIM, nullptr, nullptr, nullptr,
                1, 0, 1, 0, 0, 0);

    // ---- MoE branch (rmsnorm2 has gating fused) ----
    rmsnorm_kernel<<<TOKENS, 256>>>(out, g2, xn, gate, 0);

    // all experts in one launch each (gridDim.z = NE)
    launch_gemm(xn, w1, h, nullptr, TOKENS, HIDDEN, DIM, cnt, idx, nullptr,
                0, 1, NE, 0, (long)DIM * HIDDEN, (long)TOKENS * HIDDEN);
    launch_gemm(xn, w3, h, nullptr, TOKENS, HIDDEN, DIM, cnt, idx, nullptr,
                2, 1, NE, 0, (long)DIM * HIDDEN, (long)TOKENS * HIDDEN);
    launch_gemm(h, w2, out, nullptr, TOKENS, DIM, HIDDEN, cnt, idx, wgt,
                3, 0, NE, (long)TOKENS * HIDDEN, (long)HIDDEN * DIM, 0);
}

// round 12
// speedup vs baseline: 8.5563x; 1.2408x over previous
#include <cuda_runtime.h>
#include <cuda_fp16.h>
#include <math.h>

#define TOKENS 4096
#define DIM    1024
#define SEQ    2048
#define NH     16
#define NKV    4
#define HD     64
#define HIDDEN 3072
#define NE     4
#define RMS_EPS 1.1920928955078125e-07f

// ---------------- scratch ----------------------------------------------------
__device__ __half g_xn16 [TOKENS * DIM];
__device__ __half g_att16[TOKENS * DIM];
__device__ __half g_h16  [NE * TOKENS * HIDDEN];
__device__ float  g_q  [TOKENS * DIM];
__device__ float  g_k  [TOKENS * NKV * HD];
__device__ float  g_v  [TOKENS * NKV * HD];
__device__ int    g_cnt[NE];
__device__ int    g_idx[NE * TOKENS];
__device__ float  g_wgt[NE * TOKENS];
// fp16 weights
__device__ __half g_wq16[DIM * DIM];
__device__ __half g_wk16[DIM * NKV * HD];
__device__ __half g_wv16[DIM * NKV * HD];
__device__ __half g_wo16[DIM * DIM];
__device__ __half g_w1h [NE * DIM * HIDDEN];
__device__ __half g_w2h [NE * HIDDEN * DIM];
__device__ __half g_w3h [NE * DIM * HIDDEN];

__device__ __forceinline__ float tf32_rna(float x) {
    unsigned u;
    asm("cvt.rna.tf32.f32 %0, %1;" : "=r"(u) : "f"(x));
    return __uint_as_float(u);
}
__device__ __forceinline__ unsigned smem_u32(const void* p) {
    return (unsigned)__cvta_generic_to_shared(p);
}
__device__ __forceinline__ void cp16(unsigned dst, const void* src, int sz) {
    asm volatile("cp.async.cg.shared.global [%0], [%1], 16, %2;"
                 :: "r"(dst), "l"(src), "r"(sz));
}
__device__ __forceinline__ void cp_commit() {
    asm volatile("cp.async.commit_group;");
}
template<int N> __device__ __forceinline__ void cp_wait() {
    asm volatile("cp.async.wait_group %0;" :: "n"(N));
}
__device__ __forceinline__ void ldsm_x4(unsigned& r0, unsigned& r1,
                                        unsigned& r2, unsigned& r3, unsigned a) {
    asm volatile("ldmatrix.sync.aligned.m8n8.x4.shared.b16 {%0,%1,%2,%3}, [%4];"
                 : "=r"(r0), "=r"(r1), "=r"(r2), "=r"(r3) : "r"(a));
}
__device__ __forceinline__ void ldsm_x4t(unsigned& r0, unsigned& r1,
                                         unsigned& r2, unsigned& r3, unsigned a) {
    asm volatile("ldmatrix.sync.aligned.m8n8.x4.trans.shared.b16 {%0,%1,%2,%3}, [%4];"
                 : "=r"(r0), "=r"(r1), "=r"(r2), "=r"(r3) : "r"(a));
}
__device__ __forceinline__ void mma_f16(float c[4], unsigned a0, unsigned a1,
                                        unsigned a2, unsigned a3,
                                        unsigned b0, unsigned b1) {
    asm volatile("mma.sync.aligned.m16n8k16.row.col.f32.f16.f16.f32 "
        "{%0,%1,%2,%3}, {%4,%5,%6,%7}, {%8,%9}, {%0,%1,%2,%3};"
        : "+f"(c[0]), "+f"(c[1]), "+f"(c[2]), "+f"(c[3])
        : "r"(a0), "r"(a1), "r"(a2), "r"(a3), "r"(b0), "r"(b1));
}
__device__ __forceinline__ void mma_tf32(float c[4], unsigned a0, unsigned a1,
                                         unsigned a2, unsigned a3,
                                         unsigned b0, unsigned b1) {
    asm volatile("mma.sync.aligned.m16n8k8.row.col.f32.tf32.tf32.f32 "
        "{%0,%1,%2,%3}, {%4,%5,%6,%7}, {%8,%9}, {%0,%1,%2,%3};"
        : "+f"(c[0]), "+f"(c[1]), "+f"(c[2]), "+f"(c[3])
        : "r"(a0), "r"(a1), "r"(a2), "r"(a3), "r"(b0), "r"(b1));
}

// ---------------- fp32 -> fp16 weight conversion -----------------------------
__global__ void f2h_kernel(const float* __restrict__ s, __half* __restrict__ d, int n4) {
    int i = blockIdx.x * blockDim.x + threadIdx.x;
    if (i >= n4) return;
    float4 v = ((const float4*)s)[i];
    __half2* dp = (__half2*)(d + i * 4);
    dp[0] = __floats2half2_rn(v.x, v.y);
    dp[1] = __floats2half2_rn(v.z, v.w);
}

// ---------------- RMSNorm -> fp16 (+optional fused MoE gate) -----------------
__global__ void rmsnorm_kernel(const float* __restrict__ x, const float* __restrict__ g,
                               __half* __restrict__ o, const float* __restrict__ gate,
                               int zcnt) {
    int t = blockIdx.x, tid = threadIdx.x;
    if (zcnt && t == 0 && tid < NE) g_cnt[tid] = 0;
    const float* xr = x + (size_t)t * DIM;
    float ss = 0.f;
    for (int i = tid; i < DIM; i += 256) { float v = xr[i]; ss += v * v; }
    #pragma unroll
    for (int o2 = 16; o2; o2 >>= 1) ss += __shfl_xor_sync(0xffffffffu, ss, o2);
    __shared__ float sw[8];
    __shared__ float sg[8][NE];
    if ((tid & 31) == 0) sw[tid >> 5] = ss;
    __syncthreads();
    if (tid < 8) {
        float v = sw[tid];
        #pragma unroll
        for (int o2 = 4; o2; o2 >>= 1) v += __shfl_xor_sync(0xffu, v, o2);
        if (tid == 0) sw[0] = v;
    }
    __syncthreads();
    float r = rsqrtf(sw[0] * (1.0f / DIM) + RMS_EPS);
    __half* orow = o + (size_t)t * DIM;
    if (!gate) {
        for (int i = tid; i < DIM; i += 256)
            orow[i] = __float2half_rn(xr[i] * r * g[i]);
        return;
    }
    float a0 = 0.f, a1 = 0.f, a2 = 0.f, a3 = 0.f;
    for (int i = tid; i < DIM; i += 256) {
        float val = xr[i] * r * g[i];
        orow[i] = __float2half_rn(val);
        const float* gr = gate + (size_t)i * NE;
        a0 += val * gr[0]; a1 += val * gr[1]; a2 += val * gr[2]; a3 += val * gr[3];
    }
    #pragma unroll
    for (int o2 = 16; o2; o2 >>= 1) {
        a0 += __shfl_xor_sync(0xffffffffu, a0, o2);
        a1 += __shfl_xor_sync(0xffffffffu, a1, o2);
        a2 += __shfl_xor_sync(0xffffffffu, a2, o2);
        a3 += __shfl_xor_sync(0xffffffffu, a3, o2);
    }
    if ((tid & 31) == 0) {
        int w = tid >> 5;
        sg[w][0] = a0; sg[w][1] = a1; sg[w][2] = a2; sg[w][3] = a3;
    }
    __syncthreads();
    if (tid == 0) {
        float p[NE];
        #pragma unroll
        for (int e = 0; e < NE; e++) {
            float s = 0.f;
            #pragma unroll
            for (int w = 0; w < 8; w++) s += sg[w][e];
            p[e] = s;
        }
        float mx = fmaxf(fmaxf(p[0], p[1]), fmaxf(p[2], p[3]));
        #pragma unroll
        for (int e = 0; e < NE; e++) p[e] = __expf(p[e] - mx);
        int e0 = 0;
        #pragma unroll
        for (int e = 1; e < NE; e++) if (p[e] > p[e0]) e0 = e;
        int e1 = -1;
        #pragma unroll
        for (int e = 0; e < NE; e++) if (e != e0 && (e1 < 0 || p[e] > p[e1])) e1 = e;
        float w0 = p[e0], w1 = p[e1], ws = p[e0] + p[e1];
        w0 /= ws; w1 /= ws;
        int s0 = atomicAdd(&g_cnt[e0], 1);
        g_idx[e0 * TOKENS + s0] = t; g_wgt[e0 * TOKENS + s0] = w0;
        int s1 = atomicAdd(&g_cnt[e1], 1);
        g_idx[e1 * TOKENS + s1] = t; g_wgt[e1 * TOKENS + s1] = w1;
    }
}

// ---------------- fp16 GEMM: 128x128x32, 3-stage, 1 sync/iter ----------------
#define TM 128
#define TN 128
#define SAB 80                 /* A row stride bytes (32 halves + pad) */
#define SBB 272                /* B row stride bytes (128 halves + pad) */
#define A_STG (128 * SAB)      /* 10240 */
#define B_STG (32 * SBB)       /* 8704  */
#define STG   (A_STG + B_STG)  /* 18944 */
#define GEMM_SMEM_B (3 * STG)

// epi: 0=Cf=acc ; 1=Cf=acc+R ; 2=Ch=h(silu(Ch)*acc) ; 3=atomicAdd(Cf[idx],acc*w) ; 4=Ch=h(acc)
__global__ void __launch_bounds__(256, 2)
gemm16_kernel(const __half* __restrict__ A, const __half* __restrict__ B,
              float* __restrict__ Cf, __half* __restrict__ Ch,
              const float* __restrict__ R,
              int M, int N, int K,
              const int* __restrict__ cnt,
              const int* __restrict__ gidx, const float* __restrict__ gwgt,
              int epi, int gatherA,
              const __half* __restrict__ B2, const __half* __restrict__ B3,
              float* __restrict__ C2, float* __restrict__ C3, int qkv,
              long aStride, long bStride, long cStride) {
    int ez = blockIdx.z;
    if (cnt)  cnt  += ez;
    if (gidx) gidx += (size_t)ez * TOKENS;
    if (gwgt) gwgt += (size_t)ez * TOKENS;
    A += (size_t)ez * aStride;
    B += (size_t)ez * bStride;
    if (Cf) Cf += (size_t)ez * cStride;
    if (Ch) Ch += (size_t)ez * cStride;

    int Meff = cnt ? *cnt : M;
    int rowBase = blockIdx.y * TM;
    if (rowBase >= Meff) return;

    extern __shared__ __align__(16) char gsm[];
    unsigned sm0 = smem_u32(gsm);

    int tid  = threadIdx.x;
    int lane = tid & 31;
    int wid  = tid >> 5;
    int wm   = wid & 1;
    int wn   = wid >> 1;
    int nBase = blockIdx.x * TN;

    const __half* Bq = B; float* Cq = Cf; int ld = N; int nLoc = nBase;
    if (qkv) {
        if (nBase >= 1280)      { Bq = B3; Cq = C3; ld = 256;  nLoc = nBase - 1280; }
        else if (nBase >= 1024) { Bq = B2; Cq = C2; ld = 256;  nLoc = nBase - 1024; }
        else                    {                   ld = 1024; }
    }

    float acc[4][4][4];
    #pragma unroll
    for (int i = 0; i < 4; i++)
        #pragma unroll
        for (int j = 0; j < 4; j++)
            #pragma unroll
            for (int q = 0; q < 4; q++) acc[i][j][q] = 0.f;

    // cp.async: 2 slots each for A (128r x 4 chunks) and B (32r x 16 chunks)
    const __half* aP[2]; unsigned aO[2]; int aSz[2];
    const __half* bP[2]; unsigned bO[2];
    #pragma unroll
    for (int s = 0; s < 2; s++) {
        int f = tid + s * 256;
        int ar = f >> 2, ac = f & 3;
        int row = rowBase + ar;
        bool ok = row < Meff;
        long src = 0;
        if (ok) src = gatherA ? (long)gidx[row] : (long)row;
        aP[s] = A + src * (size_t)K + ac * 8;
        aSz[s] = ok ? 16 : 0;
        aO[s] = (unsigned)(ar * SAB + ac * 16);
        int br = f >> 4, bc = f & 15;
        bP[s] = Bq + (size_t)br * ld + nLoc + bc * 8;
        bO[s] = (unsigned)(A_STG + br * SBB + bc * 16);
    }

    int nIter = K / 32;
    #pragma unroll
    for (int p = 0; p < 2; p++) {
        unsigned sb = sm0 + p * STG;
        int kt = p * 32;
        #pragma unroll
        for (int s = 0; s < 2; s++) {
            cp16(sb + aO[s], aP[s] + kt, aSz[s]);
            cp16(sb + bO[s], bP[s] + (size_t)kt * ld, 16);
        }
        cp_commit();
    }

    // ldmatrix lane addresses
    int rA = (lane & 7) + ((lane >> 3) & 1) * 8;   // m within 16
    int gA = lane >> 4;                             // k granule
    unsigned aLane = (unsigned)((wm * 64 + rA) * SAB + gA * 16);
    int rB = (lane & 7) + ((lane >> 3) & 1) * 8;   // k within 16
    int gB = lane >> 4;                             // n8 group
    unsigned bLane = (unsigned)(A_STG + rB * SBB + (wn * 32 + gB * 8) * 2);

    int st = 0;
    for (int it = 0; it < nIter; it++) {
        if (it + 1 < nIter) cp_wait<1>(); else cp_wait<0>();
        __syncthreads();
        unsigned sb = sm0 + st * STG;

        #pragma unroll
        for (int k16 = 0; k16 < 2; k16++) {
            unsigned bf[4][2];
            #pragma unroll
            for (int jp = 0; jp < 2; jp++) {
                unsigned b0, b1, b2, b3;
                ldsm_x4t(b0, b1, b2, b3,
                         sb + bLane + (unsigned)(k16 * 16 * SBB + jp * 32));
                bf[jp * 2][0] = b0; bf[jp * 2][1] = b1;
                bf[jp * 2 + 1][0] = b2; bf[jp * 2 + 1][1] = b3;
            }
            #pragma unroll
            for (int i = 0; i < 4; i++) {
                unsigned a0, a1, a2, a3;
                ldsm_x4(a0, a1, a2, a3,
                        sb + aLane + (unsigned)(i * 16 * SAB + k16 * 32));
                #pragma unroll
                for (int j = 0; j < 4; j++)
                    mma_f16(acc[i][j], a0, a1, a2, a3, bf[j][0], bf[j][1]);
            }
        }

        if (it + 2 < nIter) {
            unsigned sn = sm0 + ((st + 2 >= 3) ? st - 1 : st + 2) * STG;
            int kt = (it + 2) * 32;
            #pragma unroll
            for (int s = 0; s < 2; s++) {
                cp16(sn + aO[s], aP[s] + kt, aSz[s]);
                cp16(sn + bO[s], bP[s] + (size_t)kt * ld, 16);
            }
            cp_commit();
        }
        st = (st + 1 == 3) ? 0 : st + 1;
    }

    // epilogue (D layout of m16n8: row lane>>2, col pair (lane&3)*2)
    int r = lane >> 2, c = lane & 3;
    #pragma unroll
    for (int i = 0; i < 4; i++) {
        int rbase = rowBase + wm * 64 + i * 16 + r;
        #pragma unroll
        for (int half = 0; half < 2; half++) {
            int rr = rbase + half * 8;
            if (rr >= Meff) continue;
            int tok = 0; float w = 0.f;
            if (epi == 3) { tok = gidx[rr]; w = gwgt[rr]; }
            #pragma unroll
            for (int j = 0; j < 4; j++) {
                int col = nLoc + wn * 32 + j * 8 + (c << 1);
                float v0 = acc[i][j][half * 2];
                float v1 = acc[i][j][half * 2 + 1];
                if (epi == 0) {
                    *(float2*)(Cq + (size_t)rr * ld + col) = make_float2(v0, v1);
                } else if (epi == 1) {
                    float2 rv = *(const float2*)(R + (size_t)rr * ld + col);
                    *(float2*)(Cq + (size_t)rr * ld + col) =
                        make_float2(v0 + rv.x, v1 + rv.y);
                } else if (epi == 2) {
                    __half2* hp = (__half2*)(Ch + (size_t)rr * ld + col);
                    float2 hv = __half22float2(*hp);
                    float s0 = hv.x / (1.f + __expf(-hv.x));
                    float s1 = hv.y / (1.f + __expf(-hv.y));
                    *hp = __floats2half2_rn(s0 * v0, s1 * v1);
                } else if (epi == 3) {
                    float* cp = Cq + (size_t)tok * ld + col;
                    atomicAdd(cp,     v0 * w);
                    atomicAdd(cp + 1, v1 * w);
                } else { // 4: half store
                    *(__half2*)(Ch + (size_t)rr * ld + col) = __floats2half2_rn(v0, v1);
                }
            }
        }
    }
}

// ---------------- RoPE (fp32 q,k) --------------------------------------------
__global__ void rope_kernel(float* __restrict__ q, float* __restrict__ k) {
    int id = blockIdx.x * blockDim.x + threadIdx.x;
    const int NQ = TOKENS * NH * 32;
    const int NK2 = TOKENS * NKV * 32;
    if (id >= NQ + NK2) return;
    float* base; int t, i;
    if (id < NQ) {
        t = id >> 9; int r = id & 511; int h = r >> 5; i = r & 31;
        base = q + ((size_t)t * NH + h) * HD;
    } else {
        int id2 = id - NQ;
        t = id2 >> 7; int r = id2 & 127; int h = r >> 5; i = r & 31;
        base = k + ((size_t)t * NKV + h) * HD;
    }
    int pos = t & (SEQ - 1);
    float inv = exp2f(-(float)i * 0.4152410118609203f);
    float fr = (float)pos * inv;
    float sn, cs;
    sincosf(fr, &sn, &cs);
    float x1 = base[i], x2 = base[i + 32];
    base[i]      = x1 * cs - x2 * sn;
    base[i + 32] = x2 * cs + x1 * sn;
}

// ---------------- flash attention (tf32 mma, fp16 output) --------------------
#define KST 68
#define VST 72
#define KTILE_F (64 * KST)
#define VTILE_F (64 * VST)
#define KTILE_B (KTILE_F * 4)
#define VTILE_B (VTILE_F * 4)
#define OFF_V_F (2 * KTILE_F)
#define OFF_P_F (2 * KTILE_F + 2 * VTILE_F)
#define FLASH_SMEM_B ((OFF_P_F + 128 * KST) * 4)

__global__ void __launch_bounds__(256, 1)
flash_attn_kernel(const float* __restrict__ q, const float* __restrict__ k,
                  const float* __restrict__ v, __half* __restrict__ att) {
    extern __shared__ float fs[];
    float* Pb = fs + OFF_P_F;
    int qi = (SEQ / 128 - 1) - blockIdx.x;
    int h = blockIdx.y, b = blockIdx.z, hk = h >> 2;
    int qbase = qi * 128;
    int tid = threadIdx.x, lane = tid & 31, w = tid >> 5;
    int lr = lane >> 2, cq = lane & 3;
    int row0 = w * 16 + lr, row1 = row0 + 8;

    unsigned fsBase = smem_u32(fs);
    int rowA = (lane & 7) + ((lane >> 3) & 1) * 8;
    int colA = (lane >> 4) * 4;
    unsigned pLane = fsBase + (unsigned)((OFF_P_F + (w * 16 + rowA) * KST + colA) * 4);
    int rowK = (lane & 7) + ((lane >> 4) & 1) * 8;
    int colK = ((lane >> 3) & 1) * 4;
    unsigned kLane = fsBase + (unsigned)((rowK * KST + colK) * 4);

    const size_t kvs = (size_t)NKV * HD;
    const float* kb = k + ((size_t)(b * SEQ) * NKV + hk) * HD;
    const float* vb = v + ((size_t)(b * SEQ) * NKV + hk) * HD;

    unsigned kDst[4], vDst[4]; const float* kSrc[4]; const float* vSrc[4];
    #pragma unroll
    for (int it = 0; it < 4; it++) {
        int idx = tid + it * 256;
        int rr = idx >> 4, cc = (idx & 15) << 2;
        kDst[it] = fsBase + (unsigned)((rr * KST + cc) * 4);
        vDst[it] = fsBase + (unsigned)((OFF_V_F + rr * VST + cc) * 4);
        kSrc[it] = kb + (size_t)rr * kvs + cc;
        vSrc[it] = vb + (size_t)rr * kvs + cc;
    }
    unsigned qa[8][4];
    {
        const float* q0 = q + ((size_t)(b * SEQ + qbase + row0) * NH + h) * HD;
        const float* q1 = q + ((size_t)(b * SEQ + qbase + row1) * NH + h) * HD;
        #pragma unroll
        for (int ks8 = 0; ks8 < 8; ks8++) {
            int kk = ks8 * 8;
            qa[ks8][0] = __float_as_uint(q0[kk + cq] * 0.125f);
            qa[ks8][1] = __float_as_uint(q1[kk + cq] * 0.125f);
            qa[ks8][2] = __float_as_uint(q0[kk + cq + 4] * 0.125f);
            qa[ks8][3] = __float_as_uint(q1[kk + cq + 4] * 0.125f);
        }
    }
    float oacc[8][4];
    #pragma unroll
    for (int nf = 0; nf < 8; nf++)
        #pragma unroll
        for (int t2 = 0; t2 < 4; t2++) oacc[nf][t2] = 0.f;
    float m0 = -3.0e38f, m1 = -3.0e38f, l0 = 0.f, l1 = 0.f;
    int nkt = 2 * qi + 2;

    #pragma unroll
    for (int it = 0; it < 4; it++) { cp16(kDst[it], kSrc[it], 16); cp16(vDst[it], vSrc[it], 16); }
    cp_commit();

    for (int kt = 0; kt < nkt; kt++) {
        int cur = kt & 1;
        __syncthreads();
        if (kt + 1 < nkt) {
            size_t off = (size_t)(kt + 1) * 64 * kvs;
            int nb = cur ^ 1;
            #pragma unroll
            for (int it = 0; it < 4; it++) {
                cp16(kDst[it] + nb * KTILE_B, kSrc[it] + off, 16);
                cp16(vDst[it] + nb * VTILE_B, vSrc[it] + off, 16);
            }
            cp_commit();
            cp_wait<1>();
        } else cp_wait<0>();
        __syncthreads();

        const float* Vsf = fs + OFF_V_F + cur * VTILE_F;
        float s[8][4];
        #pragma unroll
        for (int nf = 0; nf < 8; nf++)
            #pragma unroll
            for (int t2 = 0; t2 < 4; t2++) s[nf][t2] = 0.f;
        #pragma unroll
        for (int ks8 = 0; ks8 < 8; ks8++) {
            int kk = ks8 * 8;
            #pragma unroll
            for (int nfp = 0; nfp < 4; nfp++) {
                unsigned kb0, kb1, kb2, kb3;
                ldsm_x4(kb0, kb1, kb2, kb3,
                        kLane + cur * KTILE_B + (unsigned)((nfp * 16 * KST + kk) * 4));
                mma_tf32(s[2*nfp],   qa[ks8][0], qa[ks8][1], qa[ks8][2], qa[ks8][3], kb0, kb1);
                mma_tf32(s[2*nfp+1], qa[ks8][0], qa[ks8][1], qa[ks8][2], qa[ks8][3], kb2, kb3);
            }
        }
        if (kt + 2 >= nkt) {
            int dk = kt * 64 - qbase;
            #pragma unroll
            for (int nf = 0; nf < 8; nf++) {
                int c0 = nf * 8 + cq * 2 + dk;
                if (c0     > row0) s[nf][0] = -3.0e38f;
                if (c0 + 1 > row0) s[nf][1] = -3.0e38f;
                if (c0     > row1) s[nf][2] = -3.0e38f;
                if (c0 + 1 > row1) s[nf][3] = -3.0e38f;
            }
        }
        float rm0 = -3.0e38f, rm1 = -3.0e38f;
        #pragma unroll
        for (int nf = 0; nf < 8; nf++) {
            rm0 = fmaxf(rm0, fmaxf(s[nf][0], s[nf][1]));
            rm1 = fmaxf(rm1, fmaxf(s[nf][2], s[nf][3]));
        }
        rm0 = fmaxf(rm0, __shfl_xor_sync(0xffffffffu, rm0, 1));
        rm0 = fmaxf(rm0, __shfl_xor_sync(0xffffffffu, rm0, 2));
        rm1 = fmaxf(rm1, __shfl_xor_sync(0xffffffffu, rm1, 1));
        rm1 = fmaxf(rm1, __shfl_xor_sync(0xffffffffu, rm1, 2));
        float mn0 = fmaxf(m0, rm0), mn1 = fmaxf(m1, rm1);
        float sc0 = __expf(m0 - mn0), sc1 = __expf(m1 - mn1);
        m0 = mn0; m1 = mn1;
        l0 *= sc0; l1 *= sc1;
        #pragma unroll
        for (int nf = 0; nf < 8; nf++) {
            float p0 = __expf(s[nf][0] - mn0), p1 = __expf(s[nf][1] - mn0);
            float p2 = __expf(s[nf][2] - mn1), p3 = __expf(s[nf][3] - mn1);
            l0 += p0 + p1; l1 += p2 + p3;
            int c0 = nf * 8 + cq * 2;
            *(float2*)&Pb[row0 * KST + c0] = make_float2(p0, p1);
            *(float2*)&Pb[row1 * KST + c0] = make_float2(p2, p3);
            oacc[nf][0] *= sc0; oacc[nf][1] *= sc0;
            oacc[nf][2] *= sc1; oacc[nf][3] *= sc1;
        }
        __syncwarp();
        #pragma unroll
        for (int ks8 = 0; ks8 < 8; ks8++) {
            int kk = ks8 * 8;
            unsigned a0, a1, a2, a3;
            ldsm_x4(a0, a1, a2, a3, pLane + (unsigned)(kk * 4));
            #pragma unroll
            for (int nf = 0; nf < 8; nf++) {
                unsigned b0 = __float_as_uint(Vsf[(kk + cq) * VST + nf * 8 + lr]);
                unsigned b1 = __float_as_uint(Vsf[(kk + cq + 4) * VST + nf * 8 + lr]);
                mma_tf32(oacc[nf], a0, a1, a2, a3, b0, b1);
            }
        }
    }
    l0 += __shfl_xor_sync(0xffffffffu, l0, 1);
    l0 += __shfl_xor_sync(0xffffffffu, l0, 2);
    l1 += __shfl_xor_sync(0xffffffffu, l1, 1);
    l1 += __shfl_xor_sync(0xffffffffu, l1, 2);
    float i0 = 1.f / l0, i1 = 1.f / l1;
    __half* o0 = att + ((size_t)(b * SEQ + qbase + row0) * NH + h) * HD;
    __half* o1 = att + ((size_t)(b * SEQ + qbase + row1) * NH + h) * HD;
    #pragma unroll
    for (int nf = 0; nf < 8; nf++) {
        int c0 = nf * 8 + cq * 2;
        *(__half2*)(o0 + c0) = __floats2half2_rn(oacc[nf][0] * i0, oacc[nf][1] * i0);
        *(__half2*)(o1 + c0) = __floats2half2_rn(oacc[nf][2] * i1, oacc[nf][3] * i1);
    }
}

// ---------------- launch ------------------------------------------------------
static inline void launch_gemm(const __half* A, const __half* B, float* Cf, __half* Ch,
                               const float* R, int M, int N, int K,
                               const int* cnt, const int* gi, const float* gw,
                               int epi, int gat, int nz, long aS, long bS, long cS) {
    dim3 grid(N / TN, (M + TM - 1) / TM, nz);
    gemm16_kernel<<<grid, 256, GEMM_SMEM_B>>>(A, B, Cf, Ch, R, M, N, K, cnt, gi, gw,
                                              epi, gat, nullptr, nullptr, nullptr,
                                              nullptr, 0, aS, bS, cS);
}
static inline void conv(const float* s, __half* d, long n) {
    f2h_kernel<<<(unsigned)((n / 4 + 255) / 256), 256>>>(s, d, (int)(n / 4));
}

extern "C" void kernel_launch(void* const* d_in, const int* in_sizes, int n_in,
                              void* d_out, int out_size) {
    const float* x    = (const float*)d_in[0];
    const float* g1   = (const float*)d_in[1];
    const float* g2   = (const float*)d_in[2];
    const float* wq   = (const float*)d_in[3];
    const float* wk   = (const float*)d_in[4];
    const float* wv   = (const float*)d_in[5];
    const float* wo   = (const float*)d_in[6];
    const float* gate = (const float*)d_in[7];
    const float* w1   = (const float*)d_in[8];
    const float* w2   = (const float*)d_in[9];
    const float* w3   = (const float*)d_in[10];
    float* out = (float*)d_out;

    __half *xn16, *att16, *h16, *wq16, *wk16, *wv16, *wo16, *w1h, *w2h, *w3h;
    float *q, *k, *v, *wgt;
    int *cnt, *idx;
    cudaGetSymbolAddress((void**)&xn16,  g_xn16);
    cudaGetSymbolAddress((void**)&att16, g_att16);
    cudaGetSymbolAddress((void**)&h16,   g_h16);
    cudaGetSymbolAddress((void**)&q,   g_q);
    cudaGetSymbolAddress((void**)&k,   g_k);
    cudaGetSymbolAddress((void**)&v,   g_v);
    cudaGetSymbolAddress((void**)&cnt, g_cnt);
    cudaGetSymbolAddress((void**)&idx, g_idx);
    cudaGetSymbolAddress((void**)&wgt, g_wgt);
    cudaGetSymbolAddress((void**)&wq16, g_wq16);
    cudaGetSymbolAddress((void**)&wk16, g_wk16);
    cudaGetSymbolAddress((void**)&wv16, g_wv16);
    cudaGetSymbolAddress((void**)&wo16, g_wo16);
    cudaGetSymbolAddress((void**)&w1h, g_w1h);
    cudaGetSymbolAddress((void**)&w2h, g_w2h);
    cudaGetSymbolAddress((void**)&w3h, g_w3h);

    cudaFuncSetAttribute(flash_attn_kernel,
                         cudaFuncAttributeMaxDynamicSharedMemorySize, FLASH_SMEM_B);
    cudaFuncSetAttribute(gemm16_kernel,
                         cudaFuncAttributeMaxDynamicSharedMemorySize, GEMM_SMEM_B);

    // weight conversion (fp32 -> fp16)
    conv(wq, wq16, (long)DIM * DIM);
    conv(wk, wk16, (long)DIM * NKV * HD);
    conv(wv, wv16, (long)DIM * NKV * HD);
    conv(wo, wo16, (long)DIM * DIM);
    conv(w1, w1h, (long)NE * DIM * HIDDEN);
    conv(w2, w2h, (long)NE * HIDDEN * DIM);
    conv(w3, w3h, (long)NE * DIM * HIDDEN);

    rmsnorm_kernel<<<TOKENS, 256>>>(x, g1, xn16, nullptr, 1);

    {   // fused q/k/v: virtual N = 1536 (1024 q | 256 k | 256 v), fp32 out
        dim3 grid(1536 / TN, TOKENS / TM, 1);
        gemm16_kernel<<<grid, 256, GEMM_SMEM_B>>>(xn16, wq16, q, nullptr, nullptr,
                                                  TOKENS, 1536, DIM,
                                                  nullptr, nullptr, nullptr, 0, 0,
                                                  wk16, wv16, k, v, 1, 0, 0, 0);
    }
    int ropeN = TOKENS * NH * 32 + TOKENS * NKV * 32;
    rope_kernel<<<(ropeN + 255) / 256, 256>>>(q, k);
    {
        dim3 grid(SEQ / 128, NH, 2);
        flash_attn_kernel<<<grid, 256, FLASH_SMEM_B>>>(q, k, v, att16);
    }
    // out = x + att @ wo
    launch_gemm(att16, wo16, out, nullptr, x, TOKENS, DIM, DIM,
                nullptr, nullptr, nullptr, 1, 0, 1, 0, 0, 0);

    rmsnorm_kernel<<<TOKENS, 256>>>(out, g2, xn16, gate, 0);

    // MoE, batched over experts
    launch_gemm(xn16, w1h, nullptr, h16, nullptr, TOKENS, HIDDEN, DIM,
                cnt, idx, nullptr, 4, 1, NE, 0, (long)DIM * HIDDEN, (long)TOKENS * HIDDEN);
    launch_gemm(xn16, w3h, nullptr, h16, nullptr, TOKENS, HIDDEN, DIM,
                cnt, idx, nullptr, 2, 1, NE, 0, (long)DIM * HIDDEN, (long)TOKENS * HIDDEN);
    launch_gemm(h16, w2h, out, nullptr, nullptr, TOKENS, DIM, HIDDEN,
                cnt, idx, wgt, 3, 0, NE, (long)TOKENS * HIDDEN, (long)HIDDEN * DIM, 0);
}

// round 14
// speedup vs baseline: 9.2387x; 1.0798x over previous
#include <cuda_runtime.h>
#include <cuda_fp16.h>
#include <math.h>

#define TOKENS 4096
#define DIM    1024
#define SEQ    2048
#define NH     16
#define NKV    4
#define HD     64
#define HIDDEN 3072
#define NE     4
#define RMS_EPS 1.1920928955078125e-07f

// ---------------- scratch ----------------------------------------------------
__device__ __half g_xn16 [TOKENS * DIM];
__device__ __half g_att16[TOKENS * DIM];
__device__ __half g_h16  [NE * TOKENS * HIDDEN];
__device__ __half g_q16 [TOKENS * DIM];
__device__ __half g_k16 [TOKENS * NKV * HD];
__device__ __half g_v16 [TOKENS * NKV * HD];
__device__ int    g_cnt[NE];
__device__ int    g_idx[NE * TOKENS];
__device__ float  g_wgt[NE * TOKENS];
__device__ __half g_wq16[DIM * DIM];
__device__ __half g_wk16[DIM * NKV * HD];
__device__ __half g_wv16[DIM * NKV * HD];
__device__ __half g_wo16[DIM * DIM];
__device__ __half g_w1h [NE * DIM * HIDDEN];
__device__ __half g_w2h [NE * HIDDEN * DIM];
__device__ __half g_w3h [NE * DIM * HIDDEN];

__device__ __forceinline__ unsigned h2u(__half2 h) {
    unsigned u;
    memcpy(&u, &h, 4);
    return u;
}
__device__ __forceinline__ unsigned smem_u32(const void* p) {
    return (unsigned)__cvta_generic_to_shared(p);
}
__device__ __forceinline__ void cp16(unsigned dst, const void* src, int sz) {
    asm volatile("cp.async.cg.shared.global [%0], [%1], 16, %2;"
                 :: "r"(dst), "l"(src), "r"(sz));
}
__device__ __forceinline__ void cp_commit() {
    asm volatile("cp.async.commit_group;");
}
template<int N> __device__ __forceinline__ void cp_wait() {
    asm volatile("cp.async.wait_group %0;" :: "n"(N));
}
__device__ __forceinline__ void ldsm_x4(unsigned& r0, unsigned& r1,
                                        unsigned& r2, unsigned& r3, unsigned a) {
    asm volatile("ldmatrix.sync.aligned.m8n8.x4.shared.b16 {%0,%1,%2,%3}, [%4];"
                 : "=r"(r0), "=r"(r1), "=r"(r2), "=r"(r3) : "r"(a));
}
__device__ __forceinline__ void ldsm_x4t(unsigned& r0, unsigned& r1,
                                         unsigned& r2, unsigned& r3, unsigned a) {
    asm volatile("ldmatrix.sync.aligned.m8n8.x4.trans.shared.b16 {%0,%1,%2,%3}, [%4];"
                 : "=r"(r0), "=r"(r1), "=r"(r2), "=r"(r3) : "r"(a));
}
__device__ __forceinline__ void mma_f16(float c[4], unsigned a0, unsigned a1,
                                        unsigned a2, unsigned a3,
                                        unsigned b0, unsigned b1) {
    asm volatile("mma.sync.aligned.m16n8k16.row.col.f32.f16.f16.f32 "
        "{%0,%1,%2,%3}, {%4,%5,%6,%7}, {%8,%9}, {%0,%1,%2,%3};"
        : "+f"(c[0]), "+f"(c[1]), "+f"(c[2]), "+f"(c[3])
        : "r"(a0), "r"(a1), "r"(a2), "r"(a3), "r"(b0), "r"(b1));
}

// ---------------- fused fp32 -> fp16 weight conversion (ONE launch) ----------
__global__ void convall_kernel(const float* __restrict__ wq, const float* __restrict__ wk,
                               const float* __restrict__ wv, const float* __restrict__ wo,
                               const float* __restrict__ w1, const float* __restrict__ w2,
                               const float* __restrict__ w3) {
    long i = (long)blockIdx.x * blockDim.x + threadIdx.x;
    const float* s; __half* d; long off;
    if      (i < 262144L)  { s = wq; d = g_wq16; off = i; }
    else if (i < 327680L)  { s = wk; d = g_wk16; off = i - 262144L; }
    else if (i < 393216L)  { s = wv; d = g_wv16; off = i - 327680L; }
    else if (i < 655360L)  { s = wo; d = g_wo16; off = i - 393216L; }
    else if (i < 3801088L) { s = w1; d = g_w1h;  off = i - 655360L; }
    else if (i < 6946816L) { s = w2; d = g_w2h;  off = i - 3801088L; }
    else if (i < 10092544L){ s = w3; d = g_w3h;  off = i - 6946816L; }
    else return;
    float4 v = ((const float4*)s)[off];
    __half2* dp = (__half2*)(d + off * 4);
    dp[0] = __floats2half2_rn(v.x, v.y);
    dp[1] = __floats2half2_rn(v.z, v.w);
}

// ---------------- RMSNorm -> fp16 (+optional fused MoE gate) -----------------
__global__ void rmsnorm_kernel(const float* __restrict__ x, const float* __restrict__ g,
                               __half* __restrict__ o, const float* __restrict__ gate,
                               int zcnt) {
    int t = blockIdx.x, tid = threadIdx.x;
    if (zcnt && t == 0 && tid < NE) g_cnt[tid] = 0;
    const float* xr = x + (size_t)t * DIM;
    float ss = 0.f;
    for (int i = tid; i < DIM; i += 256) { float v = xr[i]; ss += v * v; }
    #pragma unroll
    for (int o2 = 16; o2; o2 >>= 1) ss += __shfl_xor_sync(0xffffffffu, ss, o2);
    __shared__ float sw[8];
    __shared__ float sg[8][NE];
    if ((tid & 31) == 0) sw[tid >> 5] = ss;
    __syncthreads();
    if (tid < 8) {
        float v = sw[tid];
        #pragma unroll
        for (int o2 = 4; o2; o2 >>= 1) v += __shfl_xor_sync(0xffu, v, o2);
        if (tid == 0) sw[0] = v;
    }
    __syncthreads();
    float r = rsqrtf(sw[0] * (1.0f / DIM) + RMS_EPS);
    __half* orow = o + (size_t)t * DIM;
    if (!gate) {
        for (int i = tid; i < DIM; i += 256)
            orow[i] = __float2half_rn(xr[i] * r * g[i]);
        return;
    }
    float a0 = 0.f, a1 = 0.f, a2 = 0.f, a3 = 0.f;
    for (int i = tid; i < DIM; i += 256) {
        float val = xr[i] * r * g[i];
        orow[i] = __float2half_rn(val);
        const float* gr = gate + (size_t)i * NE;
        a0 += val * gr[0]; a1 += val * gr[1]; a2 += val * gr[2]; a3 += val * gr[3];
    }
    #pragma unroll
    for (int o2 = 16; o2; o2 >>= 1) {
        a0 += __shfl_xor_sync(0xffffffffu, a0, o2);
        a1 += __shfl_xor_sync(0xffffffffu, a1, o2);
        a2 += __shfl_xor_sync(0xffffffffu, a2, o2);
        a3 += __shfl_xor_sync(0xffffffffu, a3, o2);
    }
    if ((tid & 31) == 0) {
        int w = tid >> 5;
        sg[w][0] = a0; sg[w][1] = a1; sg[w][2] = a2; sg[w][3] = a3;
    }
    __syncthreads();
    if (tid == 0) {
        float p[NE];
        #pragma unroll
        for (int e = 0; e < NE; e++) {
            float s = 0.f;
            #pragma unroll
            for (int w = 0; w < 8; w++) s += sg[w][e];
            p[e] = s;
        }
        float mx = fmaxf(fmaxf(p[0], p[1]), fmaxf(p[2], p[3]));
        #pragma unroll
        for (int e = 0; e < NE; e++) p[e] = __expf(p[e] - mx);
        int e0 = 0;
        #pragma unroll
        for (int e = 1; e < NE; e++) if (p[e] > p[e0]) e0 = e;
        int e1 = -1;
        #pragma unroll
        for (int e = 0; e < NE; e++) if (e != e0 && (e1 < 0 || p[e] > p[e1])) e1 = e;
        float w0 = p[e0], w1 = p[e1], ws = p[e0] + p[e1];
        w0 /= ws; w1 /= ws;
        int s0 = atomicAdd(&g_cnt[e0], 1);
        g_idx[e0 * TOKENS + s0] = t; g_wgt[e0 * TOKENS + s0] = w0;
        int s1 = atomicAdd(&g_cnt[e1], 1);
        g_idx[e1 * TOKENS + s1] = t; g_wgt[e1 * TOKENS + s1] = w1;
    }
}

// ---------------- fp16 GEMM: 128x128x32, 3-stage, 1 sync/iter ----------------
#define TM 128
#define TN 128
#define SAB 80
#define SBB 272
#define A_STG (128 * SAB)
#define B_STG (32 * SBB)
#define STG   (A_STG + B_STG)
#define GEMM_SMEM_B (3 * STG)

// epi: 0=Cf=acc ; 1=Cf=acc+R ; 2=Ch=h(silu(Ch)*acc) ; 3=atomicAdd(Cf[idx],acc*w) ; 4=Ch=h(acc)
__global__ void __launch_bounds__(256, 2)
gemm16_kernel(const __half* __restrict__ A, const __half* __restrict__ B,
              float* __restrict__ Cf, __half* __restrict__ Ch,
              const float* __restrict__ R,
              int M, int N, int K,
              const int* __restrict__ cnt,
              const int* __restrict__ gidx, const float* __restrict__ gwgt,
              int epi, int gatherA,
              const __half* __restrict__ B2, const __half* __restrict__ B3,
              __half* __restrict__ Ch2, __half* __restrict__ Ch3, int qkv,
              long aStride, long bStride, long cStride) {
    int ez = blockIdx.z;
    if (cnt)  cnt  += ez;
    if (gidx) gidx += (size_t)ez * TOKENS;
    if (gwgt) gwgt += (size_t)ez * TOKENS;
    A += (size_t)ez * aStride;
    B += (size_t)ez * bStride;
    if (Cf) Cf += (size_t)ez * cStride;
    if (Ch) Ch += (size_t)ez * cStride;

    int Meff = cnt ? *cnt : M;
    int rowBase = blockIdx.y * TM;
    if (rowBase >= Meff) return;

    extern __shared__ __align__(16) char gsm[];
    unsigned sm0 = smem_u32(gsm);

    int tid  = threadIdx.x;
    int lane = tid & 31;
    int wid  = tid >> 5;
    int wm   = wid & 1;
    int wn   = wid >> 1;
    int nBase = blockIdx.x * TN;

    const __half* Bq = B; float* Cq = Cf; __half* ChR = Ch; int ld = N; int nLoc = nBase;
    if (qkv) {
        if (nBase >= 1280)      { Bq = B3; ChR = Ch3; ld = 256;  nLoc = nBase - 1280; }
        else if (nBase >= 1024) { Bq = B2; ChR = Ch2; ld = 256;  nLoc = nBase - 1024; }
        else                    {                     ld = 1024; }
    }

    float acc[4][4][4];
    #pragma unroll
    for (int i = 0; i < 4; i++)
        #pragma unroll
        for (int j = 0; j < 4; j++)
            #pragma unroll
            for (int q = 0; q < 4; q++) acc[i][j][q] = 0.f;

    const __half* aP[2]; unsigned aO[2]; int aSz[2];
    const __half* bP[2]; unsigned bO[2];
    #pragma unroll
    for (int s = 0; s < 2; s++) {
        int f = tid + s * 256;
        int ar = f >> 2, ac = f & 3;
        int row = rowBase + ar;
        bool ok = row < Meff;
        long src = 0;
        if (ok) src = gatherA ? (long)gidx[row] : (long)row;
        aP[s] = A + src * (size_t)K + ac * 8;
        aSz[s] = ok ? 16 : 0;
        aO[s] = (unsigned)(ar * SAB + ac * 16);
        int br = f >> 4, bc = f & 15;
        bP[s] = Bq + (size_t)br * ld + nLoc + bc * 8;
        bO[s] = (unsigned)(A_STG + br * SBB + bc * 16);
    }

    int nIter = K / 32;
    #pragma unroll
    for (int p = 0; p < 2; p++) {
        unsigned sb = sm0 + p * STG;
        int kt = p * 32;
        #pragma unroll
        for (int s = 0; s < 2; s++) {
            cp16(sb + aO[s], aP[s] + kt, aSz[s]);
            cp16(sb + bO[s], bP[s] + (size_t)kt * ld, 16);
        }
        cp_commit();
    }

    int rA = (lane & 7) + ((lane >> 3) & 1) * 8;
    int gA = lane >> 4;
    unsigned aLane = (unsigned)((wm * 64 + rA) * SAB + gA * 16);
    int rB = (lane & 7) + ((lane >> 3) & 1) * 8;
    int gB = lane >> 4;
    unsigned bLane = (unsigned)(A_STG + rB * SBB + (wn * 32 + gB * 8) * 2);

    int st = 0;
    for (int it = 0; it < nIter; it++) {
        if (it + 1 < nIter) cp_wait<1>(); else cp_wait<0>();
        __syncthreads();
        unsigned sb = sm0 + st * STG;

        #pragma unroll
        for (int k16 = 0; k16 < 2; k16++) {
            unsigned bf[4][2];
            #pragma unroll
            for (int jp = 0; jp < 2; jp++) {
                unsigned b0, b1, b2, b3;
                ldsm_x4t(b0, b1, b2, b3,
                         sb + bLane + (unsigned)(k16 * 16 * SBB + jp * 32));
                bf[jp * 2][0] = b0; bf[jp * 2][1] = b1;
                bf[jp * 2 + 1][0] = b2; bf[jp * 2 + 1][1] = b3;
            }
            #pragma unroll
            for (int i = 0; i < 4; i++) {
                unsigned a0, a1, a2, a3;
                ldsm_x4(a0, a1, a2, a3,
                        sb + aLane + (unsigned)(i * 16 * SAB + k16 * 32));
                #pragma unroll
                for (int j = 0; j < 4; j++)
                    mma_f16(acc[i][j], a0, a1, a2, a3, bf[j][0], bf[j][1]);
            }
        }

        if (it + 2 < nIter) {
            unsigned sn = sm0 + ((st + 2 >= 3) ? st - 1 : st + 2) * STG;
            int kt = (it + 2) * 32;
            #pragma unroll
            for (int s = 0; s < 2; s++) {
                cp16(sn + aO[s], aP[s] + kt, aSz[s]);
                cp16(sn + bO[s], bP[s] + (size_t)kt * ld, 16);
            }
            cp_commit();
        }
        st = (st + 1 == 3) ? 0 : st + 1;
    }

    int r = lane >> 2, c = lane & 3;
    #pragma unroll
    for (int i = 0; i < 4; i++) {
        int rbase = rowBase + wm * 64 + i * 16 + r;
        #pragma unroll
        for (int half = 0; half < 2; half++) {
            int rr = rbase + half * 8;
            if (rr >= Meff) continue;
            int tok = 0; float w = 0.f;
            if (epi == 3) { tok = gidx[rr]; w = gwgt[rr]; }
            #pragma unroll
            for (int j = 0; j < 4; j++) {
                int col = nLoc + wn * 32 + j * 8 + (c << 1);
                float v0 = acc[i][j][half * 2];
                float v1 = acc[i][j][half * 2 + 1];
                if (epi == 0) {
                    *(float2*)(Cq + (size_t)rr * ld + col) = make_float2(v0, v1);
                } else if (epi == 1) {
                    float2 rv = *(const float2*)(R + (size_t)rr * ld + col);
                    *(float2*)(Cq + (size_t)rr * ld + col) =
                        make_float2(v0 + rv.x, v1 + rv.y);
                } else if (epi == 2) {
                    __half2* hp = (__half2*)(Ch + (size_t)rr * ld + col);
                    float2 hv = __half22float2(*hp);
                    float s0 = hv.x / (1.f + __expf(-hv.x));
                    float s1 = hv.y / (1.f + __expf(-hv.y));
                    *hp = __floats2half2_rn(s0 * v0, s1 * v1);
                } else if (epi == 3) {
                    float* cp = Cq + (size_t)tok * ld + col;
                    atomicAdd(cp,     v0 * w);
                    atomicAdd(cp + 1, v1 * w);
                } else {
                    *(__half2*)(ChR + (size_t)rr * ld + col) = __floats2half2_rn(v0, v1);
                }
            }
        }
    }
}

// ---------------- RoPE on fp16 q,k (in place) --------------------------------
__global__ void rope16_kernel(__half* __restrict__ q, __half* __restrict__ k) {
    int id = blockIdx.x * blockDim.x + threadIdx.x;
    const int NQ = TOKENS * NH * 32;
    const int NK2 = TOKENS * NKV * 32;
    if (id >= NQ + NK2) return;
    __half* base; int t, i;
    if (id < NQ) {
        t = id >> 9; int r = id & 511; int h = r >> 5; i = r & 31;
        base = q + ((size_t)t * NH + h) * HD;
    } else {
        int id2 = id - NQ;
        t = id2 >> 7; int r = id2 & 127; int h = r >> 5; i = r & 31;
        base = k + ((size_t)t * NKV + h) * HD;
    }
    int pos = t & (SEQ - 1);
    float inv = exp2f(-(float)i * 0.4152410118609203f);
    float fr = (float)pos * inv;
    float sn, cs;
    sincosf(fr, &sn, &cs);
    float x1 = __half2float(base[i]), x2 = __half2float(base[i + 32]);
    base[i]      = __float2half_rn(x1 * cs - x2 * sn);
    base[i + 32] = __float2half_rn(x2 * cs + x1 * sn);
}

// ---------------- fp16 flash attention: 128 q-rows x 64-key tiles ------------
#define HST 72
#define KOFF 0
#define VOFF (2 * 64 * HST)
#define POFF (VOFF + 2 * 64 * HST)
#define KTB  (64 * HST * 2)
#define FLASH_SMEM_B ((POFF + 128 * HST) * 2)

__global__ void __launch_bounds__(256, 1)
flash16_kernel(const __half* __restrict__ q, const __half* __restrict__ k,
               const __half* __restrict__ v, __half* __restrict__ att) {
    extern __shared__ __half hs[];
    int qi = (SEQ / 128 - 1) - blockIdx.x;
    int h = blockIdx.y, b = blockIdx.z, hk = h >> 2;
    int qbase = qi * 128;
    int tid = threadIdx.x, lane = tid & 31, w = tid >> 5;
    int lr = lane >> 2, cq = lane & 3;
    int row0 = w * 16 + lr, row1 = row0 + 8;
    unsigned base = smem_u32(hs);

    int rA = (lane & 7) + ((lane >> 3) & 1) * 8;
    int cA = ((lane >> 4) & 1) * 8;
    unsigned pLane = base + (unsigned)((POFF + (w * 16 + rA) * HST + cA) * 2);
    unsigned kLane = base + (unsigned)((KOFF + rA * HST + cA) * 2);
    int gB = lane >> 4;
    unsigned vLane = base + (unsigned)((VOFF + rA * HST + gB * 8) * 2);

    const size_t kvs = (size_t)NKV * HD;
    const __half* kb = k + ((size_t)(b * SEQ) * NKV + hk) * HD;
    const __half* vb = v + ((size_t)(b * SEQ) * NKV + hk) * HD;

    unsigned kDst[2], vDst[2]; const __half* kSrc[2]; const __half* vSrc[2];
    #pragma unroll
    for (int s = 0; s < 2; s++) {
        int idx = tid + s * 256;
        int rr = idx >> 3, cc = idx & 7;
        kDst[s] = base + (unsigned)((KOFF + rr * HST + cc * 8) * 2);
        vDst[s] = base + (unsigned)((VOFF + rr * HST + cc * 8) * 2);
        kSrc[s] = kb + (size_t)rr * kvs + cc * 8;
        vSrc[s] = vb + (size_t)rr * kvs + cc * 8;
    }

    // Q fragments, pre-scaled by 0.125 (exact in fp16)
    unsigned qa[4][4];
    {
        const __half* q0 = q + ((size_t)(b * SEQ + qbase + row0) * NH + h) * HD;
        const __half* q1 = q + ((size_t)(b * SEQ + qbase + row1) * NH + h) * HD;
        __half2 sc = __float2half2_rn(0.125f);
        #pragma unroll
        for (int g = 0; g < 4; g++) {
            int kk = g * 16 + cq * 2;
            qa[g][0] = h2u(__hmul2(*(const __half2*)(q0 + kk), sc));
            qa[g][1] = h2u(__hmul2(*(const __half2*)(q1 + kk), sc));
            qa[g][2] = h2u(__hmul2(*(const __half2*)(q0 + kk + 8), sc));
            qa[g][3] = h2u(__hmul2(*(const __half2*)(q1 + kk + 8), sc));
        }
    }

    float oacc[8][4];
    #pragma unroll
    for (int nf = 0; nf < 8; nf++)
        #pragma unroll
        for (int t2 = 0; t2 < 4; t2++) oacc[nf][t2] = 0.f;
    float m0 = -3.0e38f, m1 = -3.0e38f, l0 = 0.f, l1 = 0.f;
    int nkt = 2 * qi + 2;

    #pragma unroll
    for (int s = 0; s < 2; s++) { cp16(kDst[s], kSrc[s], 16); cp16(vDst[s], vSrc[s], 16); }
    cp_commit();

    for (int kt = 0; kt < nkt; kt++) {
        int cur = kt & 1;
        __syncthreads();
        if (kt + 1 < nkt) {
            size_t off = (size_t)(kt + 1) * 64 * kvs;
            int nb = cur ^ 1;
            #pragma unroll
            for (int s = 0; s < 2; s++) {
                cp16(kDst[s] + nb * KTB, kSrc[s] + off, 16);
                cp16(vDst[s] + nb * KTB, vSrc[s] + off, 16);
            }
            cp_commit();
            cp_wait<1>();
        } else cp_wait<0>();
        __syncthreads();

        // S = Q @ K^T (fp16 mma k16)
        float s[8][4];
        #pragma unroll
        for (int nf = 0; nf < 8; nf++)
            #pragma unroll
            for (int t2 = 0; t2 < 4; t2++) s[nf][t2] = 0.f;
        #pragma unroll
        for (int g = 0; g < 4; g++) {
            #pragma unroll
            for (int nfp = 0; nfp < 4; nfp++) {
                unsigned b0, b1, b2, b3;
                ldsm_x4(b0, b1, b2, b3,
                        kLane + cur * KTB + (unsigned)(nfp * 16 * HST * 2 + g * 32));
                mma_f16(s[2 * nfp],     qa[g][0], qa[g][1], qa[g][2], qa[g][3], b0, b2);
                mma_f16(s[2 * nfp + 1], qa[g][0], qa[g][1], qa[g][2], qa[g][3], b1, b3);
            }
        }

        if (kt + 2 >= nkt) {
            int dk = kt * 64 - qbase;
            #pragma unroll
            for (int nf = 0; nf < 8; nf++) {
                int c0 = nf * 8 + cq * 2 + dk;
                if (c0     > row0) s[nf][0] = -3.0e38f;
                if (c0 + 1 > row0) s[nf][1] = -3.0e38f;
                if (c0     > row1) s[nf][2] = -3.0e38f;
                if (c0 + 1 > row1) s[nf][3] = -3.0e38f;
            }
        }

        float rm0 = -3.0e38f, rm1 = -3.0e38f;
        #pragma unroll
        for (int nf = 0; nf < 8; nf++) {
            rm0 = fmaxf(rm0, fmaxf(s[nf][0], s[nf][1]));
            rm1 = fmaxf(rm1, fmaxf(s[nf][2], s[nf][3]));
        }
        rm0 = fmaxf(rm0, __shfl_xor_sync(0xffffffffu, rm0, 1));
        rm0 = fmaxf(rm0, __shfl_xor_sync(0xffffffffu, rm0, 2));
        rm1 = fmaxf(rm1, __shfl_xor_sync(0xffffffffu, rm1, 1));
        rm1 = fmaxf(rm1, __shfl_xor_sync(0xffffffffu, rm1, 2));
        float mn0 = fmaxf(m0, rm0), mn1 = fmaxf(m1, rm1);
        float sc0 = __expf(m0 - mn0), sc1 = __expf(m1 - mn1);
        m0 = mn0; m1 = mn1;
        l0 *= sc0; l1 *= sc1;
        __half* Pb = hs + POFF;
        #pragma unroll
        for (int nf = 0; nf < 8; nf++) {
            float p0 = __expf(s[nf][0] - mn0), p1 = __expf(s[nf][1] - mn0);
            float p2 = __expf(s[nf][2] - mn1), p3 = __expf(s[nf][3] - mn1);
            l0 += p0 + p1; l1 += p2 + p3;
            int c0 = nf * 8 + cq * 2;
            *(__half2*)(Pb + row0 * HST + c0) = __floats2half2_rn(p0, p1);
            *(__half2*)(Pb + row1 * HST + c0) = __floats2half2_rn(p2, p3);
            oacc[nf][0] *= sc0; oacc[nf][1] *= sc0;
            oacc[nf][2] *= sc1; oacc[nf][3] *= sc1;
        }
        __syncwarp();

        // O += P @ V (P A-frags, V trans B-frags)
        #pragma unroll
        for (int g = 0; g < 4; g++) {
            unsigned a0, a1, a2, a3;
            ldsm_x4(a0, a1, a2, a3, pLane + (unsigned)(g * 32));
            #pragma unroll
            for (int jp = 0; jp < 4; jp++) {
                unsigned b0, b1, b2, b3;
                ldsm_x4t(b0, b1, b2, b3,
                         vLane + cur * KTB + (unsigned)(g * 16 * HST * 2 + jp * 32));
                mma_f16(oacc[2 * jp],     a0, a1, a2, a3, b0, b1);
                mma_f16(oacc[2 * jp + 1], a0, a1, a2, a3, b2, b3);
            }
        }
    }

    l0 += __shfl_xor_sync(0xffffffffu, l0, 1);
    l0 += __shfl_xor_sync(0xffffffffu, l0, 2);
    l1 += __shfl_xor_sync(0xffffffffu, l1, 1);
    l1 += __shfl_xor_sync(0xffffffffu, l1, 2);
    float i0 = 1.f / l0, i1 = 1.f / l1;
    __half* o0 = att + ((size_t)(b * SEQ + qbase + row0) * NH + h) * HD;
    __half* o1 = att + ((size_t)(b * SEQ + qbase + row1) * NH + h) * HD;
    #pragma unroll
    for (int nf = 0; nf < 8; nf++) {
        int c0 = nf * 8 + cq * 2;
        *(__half2*)(o0 + c0) = __floats2half2_rn(oacc[nf][0] * i0, oacc[nf][1] * i0);
        *(__half2*)(o1 + c0) = __floats2half2_rn(oacc[nf][2] * i1, oacc[nf][3] * i1);
    }
}

// ---------------- launch ------------------------------------------------------
static inline void launch_gemm(const __half* A, const __half* B, float* Cf, __half* Ch,
                               const float* R, int M, int N, int K,
                               const int* cnt, const int* gi, const float* gw,
                               int epi, int gat, int nz, long aS, long bS, long cS) {
    dim3 grid(N / TN, (M + TM - 1) / TM, nz);
    gemm16_kernel<<<grid, 256, GEMM_SMEM_B>>>(A, B, Cf, Ch, R, M, N, K, cnt, gi, gw,
                                              epi, gat, nullptr, nullptr, nullptr,
                                              nullptr, 0, aS, bS, cS);
}

extern "C" void kernel_launch(void* const* d_in, const int* in_sizes, int n_in,
                              void* d_out, int out_size) {
    const float* x    = (const float*)d_in[0];
    const float* g1   = (const float*)d_in[1];
    const float* g2   = (const float*)d_in[2];
    const float* wq   = (const float*)d_in[3];
    const float* wk   = (const float*)d_in[4];
    const float* wv   = (const float*)d_in[5];
    const float* wo   = (const float*)d_in[6];
    const float* gate = (const float*)d_in[7];
    const float* w1   = (const float*)d_in[8];
    const float* w2   = (const float*)d_in[9];
    const float* w3   = (const float*)d_in[10];
    float* out = (float*)d_out;

    __half *xn16, *att16, *h16, *q16, *k16, *v16;
    __half *wq16, *wk16, *wv16, *wo16, *w1h, *w2h, *w3h;
    float *wgt;
    int *cnt, *idx;
    cudaGetSymbolAddress((void**)&xn16,  g_xn16);
    cudaGetSymbolAddress((void**)&att16, g_att16);
    cudaGetSymbolAddress((void**)&h16,   g_h16);
    cudaGetSymbolAddress((void**)&q16, g_q16);
    cudaGetSymbolAddress((void**)&k16, g_k16);
    cudaGetSymbolAddress((void**)&v16, g_v16);
    cudaGetSymbolAddress((void**)&cnt, g_cnt);
    cudaGetSymbolAddress((void**)&idx, g_idx);
    cudaGetSymbolAddress((void**)&wgt, g_wgt);
    cudaGetSymbolAddress((void**)&wq16, g_wq16);
    cudaGetSymbolAddress((void**)&wk16, g_wk16);
    cudaGetSymbolAddress((void**)&wv16, g_wv16);
    cudaGetSymbolAddress((void**)&wo16, g_wo16);
    cudaGetSymbolAddress((void**)&w1h, g_w1h);
    cudaGetSymbolAddress((void**)&w2h, g_w2h);
    cudaGetSymbolAddress((void**)&w3h, g_w3h);

    cudaFuncSetAttribute(flash16_kernel,
                         cudaFuncAttributeMaxDynamicSharedMemorySize, FLASH_SMEM_B);
    cudaFuncSetAttribute(gemm16_kernel,
                         cudaFuncAttributeMaxDynamicSharedMemorySize, GEMM_SMEM_B);

    // 1: fused weight conversion
    convall_kernel<<<(10092544 + 255) / 256, 256>>>(wq, wk, wv, wo, w1, w2, w3);
    // 2: rmsnorm1 (+cnt zero)
    rmsnorm_kernel<<<TOKENS, 256>>>(x, g1, xn16, nullptr, 1);
    // 3: fused q/k/v (fp16 outputs)
    {
        dim3 grid(1536 / TN, TOKENS / TM, 1);
        gemm16_kernel<<<grid, 256, GEMM_SMEM_B>>>(xn16, wq16, nullptr, q16, nullptr,
                                                  TOKENS, 1536, DIM,
                                                  nullptr, nullptr, nullptr, 4, 0,
                                                  wk16, wv16, k16, v16, 1, 0, 0, 0);
    }
    // 4: rope
    int ropeN = TOKENS * NH * 32 + TOKENS * NKV * 32;
    rope16_kernel<<<(ropeN + 255) / 256, 256>>>(q16, k16);
    // 5: flash
    {
        dim3 grid(SEQ / 128, NH, 2);
        flash16_kernel<<<grid, 256, FLASH_SMEM_B>>>(q16, k16, v16, att16);
    }
    // 6: out = x + att @ wo   (ncu profiles this launch)
    launch_gemm(att16, wo16, out, nullptr, x, TOKENS, DIM, DIM,
                nullptr, nullptr, nullptr, 1, 0, 1, 0, 0, 0);
    // 7: rmsnorm2 + gate
    rmsnorm_kernel<<<TOKENS, 256>>>(out, g2, xn16, gate, 0);
    // 8-10: MoE batched over experts
    launch_gemm(xn16, w1h, nullptr, h16, nullptr, TOKENS, HIDDEN, DIM,
                cnt, idx, nullptr, 4, 1, NE, 0, (long)DIM * HIDDEN, (long)TOKENS * HIDDEN);
    launch_gemm(xn16, w3h, nullptr, h16, nullptr, TOKENS, HIDDEN, DIM,
                cnt, idx, nullptr, 2, 1, NE, 0, (long)DIM * HIDDEN, (long)TOKENS * HIDDEN);
    launch_gemm(h16, w2h, out, nullptr, nullptr, TOKENS, DIM, HIDDEN,
                cnt, idx, wgt, 3, 0, NE, (long)TOKENS * HIDDEN, (long)HIDDEN * DIM, 0);
}

// round 15
// speedup vs baseline: 12.8832x; 1.3945x over previous
#include <cuda_runtime.h>
#include <cuda_fp16.h>
#include <math.h>

#define TOKENS 4096
#define DIM    1024
#define SEQ    2048
#define NH     16
#define NKV    4
#define HD     64
#define HIDDEN 3072
#define NE     4
#define RMS_EPS 1.1920928955078125e-07f

// ---------------- scratch ----------------------------------------------------
__device__ __half g_xn16 [TOKENS * DIM];
__device__ __half g_att16[TOKENS * DIM];
__device__ __half g_h16  [NE * TOKENS * HIDDEN];
__device__ __half g_q16 [TOKENS * DIM];
__device__ __half g_k16 [TOKENS * NKV * HD];
__device__ __half g_v16 [TOKENS * NKV * HD];
__device__ int    g_cnt[NE];
__device__ int    g_idx[NE * TOKENS];
__device__ float  g_wgt[NE * TOKENS];
__device__ __half g_wq16[DIM * DIM];
__device__ __half g_wk16[DIM * NKV * HD];
__device__ __half g_wv16[DIM * NKV * HD];
__device__ __half g_wo16[DIM * DIM];
__device__ __half g_w1h [NE * DIM * HIDDEN];
__device__ __half g_w2h [NE * HIDDEN * DIM];
__device__ __half g_w3h [NE * DIM * HIDDEN];

__device__ __forceinline__ unsigned h2u(__half2 h) {
    unsigned u;
    memcpy(&u, &h, 4);
    return u;
}
__device__ __forceinline__ unsigned smem_u32(const void* p) {
    return (unsigned)__cvta_generic_to_shared(p);
}
__device__ __forceinline__ void cp16(unsigned dst, const void* src, int sz) {
    asm volatile("cp.async.cg.shared.global [%0], [%1], 16, %2;"
                 :: "r"(dst), "l"(src), "r"(sz));
}
__device__ __forceinline__ void cp_commit() {
    asm volatile("cp.async.commit_group;");
}
template<int N> __device__ __forceinline__ void cp_wait() {
    asm volatile("cp.async.wait_group %0;" :: "n"(N));
}
__device__ __forceinline__ void ldsm_x4(unsigned& r0, unsigned& r1,
                                        unsigned& r2, unsigned& r3, unsigned a) {
    asm volatile("ldmatrix.sync.aligned.m8n8.x4.shared.b16 {%0,%1,%2,%3}, [%4];"
                 : "=r"(r0), "=r"(r1), "=r"(r2), "=r"(r3) : "r"(a));
}
__device__ __forceinline__ void ldsm_x4t(unsigned& r0, unsigned& r1,
                                         unsigned& r2, unsigned& r3, unsigned a) {
    asm volatile("ldmatrix.sync.aligned.m8n8.x4.trans.shared.b16 {%0,%1,%2,%3}, [%4];"
                 : "=r"(r0), "=r"(r1), "=r"(r2), "=r"(r3) : "r"(a));
}
__device__ __forceinline__ void mma_f16(float c[4], unsigned a0, unsigned a1,
                                        unsigned a2, unsigned a3,
                                        unsigned b0, unsigned b1) {
    asm volatile("mma.sync.aligned.m16n8k16.row.col.f32.f16.f16.f32 "
        "{%0,%1,%2,%3}, {%4,%5,%6,%7}, {%8,%9}, {%0,%1,%2,%3};"
        : "+f"(c[0]), "+f"(c[1]), "+f"(c[2]), "+f"(c[3])
        : "r"(a0), "r"(a1), "r"(a2), "r"(a3), "r"(b0), "r"(b1));
}

// ---------------- fused fp32 -> fp16 weight conversion (ONE launch) ----------
__global__ void convall_kernel(const float* __restrict__ wq, const float* __restrict__ wk,
                               const float* __restrict__ wv, const float* __restrict__ wo,
                               const float* __restrict__ w1, const float* __restrict__ w2,
                               const float* __restrict__ w3) {
    long i = (long)blockIdx.x * blockDim.x + threadIdx.x;
    const float* s; __half* d; long off;
    if      (i < 262144L)  { s = wq; d = g_wq16; off = i; }
    else if (i < 327680L)  { s = wk; d = g_wk16; off = i - 262144L; }
    else if (i < 393216L)  { s = wv; d = g_wv16; off = i - 327680L; }
    else if (i < 655360L)  { s = wo; d = g_wo16; off = i - 393216L; }
    else if (i < 3801088L) { s = w1; d = g_w1h;  off = i - 655360L; }
    else if (i < 6946816L) { s = w2; d = g_w2h;  off = i - 3801088L; }
    else if (i < 10092544L){ s = w3; d = g_w3h;  off = i - 6946816L; }
    else return;
    float4 v = ((const float4*)s)[off];
    __half2* dp = (__half2*)(d + off * 4);
    dp[0] = __floats2half2_rn(v.x, v.y);
    dp[1] = __floats2half2_rn(v.z, v.w);
}

// ---------------- RMSNorm -> fp16 (+optional fused MoE gate) -----------------
__global__ void rmsnorm_kernel(const float* __restrict__ x, const float* __restrict__ g,
                               __half* __restrict__ o, const float* __restrict__ gate,
                               int zcnt) {
    int t = blockIdx.x, tid = threadIdx.x;
    if (zcnt && t == 0 && tid < NE) g_cnt[tid] = 0;
    const float* xr = x + (size_t)t * DIM;
    float ss = 0.f;
    for (int i = tid; i < DIM; i += 256) { float v = xr[i]; ss += v * v; }
    #pragma unroll
    for (int o2 = 16; o2; o2 >>= 1) ss += __shfl_xor_sync(0xffffffffu, ss, o2);
    __shared__ float sw[8];
    __shared__ float sg[8][NE];
    if ((tid & 31) == 0) sw[tid >> 5] = ss;
    __syncthreads();
    if (tid < 8) {
        float v = sw[tid];
        #pragma unroll
        for (int o2 = 4; o2; o2 >>= 1) v += __shfl_xor_sync(0xffu, v, o2);
        if (tid == 0) sw[0] = v;
    }
    __syncthreads();
    float r = rsqrtf(sw[0] * (1.0f / DIM) + RMS_EPS);
    __half* orow = o + (size_t)t * DIM;
    if (!gate) {
        for (int i = tid; i < DIM; i += 256)
            orow[i] = __float2half_rn(xr[i] * r * g[i]);
        return;
    }
    float a0 = 0.f, a1 = 0.f, a2 = 0.f, a3 = 0.f;
    for (int i = tid; i < DIM; i += 256) {
        float val = xr[i] * r * g[i];
        orow[i] = __float2half_rn(val);
        const float* gr = gate + (size_t)i * NE;
        a0 += val * gr[0]; a1 += val * gr[1]; a2 += val * gr[2]; a3 += val * gr[3];
    }
    #pragma unroll
    for (int o2 = 16; o2; o2 >>= 1) {
        a0 += __shfl_xor_sync(0xffffffffu, a0, o2);
        a1 += __shfl_xor_sync(0xffffffffu, a1, o2);
        a2 += __shfl_xor_sync(0xffffffffu, a2, o2);
        a3 += __shfl_xor_sync(0xffffffffu, a3, o2);
    }
    if ((tid & 31) == 0) {
        int w = tid >> 5;
        sg[w][0] = a0; sg[w][1] = a1; sg[w][2] = a2; sg[w][3] = a3;
    }
    __syncthreads();
    if (tid == 0) {
        float p[NE];
        #pragma unroll
        for (int e = 0; e < NE; e++) {
            float s = 0.f;
            #pragma unroll
            for (int w = 0; w < 8; w++) s += sg[w][e];
            p[e] = s;
        }
        float mx = fmaxf(fmaxf(p[0], p[1]), fmaxf(p[2], p[3]));
        #pragma unroll
        for (int e = 0; e < NE; e++) p[e] = __expf(p[e] - mx);
        int e0 = 0;
        #pragma unroll
        for (int e = 1; e < NE; e++) if (p[e] > p[e0]) e0 = e;
        int e1 = -1;
        #pragma unroll
        for (int e = 0; e < NE; e++) if (e != e0 && (e1 < 0 || p[e] > p[e1])) e1 = e;
        float w0 = p[e0], w1 = p[e1], ws = p[e0] + p[e1];
        w0 /= ws; w1 /= ws;
        int s0 = atomicAdd(&g_cnt[e0], 1);
        g_idx[e0 * TOKENS + s0] = t; g_wgt[e0 * TOKENS + s0] = w0;
        int s1 = atomicAdd(&g_cnt[e1], 1);
        g_idx[e1 * TOKENS + s1] = t; g_wgt[e1 * TOKENS + s1] = w1;
    }
}

// ---------------- fp16 GEMM: 128x128x32, 3-stage, 1 sync/iter ----------------
#define TM 128
#define TN 128
#define SAB 80
#define SBB 272
#define A_STG (128 * SAB)
#define B_STG (32 * SBB)
#define STG   (A_STG + B_STG)
#define GEMM_SMEM_B (3 * STG)

// epi: 0=Cf=acc ; 1=Cf=acc+R ; 3=atomicAdd(Cf[idx],acc*w) ; 4=Ch=h(acc)
__global__ void __launch_bounds__(256, 2)
gemm16_kernel(const __half* __restrict__ A, const __half* __restrict__ B,
              float* __restrict__ Cf, __half* __restrict__ Ch,
              const float* __restrict__ R,
              int M, int N, int K,
              const int* __restrict__ cnt,
              const int* __restrict__ gidx, const float* __restrict__ gwgt,
              int epi, int gatherA,
              const __half* __restrict__ B2, const __half* __restrict__ B3,
              __half* __restrict__ Ch2, __half* __restrict__ Ch3, int qkv,
              long aStride, long bStride, long cStride) {
    int ez = blockIdx.z;
    if (cnt)  cnt  += ez;
    if (gidx) gidx += (size_t)ez * TOKENS;
    if (gwgt) gwgt += (size_t)ez * TOKENS;
    A += (size_t)ez * aStride;
    B += (size_t)ez * bStride;
    if (Cf) Cf += (size_t)ez * cStride;
    if (Ch) Ch += (size_t)ez * cStride;

    int Meff = cnt ? *cnt : M;
    int rowBase = blockIdx.y * TM;
    if (rowBase >= Meff) return;

    extern __shared__ __align__(16) char gsm[];
    unsigned sm0 = smem_u32(gsm);

    int tid  = threadIdx.x;
    int lane = tid & 31;
    int wid  = tid >> 5;
    int wm   = wid & 1;
    int wn   = wid >> 1;
    int nBase = blockIdx.x * TN;

    const __half* Bq = B; float* Cq = Cf; __half* ChR = Ch; int ld = N; int nLoc = nBase;
    if (qkv) {
        if (nBase >= 1280)      { Bq = B3; ChR = Ch3; ld = 256;  nLoc = nBase - 1280; }
        else if (nBase >= 1024) { Bq = B2; ChR = Ch2; ld = 256;  nLoc = nBase - 1024; }
        else                    {                     ld = 1024; }
    }

    float acc[4][4][4];
    #pragma unroll
    for (int i = 0; i < 4; i++)
        #pragma unroll
        for (int j = 0; j < 4; j++)
            #pragma unroll
            for (int q = 0; q < 4; q++) acc[i][j][q] = 0.f;

    const __half* aP[2]; unsigned aO[2]; int aSz[2];
    const __half* bP[2]; unsigned bO[2];
    #pragma unroll
    for (int s = 0; s < 2; s++) {
        int f = tid + s * 256;
        int ar = f >> 2, ac = f & 3;
        int row = rowBase + ar;
        bool ok = row < Meff;
        long src = 0;
        if (ok) src = gatherA ? (long)gidx[row] : (long)row;
        aP[s] = A + src * (size_t)K + ac * 8;
        aSz[s] = ok ? 16 : 0;
        aO[s] = (unsigned)(ar * SAB + ac * 16);
        int br = f >> 4, bc = f & 15;
        bP[s] = Bq + (size_t)br * ld + nLoc + bc * 8;
        bO[s] = (unsigned)(A_STG + br * SBB + bc * 16);
    }

    int nIter = K / 32;
    #pragma unroll
    for (int p = 0; p < 2; p++) {
        unsigned sb = sm0 + p * STG;
        int kt = p * 32;
        #pragma unroll
        for (int s = 0; s < 2; s++) {
            cp16(sb + aO[s], aP[s] + kt, aSz[s]);
            cp16(sb + bO[s], bP[s] + (size_t)kt * ld, 16);
        }
        cp_commit();
    }

    int rA = (lane & 7) + ((lane >> 3) & 1) * 8;
    int gA = lane >> 4;
    unsigned aLane = (unsigned)((wm * 64 + rA) * SAB + gA * 16);
    unsigned bLane = (unsigned)(A_STG + ((lane & 7) + ((lane >> 3) & 1) * 8) * SBB
                                + (wn * 32 + (lane >> 4) * 8) * 2);

    int st = 0;
    for (int it = 0; it < nIter; it++) {
        if (it + 1 < nIter) cp_wait<1>(); else cp_wait<0>();
        __syncthreads();
        unsigned sb = sm0 + st * STG;

        #pragma unroll
        for (int k16 = 0; k16 < 2; k16++) {
            unsigned bf[4][2];
            #pragma unroll
            for (int jp = 0; jp < 2; jp++) {
                unsigned b0, b1, b2, b3;
                ldsm_x4t(b0, b1, b2, b3,
                         sb + bLane + (unsigned)(k16 * 16 * SBB + jp * 32));
                bf[jp * 2][0] = b0; bf[jp * 2][1] = b1;
                bf[jp * 2 + 1][0] = b2; bf[jp * 2 + 1][1] = b3;
            }
            #pragma unroll
            for (int i = 0; i < 4; i++) {
                unsigned a0, a1, a2, a3;
                ldsm_x4(a0, a1, a2, a3,
                        sb + aLane + (unsigned)(i * 16 * SAB + k16 * 32));
                #pragma unroll
                for (int j = 0; j < 4; j++)
                    mma_f16(acc[i][j], a0, a1, a2, a3, bf[j][0], bf[j][1]);
            }
        }

        if (it + 2 < nIter) {
            unsigned sn = sm0 + ((st + 2 >= 3) ? st - 1 : st + 2) * STG;
            int kt = (it + 2) * 32;
            #pragma unroll
            for (int s = 0; s < 2; s++) {
                cp16(sn + aO[s], aP[s] + kt, aSz[s]);
                cp16(sn + bO[s], bP[s] + (size_t)kt * ld, 16);
            }
            cp_commit();
        }
        st = (st + 1 == 3) ? 0 : st + 1;
    }

    int r = lane >> 2, c = lane & 3;
    #pragma unroll
    for (int i = 0; i < 4; i++) {
        int rbase = rowBase + wm * 64 + i * 16 + r;
        #pragma unroll
        for (int half = 0; half < 2; half++) {
            int rr = rbase + half * 8;
            if (rr >= Meff) continue;
            int tok = 0; float w = 0.f;
            if (epi == 3) { tok = gidx[rr]; w = gwgt[rr]; }
            #pragma unroll
            for (int j = 0; j < 4; j++) {
                int col = nLoc + wn * 32 + j * 8 + (c << 1);
                float v0 = acc[i][j][half * 2];
                float v1 = acc[i][j][half * 2 + 1];
                if (epi == 0) {
                    *(float2*)(Cq + (size_t)rr * ld + col) = make_float2(v0, v1);
                } else if (epi == 1) {
                    float2 rv = *(const float2*)(R + (size_t)rr * ld + col);
                    *(float2*)(Cq + (size_t)rr * ld + col) =
                        make_float2(v0 + rv.x, v1 + rv.y);
                } else if (epi == 3) {
                    float* cp = Cq + (size_t)tok * ld + col;
                    atomicAdd(cp,     v0 * w);
                    atomicAdd(cp + 1, v1 * w);
                } else {
                    *(__half2*)(ChR + (size_t)rr * ld + col) = __floats2half2_rn(v0, v1);
                }
            }
        }
    }
}

// ---------------- dual GEMM: h = silu(x@w1) * (x@w3), 128x64 tile ------------
#define D_A_STG 10240                 /* 128 rows x 80B */
#define D_B_STG 4608                  /* 32 rows x 144B, per matrix */
#define D_STG (D_A_STG + 2 * D_B_STG) /* 19456 */
#define DUAL_SMEM_B (3 * D_STG)

__global__ void __launch_bounds__(256, 2)
gemm16_dual_kernel(const __half* __restrict__ A, const __half* __restrict__ B1,
                   const __half* __restrict__ B3, __half* __restrict__ H,
                   const int* __restrict__ cnt, const int* __restrict__ gidx,
                   long bStride, long hStride) {
    int ez = blockIdx.z;
    cnt  += ez;
    gidx += (size_t)ez * TOKENS;
    B1 += (size_t)ez * bStride;
    B3 += (size_t)ez * bStride;
    H  += (size_t)ez * hStride;
    int Meff = *cnt;
    int rowBase = blockIdx.y * 128;
    if (rowBase >= Meff) return;

    extern __shared__ __align__(16) char gsm[];
    unsigned sm0 = smem_u32(gsm);

    int tid  = threadIdx.x;
    int lane = tid & 31;
    int wid  = tid >> 5;
    int wm   = wid & 1;
    int wn   = wid >> 1;          // 0..3 -> 16 cols each
    int nBase = blockIdx.x * 64;

    float a1[4][2][4], a3[4][2][4];
    #pragma unroll
    for (int i = 0; i < 4; i++)
        #pragma unroll
        for (int j = 0; j < 2; j++)
            #pragma unroll
            for (int q = 0; q < 4; q++) { a1[i][j][q] = 0.f; a3[i][j][q] = 0.f; }

    const __half* aP[2]; unsigned aO[2]; int aSz[2];
    const __half* bP[2]; unsigned bO[2];
    #pragma unroll
    for (int s = 0; s < 2; s++) {
        int f = tid + s * 256;
        int ar = f >> 2, ac = f & 3;
        int row = rowBase + ar;
        bool ok = row < Meff;
        long src = 0;
        if (ok) src = (long)gidx[row];
        aP[s] = A + src * (size_t)DIM + ac * 8;
        aSz[s] = ok ? 16 : 0;
        aO[s] = (unsigned)(ar * 80 + ac * 16);
        int mat = f >> 8, fr = f & 255;
        int br = fr >> 3, bc = fr & 7;
        bP[s] = (mat ? B3 : B1) + (size_t)br * HIDDEN + nBase + bc * 8;
        bO[s] = (unsigned)(D_A_STG + mat * D_B_STG + br * 144 + bc * 16);
    }

    const int nIter = DIM / 32;   // 32
    #pragma unroll
    for (int p = 0; p < 2; p++) {
        unsigned sb = sm0 + p * D_STG;
        int kt = p * 32;
        #pragma unroll
        for (int s = 0; s < 2; s++) {
            cp16(sb + aO[s], aP[s] + kt, aSz[s]);
            cp16(sb + bO[s], bP[s] + (size_t)kt * HIDDEN, 16);
        }
        cp_commit();
    }

    int rA = (lane & 7) + ((lane >> 3) & 1) * 8;
    int gA = lane >> 4;
    unsigned aLane = (unsigned)((wm * 64 + rA) * 80 + gA * 16);
    unsigned bLane = (unsigned)(D_A_STG + rA * 144 + (wn * 16 + gA * 8) * 2);

    int st = 0;
    for (int it = 0; it < nIter; it++) {
        if (it + 1 < nIter) cp_wait<1>(); else cp_wait<0>();
        __syncthreads();
        unsigned sb = sm0 + st * D_STG;

        #pragma unroll
        for (int k16 = 0; k16 < 2; k16++) {
            unsigned bf1[2][2], bf3[2][2];
            {
                unsigned b0, b1, b2, b3;
                ldsm_x4t(b0, b1, b2, b3, sb + bLane + (unsigned)(k16 * 16 * 144));
                bf1[0][0] = b0; bf1[0][1] = b1; bf1[1][0] = b2; bf1[1][1] = b3;
                ldsm_x4t(b0, b1, b2, b3,
                         sb + bLane + (unsigned)(D_B_STG + k16 * 16 * 144));
                bf3[0][0] = b0; bf3[0][1] = b1; bf3[1][0] = b2; bf3[1][1] = b3;
            }
            #pragma unroll
            for (int i = 0; i < 4; i++) {
                unsigned x0, x1, x2, x3;
                ldsm_x4(x0, x1, x2, x3,
                        sb + aLane + (unsigned)(i * 16 * 80 + k16 * 32));
                #pragma unroll
                for (int jp = 0; jp < 2; jp++) {
                    mma_f16(a1[i][jp], x0, x1, x2, x3, bf1[jp][0], bf1[jp][1]);
                    mma_f16(a3[i][jp], x0, x1, x2, x3, bf3[jp][0], bf3[jp][1]);
                }
            }
        }

        if (it + 2 < nIter) {
            unsigned sn = sm0 + ((st + 2 >= 3) ? st - 1 : st + 2) * D_STG;
            int kt = (it + 2) * 32;
            #pragma unroll
            for (int s = 0; s < 2; s++) {
                cp16(sn + aO[s], aP[s] + kt, aSz[s]);
                cp16(sn + bO[s], bP[s] + (size_t)kt * HIDDEN, 16);
            }
            cp_commit();
        }
        st = (st + 1 == 3) ? 0 : st + 1;
    }

    int r = lane >> 2, c = lane & 3;
    #pragma unroll
    for (int i = 0; i < 4; i++) {
        int rbase = rowBase + wm * 64 + i * 16 + r;
        #pragma unroll
        for (int half = 0; half < 2; half++) {
            int rr = rbase + half * 8;
            if (rr >= Meff) continue;
            #pragma unroll
            for (int jp = 0; jp < 2; jp++) {
                int col = nBase + wn * 16 + jp * 8 + (c << 1);
                float u0 = a1[i][jp][half * 2],     u1 = a1[i][jp][half * 2 + 1];
                float v0 = a3[i][jp][half * 2],     v1 = a3[i][jp][half * 2 + 1];
                float s0 = u0 / (1.f + __expf(-u0)) * v0;
                float s1 = u1 / (1.f + __expf(-u1)) * v1;
                *(__half2*)(H + (size_t)rr * HIDDEN + col) = __floats2half2_rn(s0, s1);
            }
        }
    }
}

// ---------------- RoPE on fp16 q,k (in place) --------------------------------
__global__ void rope16_kernel(__half* __restrict__ q, __half* __restrict__ k) {
    int id = blockIdx.x * blockDim.x + threadIdx.x;
    const int NQ = TOKENS * NH * 32;
    const int NK2 = TOKENS * NKV * 32;
    if (id >= NQ + NK2) return;
    __half* base; int t, i;
    if (id < NQ) {
        t = id >> 9; int r = id & 511; int h = r >> 5; i = r & 31;
        base = q + ((size_t)t * NH + h) * HD;
    } else {
        int id2 = id - NQ;
        t = id2 >> 7; int r = id2 & 127; int h = r >> 5; i = r & 31;
        base = k + ((size_t)t * NKV + h) * HD;
    }
    int pos = t & (SEQ - 1);
    float inv = exp2f(-(float)i * 0.4152410118609203f);
    float fr = (float)pos * inv;
    float sn, cs;
    sincosf(fr, &sn, &cs);
    float x1 = __half2float(base[i]), x2 = __half2float(base[i + 32]);
    base[i]      = __float2half_rn(x1 * cs - x2 * sn);
    base[i + 32] = __float2half_rn(x2 * cs + x1 * sn);
}

// ---------------- fp16 flash attention: 128 q-rows x 64-key tiles ------------
#define HST 72
#define KOFF 0
#define VOFF (2 * 64 * HST)
#define POFF (VOFF + 2 * 64 * HST)
#define KTB  (64 * HST * 2)
#define FLASH_SMEM_B ((POFF + 128 * HST) * 2)

__global__ void __launch_bounds__(256, 1)
flash16_kernel(const __half* __restrict__ q, const __half* __restrict__ k,
               const __half* __restrict__ v, __half* __restrict__ att) {
    extern __shared__ __half hs[];
    int qi = (SEQ / 128 - 1) - blockIdx.x;
    int h = blockIdx.y, b = blockIdx.z, hk = h >> 2;
    int qbase = qi * 128;
    int tid = threadIdx.x, lane = tid & 31, w = tid >> 5;
    int lr = lane >> 2, cq = lane & 3;
    int row0 = w * 16 + lr, row1 = row0 + 8;
    unsigned base = smem_u32(hs);

    int rA = (lane & 7) + ((lane >> 3) & 1) * 8;
    int cA = ((lane >> 4) & 1) * 8;
    unsigned pLane = base + (unsigned)((POFF + (w * 16 + rA) * HST + cA) * 2);
    unsigned kLane = base + (unsigned)((KOFF + rA * HST + cA) * 2);
    int gB = lane >> 4;
    unsigned vLane = base + (unsigned)((VOFF + rA * HST + gB * 8) * 2);

    const size_t kvs = (size_t)NKV * HD;
    const __half* kb = k + ((size_t)(b * SEQ) * NKV + hk) * HD;
    const __half* vb = v + ((size_t)(b * SEQ) * NKV + hk) * HD;

    unsigned kDst[2], vDst[2]; const __half* kSrc[2]; const __half* vSrc[2];
    #pragma unroll
    for (int s = 0; s < 2; s++) {
        int idx = tid + s * 256;
        int rr = idx >> 3, cc = idx & 7;
        kDst[s] = base + (unsigned)((KOFF + rr * HST + cc * 8) * 2);
        vDst[s] = base + (unsigned)((VOFF + rr * HST + cc * 8) * 2);
        kSrc[s] = kb + (size_t)rr * kvs + cc * 8;
        vSrc[s] = vb + (size_t)rr * kvs + cc * 8;
    }

    unsigned qa[4][4];
    {
        const __half* q0 = q + ((size_t)(b * SEQ + qbase + row0) * NH + h) * HD;
        const __half* q1 = q + ((size_t)(b * SEQ + qbase + row1) * NH + h) * HD;
        __half2 sc = __float2half2_rn(0.125f);
        #pragma unroll
        for (int g = 0; g < 4; g++) {
            int kk = g * 16 + cq * 2;
            qa[g][0] = h2u(__hmul2(*(const __half2*)(q0 + kk), sc));
            qa[g][1] = h2u(__hmul2(*(const __half2*)(q1 + kk), sc));
            qa[g][2] = h2u(__hmul2(*(const __half2*)(q0 + kk + 8), sc));
            qa[g][3] = h2u(__hmul2(*(const __half2*)(q1 + kk + 8), sc));
        }
    }

    float oacc[8][4];
    #pragma unroll
    for (int nf = 0; nf < 8; nf++)
        #pragma unroll
        for (int t2 = 0; t2 < 4; t2++) oacc[nf][t2] = 0.f;
    float m0 = -3.0e38f, m1 = -3.0e38f, l0 = 0.f, l1 = 0.f;
    int nkt = 2 * qi + 2;

    #pragma unroll
    for (int s = 0; s < 2; s++) { cp16(kDst[s], kSrc[s], 16); cp16(vDst[s], vSrc[s], 16); }
    cp_commit();

    for (int kt = 0; kt < nkt; kt++) {
        int cur = kt & 1;
        __syncthreads();
        if (kt + 1 < nkt) {
            size_t off = (size_t)(kt + 1) * 64 * kvs;
            int nb = cur ^ 1;
            #pragma unroll
            for (int s = 0; s < 2; s++) {
                cp16(kDst[s] + nb * KTB, kSrc[s] + off, 16);
                cp16(vDst[s] + nb * KTB, vSrc[s] + off, 16);
            }
            cp_commit();
            cp_wait<1>();
        } else cp_wait<0>();
        __syncthreads();

        float s[8][4];
        #pragma unroll
        for (int nf = 0; nf < 8; nf++)
            #pragma unroll
            for (int t2 = 0; t2 < 4; t2++) s[nf][t2] = 0.f;
        #pragma unroll
        for (int g = 0; g < 4; g++) {
            #pragma unroll
            for (int nfp = 0; nfp < 4; nfp++) {
                unsigned b0, b1, b2, b3;
                ldsm_x4(b0, b1, b2, b3,
                        kLane + cur * KTB + (unsigned)(nfp * 16 * HST * 2 + g * 32));
                mma_f16(s[2 * nfp],     qa[g][0], qa[g][1], qa[g][2], qa[g][3], b0, b2);
                mma_f16(s[2 * nfp + 1], qa[g][0], qa[g][1], qa[g][2], qa[g][3], b1, b3);
            }
        }

        if (kt + 2 >= nkt) {
            int dk = kt * 64 - qbase;
            #pragma unroll
            for (int nf = 0; nf < 8; nf++) {
                int c0 = nf * 8 + cq * 2 + dk;
                if (c0     > row0) s[nf][0] = -3.0e38f;
                if (c0 + 1 > row0) s[nf][1] = -3.0e38f;
                if (c0     > row1) s[nf][2] = -3.0e38f;
                if (c0 + 1 > row1) s[nf][3] = -3.0e38f;
            }
        }

        float rm0 = -3.0e38f, rm1 = -3.0e38f;
        #pragma unroll
        for (int nf = 0; nf < 8; nf++) {
            rm0 = fmaxf(rm0, fmaxf(s[nf][0], s[nf][1]));
            rm1 = fmaxf(rm1, fmaxf(s[nf][2], s[nf][3]));
        }
        rm0 = fmaxf(rm0, __shfl_xor_sync(0xffffffffu, rm0, 1));
        rm0 = fmaxf(rm0, __shfl_xor_sync(0xffffffffu, rm0, 2));
        rm1 = fmaxf(rm1, __shfl_xor_sync(0xffffffffu, rm1, 1));
        rm1 = fmaxf(rm1, __shfl_xor_sync(0xffffffffu, rm1, 2));
        float mn0 = fmaxf(m0, rm0), mn1 = fmaxf(m1, rm1);
        float sc0 = __expf(m0 - mn0), sc1 = __expf(m1 - mn1);
        m0 = mn0; m1 = mn1;
        l0 *= sc0; l1 *= sc1;
        __half* Pb = hs + POFF;
        #pragma unroll
        for (int nf = 0; nf < 8; nf++) {
            float p0 = __expf(s[nf][0] - mn0), p1 = __expf(s[nf][1] - mn0);
            float p2 = __expf(s[nf][2] - mn1), p3 = __expf(s[nf][3] - mn1);
            l0 += p0 + p1; l1 += p2 + p3;
            int c0 = nf * 8 + cq * 2;
            *(__half2*)(Pb + row0 * HST + c0) = __floats2half2_rn(p0, p1);
            *(__half2*)(Pb + row1 * HST + c0) = __floats2half2_rn(p2, p3);
            oacc[nf][0] *= sc0; oacc[nf][1] *= sc0;
            oacc[nf][2] *= sc1; oacc[nf][3] *= sc1;
        }
        __syncwarp();

        #pragma unroll
        for (int g = 0; g < 4; g++) {
            unsigned a0, a1, a2, a3;
            ldsm_x4(a0, a1, a2, a3, pLane + (unsigned)(g * 32));
            #pragma unroll
            for (int jp = 0; jp < 4; jp++) {
                unsigned b0, b1, b2, b3;
                ldsm_x4t(b0, b1, b2, b3,
                         vLane + cur * KTB + (unsigned)(g * 16 * HST * 2 + jp * 32));
                mma_f16(oacc[2 * jp],     a0, a1, a2, a3, b0, b1);
                mma_f16(oacc[2 * jp + 1], a0, a1, a2, a3, b2, b3);
            }
        }
    }

    l0 += __shfl_xor_sync(0xffffffffu, l0, 1);
    l0 += __shfl_xor_sync(0xffffffffu, l0, 2);
    l1 += __shfl_xor_sync(0xffffffffu, l1, 1);
    l1 += __shfl_xor_sync(0xffffffffu, l1, 2);
    float i0 = 1.f / l0, i1 = 1.f / l1;
    __half* o0 = att + ((size_t)(b * SEQ + qbase + row0) * NH + h) * HD;
    __half* o1 = att + ((size_t)(b * SEQ + qbase + row1) * NH + h) * HD;
    #pragma unroll
    for (int nf = 0; nf < 8; nf++) {
        int c0 = nf * 8 + cq * 2;
        *(__half2*)(o0 + c0) = __floats2half2_rn(oacc[nf][0] * i0, oacc[nf][1] * i0);
        *(__half2*)(o1 + c0) = __floats2half2_rn(oacc[nf][2] * i1, oacc[nf][3] * i1);
    }
}

// ---------------- launch ------------------------------------------------------
static inline void launch_gemm(const __half* A, const __half* B, float* Cf, __half* Ch,
                               const float* R, int M, int N, int K,
                               const int* cnt, const int* gi, const float* gw,
                               int epi, int gat, int nz, long aS, long bS, long cS) {
    dim3 grid(N / TN, (M + TM - 1) / TM, nz);
    gemm16_kernel<<<grid, 256, GEMM_SMEM_B>>>(A, B, Cf, Ch, R, M, N, K, cnt, gi, gw,
                                              epi, gat, nullptr, nullptr, nullptr,
                                              nullptr, 0, aS, bS, cS);
}

extern "C" void kernel_launch(void* const* d_in, const int* in_sizes, int n_in,
                              void* d_out, int out_size) {
    const float* x    = (const float*)d_in[0];
    const float* g1   = (const float*)d_in[1];
    const float* g2   = (const float*)d_in[2];
    const float* wq   = (const float*)d_in[3];
    const float* wk   = (const float*)d_in[4];
    const float* wv   = (const float*)d_in[5];
    const float* wo   = (const float*)d_in[6];
    const float* gate = (const float*)d_in[7];
    const float* w1   = (const float*)d_in[8];
    const float* w2   = (const float*)d_in[9];
    const float* w3   = (const float*)d_in[10];
    float* out = (float*)d_out;

    __half *xn16, *att16, *h16, *q16, *k16, *v16;
    __half *wq16, *wk16, *wv16, *wo16, *w1h, *w2h, *w3h;
    float *wgt;
    int *cnt, *idx;
    cudaGetSymbolAddress((void**)&xn16,  g_xn16);
    cudaGetSymbolAddress((void**)&att16, g_att16);
    cudaGetSymbolAddress((void**)&h16,   g_h16);
    cudaGetSymbolAddress((void**)&q16, g_q16);
    cudaGetSymbolAddress((void**)&k16, g_k16);
    cudaGetSymbolAddress((void**)&v16, g_v16);
    cudaGetSymbolAddress((void**)&cnt, g_cnt);
    cudaGetSymbolAddress((void**)&idx, g_idx);
    cudaGetSymbolAddress((void**)&wgt, g_wgt);
    cudaGetSymbolAddress((void**)&wq16, g_wq16);
    cudaGetSymbolAddress((void**)&wk16, g_wk16);
    cudaGetSymbolAddress((void**)&wv16, g_wv16);
    cudaGetSymbolAddress((void**)&wo16, g_wo16);
    cudaGetSymbolAddress((void**)&w1h, g_w1h);
    cudaGetSymbolAddress((void**)&w2h, g_w2h);
    cudaGetSymbolAddress((void**)&w3h, g_w3h);

    cudaFuncSetAttribute(flash16_kernel,
                         cudaFuncAttributeMaxDynamicSharedMemorySize, FLASH_SMEM_B);
    cudaFuncSetAttribute(gemm16_kernel,
                         cudaFuncAttributeMaxDynamicSharedMemorySize, GEMM_SMEM_B);
    cudaFuncSetAttribute(gemm16_dual_kernel,
                         cudaFuncAttributeMaxDynamicSharedMemorySize, DUAL_SMEM_B);

    convall_kernel<<<(10092544 + 255) / 256, 256>>>(wq, wk, wv, wo, w1, w2, w3);
    rmsnorm_kernel<<<TOKENS, 256>>>(x, g1, xn16, nullptr, 1);
    {   // fused q/k/v (fp16 outputs)
        dim3 grid(1536 / TN, TOKENS / TM, 1);
        gemm16_kernel<<<grid, 256, GEMM_SMEM_B>>>(xn16, wq16, nullptr, q16, nullptr,
                                                  TOKENS, 1536, DIM,
                                                  nullptr, nullptr, nullptr, 4, 0,
                                                  wk16, wv16, k16, v16, 1, 0, 0, 0);
    }
    int ropeN = TOKENS * NH * 32 + TOKENS * NKV * 32;
    rope16_kernel<<<(ropeN + 255) / 256, 256>>>(q16, k16);
    {
        dim3 grid(SEQ / 128, NH, 2);
        flash16_kernel<<<grid, 256, FLASH_SMEM_B>>>(q16, k16, v16, att16);
    }
    // out = x + att @ wo
    launch_gemm(att16, wo16, out, nullptr, x, TOKENS, DIM, DIM,
                nullptr, nullptr, nullptr, 1, 0, 1, 0, 0, 0);
    // rmsnorm2 + gate
    rmsnorm_kernel<<<TOKENS, 256>>>(out, g2, xn16, gate, 0);
    // fused w1+w3 -> h16 (one launch, all experts)
    {
        dim3 grid(HIDDEN / 64, TOKENS / 128, NE);
        gemm16_dual_kernel<<<grid, 256, DUAL_SMEM_B>>>(xn16, w1h, w3h, h16, cnt, idx,
                                                       (long)DIM * HIDDEN,
                                                       (long)TOKENS * HIDDEN);
    }
    // out[tok] += (h16 @ w2) * wgt
    launch_gemm(h16, w2h, out, nullptr, nullptr, TOKENS, DIM, HIDDEN,
                cnt, idx, wgt, 3, 0, NE, (long)TOKENS * HIDDEN, (long)HIDDEN * DIM, 0);
}

// round 16
// speedup vs baseline: 13.0500x; 1.0129x over previous
#include <cuda_runtime.h>
#include <cuda_fp16.h>
#include <math.h>

#define TOKENS 4096
#define DIM    1024
#define SEQ    2048
#define NH     16
#define NKV    4
#define HD     64
#define HIDDEN 3072
#define NE     4
#define RMS_EPS 1.1920928955078125e-07f

// ---------------- scratch ----------------------------------------------------
__device__ __half g_xn16 [TOKENS * DIM];
__device__ __half g_att16[TOKENS * DIM];
__device__ __half g_h16  [NE * TOKENS * HIDDEN];
__device__ __half g_q16 [TOKENS * DIM];
__device__ __half g_k16 [TOKENS * NKV * HD];
__device__ __half g_v16 [TOKENS * NKV * HD];
__device__ int    g_cnt[NE];
__device__ int    g_idx[NE * TOKENS];
__device__ float  g_wgt[NE * TOKENS];
__device__ __half g_wq16[DIM * DIM];
__device__ __half g_wk16[DIM * NKV * HD];
__device__ __half g_wv16[DIM * NKV * HD];
__device__ __half g_wo16[DIM * DIM];
__device__ __half g_w1h [NE * DIM * HIDDEN];
__device__ __half g_w2h [NE * HIDDEN * DIM];
__device__ __half g_w3h [NE * DIM * HIDDEN];

__device__ __forceinline__ unsigned h2u(__half2 h) {
    unsigned u;
    memcpy(&u, &h, 4);
    return u;
}
__device__ __forceinline__ unsigned smem_u32(const void* p) {
    return (unsigned)__cvta_generic_to_shared(p);
}
__device__ __forceinline__ void cp16(unsigned dst, const void* src, int sz) {
    asm volatile("cp.async.cg.shared.global [%0], [%1], 16, %2;"
                 :: "r"(dst), "l"(src), "r"(sz));
}
__device__ __forceinline__ void cp_commit() {
    asm volatile("cp.async.commit_group;");
}
template<int N> __device__ __forceinline__ void cp_wait() {
    asm volatile("cp.async.wait_group %0;" :: "n"(N));
}
__device__ __forceinline__ void ldsm_x4(unsigned& r0, unsigned& r1,
                                        unsigned& r2, unsigned& r3, unsigned a) {
    asm volatile("ldmatrix.sync.aligned.m8n8.x4.shared.b16 {%0,%1,%2,%3}, [%4];"
                 : "=r"(r0), "=r"(r1), "=r"(r2), "=r"(r3) : "r"(a));
}
__device__ __forceinline__ void ldsm_x4t(unsigned& r0, unsigned& r1,
                                         unsigned& r2, unsigned& r3, unsigned a) {
    asm volatile("ldmatrix.sync.aligned.m8n8.x4.trans.shared.b16 {%0,%1,%2,%3}, [%4];"
                 : "=r"(r0), "=r"(r1), "=r"(r2), "=r"(r3) : "r"(a));
}
__device__ __forceinline__ void mma_f16(float c[4], unsigned a0, unsigned a1,
                                        unsigned a2, unsigned a3,
                                        unsigned b0, unsigned b1) {
    asm volatile("mma.sync.aligned.m16n8k16.row.col.f32.f16.f16.f32 "
        "{%0,%1,%2,%3}, {%4,%5,%6,%7}, {%8,%9}, {%0,%1,%2,%3};"
        : "+f"(c[0]), "+f"(c[1]), "+f"(c[2]), "+f"(c[3])
        : "r"(a0), "r"(a1), "r"(a2), "r"(a3), "r"(b0), "r"(b1));
}

// ---------------- fused fp32 -> fp16 weight conversion (ONE launch) ----------
__global__ void convall_kernel(const float* __restrict__ wq, const float* __restrict__ wk,
                               const float* __restrict__ wv, const float* __restrict__ wo,
                               const float* __restrict__ w1, const float* __restrict__ w2,
                               const float* __restrict__ w3) {
    long i = (long)blockIdx.x * blockDim.x + threadIdx.x;
    const float* s; __half* d; long off;
    if      (i < 262144L)  { s = wq; d = g_wq16; off = i; }
    else if (i < 327680L)  { s = wk; d = g_wk16; off = i - 262144L; }
    else if (i < 393216L)  { s = wv; d = g_wv16; off = i - 327680L; }
    else if (i < 655360L)  { s = wo; d = g_wo16; off = i - 393216L; }
    else if (i < 3801088L) { s = w1; d = g_w1h;  off = i - 655360L; }
    else if (i < 6946816L) { s = w2; d = g_w2h;  off = i - 3801088L; }
    else if (i < 10092544L){ s = w3; d = g_w3h;  off = i - 6946816L; }
    else return;
    float4 v = ((const float4*)s)[off];
    __half2* dp = (__half2*)(d + off * 4);
    dp[0] = __floats2half2_rn(v.x, v.y);
    dp[1] = __floats2half2_rn(v.z, v.w);
}

// ---------------- RMSNorm -> fp16 (+optional fused MoE gate) -----------------
__global__ void rmsnorm_kernel(const float* __restrict__ x, const float* __restrict__ g,
                               __half* __restrict__ o, const float* __restrict__ gate,
                               int zcnt) {
    int t = blockIdx.x, tid = threadIdx.x;
    if (zcnt && t == 0 && tid < NE) g_cnt[tid] = 0;
    const float* xr = x + (size_t)t * DIM;
    float ss = 0.f;
    for (int i = tid; i < DIM; i += 256) { float v = xr[i]; ss += v * v; }
    #pragma unroll
    for (int o2 = 16; o2; o2 >>= 1) ss += __shfl_xor_sync(0xffffffffu, ss, o2);
    __shared__ float sw[8];
    __shared__ float sg[8][NE];
    if ((tid & 31) == 0) sw[tid >> 5] = ss;
    __syncthreads();
    if (tid < 8) {
        float v = sw[tid];
        #pragma unroll
        for (int o2 = 4; o2; o2 >>= 1) v += __shfl_xor_sync(0xffu, v, o2);
        if (tid == 0) sw[0] = v;
    }
    __syncthreads();
    float r = rsqrtf(sw[0] * (1.0f / DIM) + RMS_EPS);
    __half* orow = o + (size_t)t * DIM;
    if (!gate) {
        for (int i = tid; i < DIM; i += 256)
            orow[i] = __float2half_rn(xr[i] * r * g[i]);
        return;
    }
    float a0 = 0.f, a1 = 0.f, a2 = 0.f, a3 = 0.f;
    for (int i = tid; i < DIM; i += 256) {
        float val = xr[i] * r * g[i];
        orow[i] = __float2half_rn(val);
        const float* gr = gate + (size_t)i * NE;
        a0 += val * gr[0]; a1 += val * gr[1]; a2 += val * gr[2]; a3 += val * gr[3];
    }
    #pragma unroll
    for (int o2 = 16; o2; o2 >>= 1) {
        a0 += __shfl_xor_sync(0xffffffffu, a0, o2);
        a1 += __shfl_xor_sync(0xffffffffu, a1, o2);
        a2 += __shfl_xor_sync(0xffffffffu, a2, o2);
        a3 += __shfl_xor_sync(0xffffffffu, a3, o2);
    }
    if ((tid & 31) == 0) {
        int w = tid >> 5;
        sg[w][0] = a0; sg[w][1] = a1; sg[w][2] = a2; sg[w][3] = a3;
    }
    __syncthreads();
    if (tid == 0) {
        float p[NE];
        #pragma unroll
        for (int e = 0; e < NE; e++) {
            float s = 0.f;
            #pragma unroll
            for (int w = 0; w < 8; w++) s += sg[w][e];
            p[e] = s;
        }
        float mx = fmaxf(fmaxf(p[0], p[1]), fmaxf(p[2], p[3]));
        #pragma unroll
        for (int e = 0; e < NE; e++) p[e] = __expf(p[e] - mx);
        int e0 = 0;
        #pragma unroll
        for (int e = 1; e < NE; e++) if (p[e] > p[e0]) e0 = e;
        int e1 = -1;
        #pragma unroll
        for (int e = 0; e < NE; e++) if (e != e0 && (e1 < 0 || p[e] > p[e1])) e1 = e;
        float w0 = p[e0], w1 = p[e1], ws = p[e0] + p[e1];
        w0 /= ws; w1 /= ws;
        int s0 = atomicAdd(&g_cnt[e0], 1);
        g_idx[e0 * TOKENS + s0] = t; g_wgt[e0 * TOKENS + s0] = w0;
        int s1 = atomicAdd(&g_cnt[e1], 1);
        g_idx[e1 * TOKENS + s1] = t; g_wgt[e1 * TOKENS + s1] = w1;
    }
}

// ---------------- fp16 GEMM: 128x128x32, 4-stage, 1 sync/iter ----------------
#define TM 128
#define TN 128
#define SAB 80
#define SBB 272
#define A_STG (128 * SAB)
#define B_STG (32 * SBB)
#define STG   (A_STG + B_STG)
#define GEMM_SMEM_B (4 * STG)

// epi: 0=Cf=acc ; 1=Cf=acc+R ; 3=atomicAdd(Cf[idx],acc*w) ; 4=Ch=h(acc)
__global__ void __launch_bounds__(256, 2)
gemm16_kernel(const __half* __restrict__ A, const __half* __restrict__ B,
              float* __restrict__ Cf, __half* __restrict__ Ch,
              const float* __restrict__ R,
              int M, int N, int K,
              const int* __restrict__ cnt,
              const int* __restrict__ gidx, const float* __restrict__ gwgt,
              int epi, int gatherA,
              const __half* __restrict__ B2, const __half* __restrict__ B3,
              __half* __restrict__ Ch2, __half* __restrict__ Ch3, int qkv,
              long aStride, long bStride, long cStride) {
    int ez = blockIdx.z;
    if (cnt)  cnt  += ez;
    if (gidx) gidx += (size_t)ez * TOKENS;
    if (gwgt) gwgt += (size_t)ez * TOKENS;
    A += (size_t)ez * aStride;
    B += (size_t)ez * bStride;
    if (Cf) Cf += (size_t)ez * cStride;
    if (Ch) Ch += (size_t)ez * cStride;

    int Meff = cnt ? *cnt : M;
    int rowBase = blockIdx.y * TM;
    if (rowBase >= Meff) return;

    extern __shared__ __align__(16) char gsm[];
    unsigned sm0 = smem_u32(gsm);

    int tid  = threadIdx.x;
    int lane = tid & 31;
    int wid  = tid >> 5;
    int wm   = wid & 1;
    int wn   = wid >> 1;
    int nBase = blockIdx.x * TN;

    const __half* Bq = B; float* Cq = Cf; __half* ChR = Ch; int ld = N; int nLoc = nBase;
    if (qkv) {
        if (nBase >= 1280)      { Bq = B3; ChR = Ch3; ld = 256;  nLoc = nBase - 1280; }
        else if (nBase >= 1024) { Bq = B2; ChR = Ch2; ld = 256;  nLoc = nBase - 1024; }
        else                    {                     ld = 1024; }
    }

    float acc[4][4][4];
    #pragma unroll
    for (int i = 0; i < 4; i++)
        #pragma unroll
        for (int j = 0; j < 4; j++)
            #pragma unroll
            for (int q = 0; q < 4; q++) acc[i][j][q] = 0.f;

    const __half* aP[2]; unsigned aO[2]; int aSz[2];
    const __half* bP[2]; unsigned bO[2];
    #pragma unroll
    for (int s = 0; s < 2; s++) {
        int f = tid + s * 256;
        int ar = f >> 2, ac = f & 3;
        int row = rowBase + ar;
        bool ok = row < Meff;
        long src = 0;
        if (ok) src = gatherA ? (long)gidx[row] : (long)row;
        aP[s] = A + src * (size_t)K + ac * 8;
        aSz[s] = ok ? 16 : 0;
        aO[s] = (unsigned)(ar * SAB + ac * 16);
        int br = f >> 4, bc = f & 15;
        bP[s] = Bq + (size_t)br * ld + nLoc + bc * 8;
        bO[s] = (unsigned)(A_STG + br * SBB + bc * 16);
    }

    int nIter = K / 32;
    #pragma unroll
    for (int p = 0; p < 3; p++) {
        if (p < nIter) {
            unsigned sb = sm0 + p * STG;
            int kt = p * 32;
            #pragma unroll
            for (int s = 0; s < 2; s++) {
                cp16(sb + aO[s], aP[s] + kt, aSz[s]);
                cp16(sb + bO[s], bP[s] + (size_t)kt * ld, 16);
            }
        }
        cp_commit();
    }

    int rA = (lane & 7) + ((lane >> 3) & 1) * 8;
    int gA = lane >> 4;
    unsigned aLane = (unsigned)((wm * 64 + rA) * SAB + gA * 16);
    unsigned bLane = (unsigned)(A_STG + ((lane & 7) + ((lane >> 3) & 1) * 8) * SBB
                                + (wn * 32 + (lane >> 4) * 8) * 2);

    int st = 0;
    for (int it = 0; it < nIter; it++) {
        cp_wait<2>();
        __syncthreads();
        unsigned sb = sm0 + st * STG;

        #pragma unroll
        for (int k16 = 0; k16 < 2; k16++) {
            unsigned bf[4][2];
            #pragma unroll
            for (int jp = 0; jp < 2; jp++) {
                unsigned b0, b1, b2, b3;
                ldsm_x4t(b0, b1, b2, b3,
                         sb + bLane + (unsigned)(k16 * 16 * SBB + jp * 32));
                bf[jp * 2][0] = b0; bf[jp * 2][1] = b1;
                bf[jp * 2 + 1][0] = b2; bf[jp * 2 + 1][1] = b3;
            }
            #pragma unroll
            for (int i = 0; i < 4; i++) {
                unsigned a0, a1, a2, a3;
                ldsm_x4(a0, a1, a2, a3,
                        sb + aLane + (unsigned)(i * 16 * SAB + k16 * 32));
                #pragma unroll
                for (int j = 0; j < 4; j++)
                    mma_f16(acc[i][j], a0, a1, a2, a3, bf[j][0], bf[j][1]);
            }
        }

        if (it + 3 < nIter) {
            unsigned sn = sm0 + ((st + 3) & 3) * STG;
            int kt = (it + 3) * 32;
            #pragma unroll
            for (int s = 0; s < 2; s++) {
                cp16(sn + aO[s], aP[s] + kt, aSz[s]);
                cp16(sn + bO[s], bP[s] + (size_t)kt * ld, 16);
            }
        }
        cp_commit();
        st = (st + 1) & 3;
    }

    int r = lane >> 2, c = lane & 3;
    #pragma unroll
    for (int i = 0; i < 4; i++) {
        int rbase = rowBase + wm * 64 + i * 16 + r;
        #pragma unroll
        for (int half = 0; half < 2; half++) {
            int rr = rbase + half * 8;
            if (rr >= Meff) continue;
            int tok = 0; float w = 0.f;
            if (epi == 3) { tok = gidx[rr]; w = gwgt[rr]; }
            #pragma unroll
            for (int j = 0; j < 4; j++) {
                int col = nLoc + wn * 32 + j * 8 + (c << 1);
                float v0 = acc[i][j][half * 2];
                float v1 = acc[i][j][half * 2 + 1];
                if (epi == 0) {
                    *(float2*)(Cq + (size_t)rr * ld + col) = make_float2(v0, v1);
                } else if (epi == 1) {
                    float2 rv = *(const float2*)(R + (size_t)rr * ld + col);
                    *(float2*)(Cq + (size_t)rr * ld + col) =
                        make_float2(v0 + rv.x, v1 + rv.y);
                } else if (epi == 3) {
                    float* cp = Cq + (size_t)tok * ld + col;
                    atomicAdd(cp,     v0 * w);
                    atomicAdd(cp + 1, v1 * w);
                } else {
                    *(__half2*)(ChR + (size_t)rr * ld + col) = __floats2half2_rn(v0, v1);
                }
            }
        }
    }
}

// ---------------- dual GEMM: h = silu(x@w1) * (x@w3), 128x64 tile, 4-stage ---
#define D_A_STG 10240
#define D_B_STG 4608
#define D_STG (D_A_STG + 2 * D_B_STG)
#define DUAL_SMEM_B (4 * D_STG)

__global__ void __launch_bounds__(256, 2)
gemm16_dual_kernel(const __half* __restrict__ A, const __half* __restrict__ B1,
                   const __half* __restrict__ B3, __half* __restrict__ H,
                   const int* __restrict__ cnt, const int* __restrict__ gidx,
                   long bStride, long hStride) {
    int ez = blockIdx.z;
    cnt  += ez;
    gidx += (size_t)ez * TOKENS;
    B1 += (size_t)ez * bStride;
    B3 += (size_t)ez * bStride;
    H  += (size_t)ez * hStride;
    int Meff = *cnt;
    int rowBase = blockIdx.y * 128;
    if (rowBase >= Meff) return;

    extern __shared__ __align__(16) char gsm[];
    unsigned sm0 = smem_u32(gsm);

    int tid  = threadIdx.x;
    int lane = tid & 31;
    int wid  = tid >> 5;
    int wm   = wid & 1;
    int wn   = wid >> 1;
    int nBase = blockIdx.x * 64;

    float a1[4][2][4], a3[4][2][4];
    #pragma unroll
    for (int i = 0; i < 4; i++)
        #pragma unroll
        for (int j = 0; j < 2; j++)
            #pragma unroll
            for (int q = 0; q < 4; q++) { a1[i][j][q] = 0.f; a3[i][j][q] = 0.f; }

    const __half* aP[2]; unsigned aO[2]; int aSz[2];
    const __half* bP[2]; unsigned bO[2];
    #pragma unroll
    for (int s = 0; s < 2; s++) {
        int f = tid + s * 256;
        int ar = f >> 2, ac = f & 3;
        int row = rowBase + ar;
        bool ok = row < Meff;
        long src = 0;
        if (ok) src = (long)gidx[row];
        aP[s] = A + src * (size_t)DIM + ac * 8;
        aSz[s] = ok ? 16 : 0;
        aO[s] = (unsigned)(ar * 80 + ac * 16);
        int mat = f >> 8, fr = f & 255;
        int br = fr >> 3, bc = fr & 7;
        bP[s] = (mat ? B3 : B1) + (size_t)br * HIDDEN + nBase + bc * 8;
        bO[s] = (unsigned)(D_A_STG + mat * D_B_STG + br * 144 + bc * 16);
    }

    const int nIter = DIM / 32;
    #pragma unroll
    for (int p = 0; p < 3; p++) {
        unsigned sb = sm0 + p * D_STG;
        int kt = p * 32;
        #pragma unroll
        for (int s = 0; s < 2; s++) {
            cp16(sb + aO[s], aP[s] + kt, aSz[s]);
            cp16(sb + bO[s], bP[s] + (size_t)kt * HIDDEN, 16);
        }
        cp_commit();
    }

    int rA = (lane & 7) + ((lane >> 3) & 1) * 8;
    int gA = lane >> 4;
    unsigned aLane = (unsigned)((wm * 64 + rA) * 80 + gA * 16);
    unsigned bLane = (unsigned)(D_A_STG + rA * 144 + (wn * 16 + gA * 8) * 2);

    int st = 0;
    for (int it = 0; it < nIter; it++) {
        cp_wait<2>();
        __syncthreads();
        unsigned sb = sm0 + st * D_STG;

        #pragma unroll
        for (int k16 = 0; k16 < 2; k16++) {
            unsigned bf1[2][2], bf3[2][2];
            {
                unsigned b0, b1, b2, b3;
                ldsm_x4t(b0, b1, b2, b3, sb + bLane + (unsigned)(k16 * 16 * 144));
                bf1[0][0] = b0; bf1[0][1] = b1; bf1[1][0] = b2; bf1[1][1] = b3;
                ldsm_x4t(b0, b1, b2, b3,
                         sb + bLane + (unsigned)(D_B_STG + k16 * 16 * 144));
                bf3[0][0] = b0; bf3[0][1] = b1; bf3[1][0] = b2; bf3[1][1] = b3;
            }
            #pragma unroll
            for (int i = 0; i < 4; i++) {
                unsigned x0, x1, x2, x3;
                ldsm_x4(x0, x1, x2, x3,
                        sb + aLane + (unsigned)(i * 16 * 80 + k16 * 32));
                #pragma unroll
                for (int jp = 0; jp < 2; jp++) {
                    mma_f16(a1[i][jp], x0, x1, x2, x3, bf1[jp][0], bf1[jp][1]);
                    mma_f16(a3[i][jp], x0, x1, x2, x3, bf3[jp][0], bf3[jp][1]);
                }
            }
        }

        if (it + 3 < nIter) {
            unsigned sn = sm0 + ((st + 3) & 3) * D_STG;
            int kt = (it + 3) * 32;
            #pragma unroll
            for (int s = 0; s < 2; s++) {
                cp16(sn + aO[s], aP[s] + kt, aSz[s]);
                cp16(sn + bO[s], bP[s] + (size_t)kt * HIDDEN, 16);
            }
        }
        cp_commit();
        st = (st + 1) & 3;
    }

    int r = lane >> 2, c = lane & 3;
    #pragma unroll
    for (int i = 0; i < 4; i++) {
        int rbase = rowBase + wm * 64 + i * 16 + r;
        #pragma unroll
        for (int half = 0; half < 2; half++) {
            int rr = rbase + half * 8;
            if (rr >= Meff) continue;
            #pragma unroll
            for (int jp = 0; jp < 2; jp++) {
                int col = nBase + wn * 16 + jp * 8 + (c << 1);
                float u0 = a1[i][jp][half * 2],     u1 = a1[i][jp][half * 2 + 1];
                float v0 = a3[i][jp][half * 2],     v1 = a3[i][jp][half * 2 + 1];
                float s0 = u0 / (1.f + __expf(-u0)) * v0;
                float s1 = u1 / (1.f + __expf(-u1)) * v1;
                *(__half2*)(H + (size_t)rr * HIDDEN + col) = __floats2half2_rn(s0, s1);
            }
        }
    }
}

// ---------------- RoPE on fp16 q,k (in place) --------------------------------
__global__ void rope16_kernel(__half* __restrict__ q, __half* __restrict__ k) {
    int id = blockIdx.x * blockDim.x + threadIdx.x;
    const int NQ = TOKENS * NH * 32;
    const int NK2 = TOKENS * NKV * 32;
    if (id >= NQ + NK2) return;
    __half* base; int t, i;
    if (id < NQ) {
        t = id >> 9; int r = id & 511; int h = r >> 5; i = r & 31;
        base = q + ((size_t)t * NH + h) * HD;
    } else {
        int id2 = id - NQ;
        t = id2 >> 7; int r = id2 & 127; int h = r >> 5; i = r & 31;
        base = k + ((size_t)t * NKV + h) * HD;
    }
    int pos = t & (SEQ - 1);
    float inv = exp2f(-(float)i * 0.4152410118609203f);
    float fr = (float)pos * inv;
    float sn, cs;
    sincosf(fr, &sn, &cs);
    float x1 = __half2float(base[i]), x2 = __half2float(base[i + 32]);
    base[i]      = __float2half_rn(x1 * cs - x2 * sn);
    base[i + 32] = __float2half_rn(x2 * cs + x1 * sn);
}

// ---------------- fp16 flash attention: 128 q-rows x 64-key tiles ------------
#define HST 72
#define KOFF 0
#define VOFF (2 * 64 * HST)
#define POFF (VOFF + 2 * 64 * HST)
#define KTB  (64 * HST * 2)
#define FLASH_SMEM_B ((POFF + 128 * HST) * 2)

__global__ void __launch_bounds__(256, 2)
flash16_kernel(const __half* __restrict__ q, const __half* __restrict__ k,
               const __half* __restrict__ v, __half* __restrict__ att) {
    extern __shared__ __half hs[];
    int qi = (SEQ / 128 - 1) - blockIdx.x;
    int h = blockIdx.y, b = blockIdx.z, hk = h >> 2;
    int qbase = qi * 128;
    int tid = threadIdx.x, lane = tid & 31, w = tid >> 5;
    int lr = lane >> 2, cq = lane & 3;
    int row0 = w * 16 + lr, row1 = row0 + 8;
    unsigned base = smem_u32(hs);

    int rA = (lane & 7) + ((lane >> 3) & 1) * 8;
    int cA = ((lane >> 4) & 1) * 8;
    unsigned pLane = base + (unsigned)((POFF + (w * 16 + rA) * HST + cA) * 2);
    unsigned kLane = base + (unsigned)((KOFF + rA * HST + cA) * 2);
    int gB = lane >> 4;
    unsigned vLane = base + (unsigned)((VOFF + rA * HST + gB * 8) * 2);

    const size_t kvs = (size_t)NKV * HD;
    const __half* kb = k + ((size_t)(b * SEQ) * NKV + hk) * HD;
    const __half* vb = v + ((size_t)(b * SEQ) * NKV + hk) * HD;

    unsigned kDst[2], vDst[2]; const __half* kSrc[2]; const __half* vSrc[2];
    #pragma unroll
    for (int s = 0; s < 2; s++) {
        int idx = tid + s * 256;
        int rr = idx >> 3, cc = idx & 7;
        kDst[s] = base + (unsigned)((KOFF + rr * HST + cc * 8) * 2);
        vDst[s] = base + (unsigned)((VOFF + rr * HST + cc * 8) * 2);
        kSrc[s] = kb + (size_t)rr * kvs + cc * 8;
        vSrc[s] = vb + (size_t)rr * kvs + cc * 8;
    }

    unsigned qa[4][4];
    {
        const __half* q0 = q + ((size_t)(b * SEQ + qbase + row0) * NH + h) * HD;
        const __half* q1 = q + ((size_t)(b * SEQ + qbase + row1) * NH + h) * HD;
        __half2 sc = __float2half2_rn(0.125f);
        #pragma unroll
        for (int g = 0; g < 4; g++) {
            int kk = g * 16 + cq * 2;
            qa[g][0] = h2u(__hmul2(*(const __half2*)(q0 + kk), sc));
            qa[g][1] = h2u(__hmul2(*(const __half2*)(q1 + kk), sc));
            qa[g][2] = h2u(__hmul2(*(const __half2*)(q0 + kk + 8), sc));
            qa[g][3] = h2u(__hmul2(*(const __half2*)(q1 + kk + 8), sc));
        }
    }

    float oacc[8][4];
    #pragma unroll
    for (int nf = 0; nf < 8; nf++)
        #pragma unroll
        for (int t2 = 0; t2 < 4; t2++) oacc[nf][t2] = 0.f;
    float m0 = -3.0e38f, m1 = -3.0e38f, l0 = 0.f, l1 = 0.f;
    int nkt = 2 * qi + 2;

    #pragma unroll
    for (int s = 0; s < 2; s++) { cp16(kDst[s], kSrc[s], 16); cp16(vDst[s], vSrc[s], 16); }
    cp_commit();

    for (int kt = 0; kt < nkt; kt++) {
        int cur = kt & 1;
        __syncthreads();
        if (kt + 1 < nkt) {
            size_t off = (size_t)(kt + 1) * 64 * kvs;
            int nb = cur ^ 1;
            #pragma unroll
            for (int s = 0; s < 2; s++) {
                cp16(kDst[s] + nb * KTB, kSrc[s] + off, 16);
                cp16(vDst[s] + nb * KTB, vSrc[s] + off, 16);
            }
            cp_commit();
            cp_wait<1>();
        } else cp_wait<0>();
        __syncthreads();

        float s[8][4];
        #pragma unroll
        for (int nf = 0; nf < 8; nf++)
            #pragma unroll
            for (int t2 = 0; t2 < 4; t2++) s[nf][t2] = 0.f;
        #pragma unroll
        for (int g = 0; g < 4; g++) {
            #pragma unroll
            for (int nfp = 0; nfp < 4; nfp++) {
                unsigned b0, b1, b2, b3;
                ldsm_x4(b0, b1, b2, b3,
                        kLane + cur * KTB + (unsigned)(nfp * 16 * HST * 2 + g * 32));
                mma_f16(s[2 * nfp],     qa[g][0], qa[g][1], qa[g][2], qa[g][3], b0, b2);
                mma_f16(s[2 * nfp + 1], qa[g][0], qa[g][1], qa[g][2], qa[g][3], b1, b3);
            }
        }

        if (kt + 2 >= nkt) {
            int dk = kt * 64 - qbase;
            #pragma unroll
            for (int nf = 0; nf < 8; nf++) {
                int c0 = nf * 8 + cq * 2 + dk;
                if (c0     > row0) s[nf][0] = -3.0e38f;
                if (c0 + 1 > row0) s[nf][1] = -3.0e38f;
                if (c0     > row1) s[nf][2] = -3.0e38f;
                if (c0 + 1 > row1) s[nf][3] = -3.0e38f;
            }
        }

        float rm0 = -3.0e38f, rm1 = -3.0e38f;
        #pragma unroll
        for (int nf = 0; nf < 8; nf++) {
            rm0 = fmaxf(rm0, fmaxf(s[nf][0], s[nf][1]));
            rm1 = fmaxf(rm1, fmaxf(s[nf][2], s[nf][3]));
        }
        rm0 = fmaxf(rm0, __shfl_xor_sync(0xffffffffu, rm0, 1));
        rm0 = fmaxf(rm0, __shfl_xor_sync(0xffffffffu, rm0, 2));
        rm1 = fmaxf(rm1, __shfl_xor_sync(0xffffffffu, rm1, 1));
        rm1 = fmaxf(rm1, __shfl_xor_sync(0xffffffffu, rm1, 2));
        float mn0 = fmaxf(m0, rm0), mn1 = fmaxf(m1, rm1);
        float sc0 = __expf(m0 - mn0), sc1 = __expf(m1 - mn1);
        m0 = mn0; m1 = mn1;
        l0 *= sc0; l1 *= sc1;
        __half* Pb = hs + POFF;
        #pragma unroll
        for (int nf = 0; nf < 8; nf++) {
            float p0 = __expf(s[nf][0] - mn0), p1 = __expf(s[nf][1] - mn0);
            float p2 = __expf(s[nf][2] - mn1), p3 = __expf(s[nf][3] - mn1);
            l0 += p0 + p1; l1 += p2 + p3;
            int c0 = nf * 8 + cq * 2;
            *(__half2*)(Pb + row0 * HST + c0) = __floats2half2_rn(p0, p1);
            *(__half2*)(Pb + row1 * HST + c0) = __floats2half2_rn(p2, p3);
            oacc[nf][0] *= sc0; oacc[nf][1] *= sc0;
            oacc[nf][2] *= sc1; oacc[nf][3] *= sc1;
        }
        __syncwarp();

        #pragma unroll
        for (int g = 0; g < 4; g++) {
            unsigned a0, a1, a2, a3;
            ldsm_x4(a0, a1, a2, a3, pLane + (unsigned)(g * 32));
            #pragma unroll
            for (int jp = 0; jp < 4; jp++) {
                unsigned b0, b1, b2, b3;
                ldsm_x4t(b0, b1, b2, b3,
                         vLane + cur * KTB + (unsigned)(g * 16 * HST * 2 + jp * 32));
                mma_f16(oacc[2 * jp],     a0, a1, a2, a3, b0, b1);
                mma_f16(oacc[2 * jp + 1], a0, a1, a2, a3, b2, b3);
            }
        }
    }

    l0 += __shfl_xor_sync(0xffffffffu, l0, 1);
    l0 += __shfl_xor_sync(0xffffffffu, l0, 2);
    l1 += __shfl_xor_sync(0xffffffffu, l1, 1);
    l1 += __shfl_xor_sync(0xffffffffu, l1, 2);
    float i0 = 1.f / l0, i1 = 1.f / l1;
    __half* o0 = att + ((size_t)(b * SEQ + qbase + row0) * NH + h) * HD;
    __half* o1 = att + ((size_t)(b * SEQ + qbase + row1) * NH + h) * HD;
    #pragma unroll
    for (int nf = 0; nf < 8; nf++) {
        int c0 = nf * 8 + cq * 2;
        *(__half2*)(o0 + c0) = __floats2half2_rn(oacc[nf][0] * i0, oacc[nf][1] * i0);
        *(__half2*)(o1 + c0) = __floats2half2_rn(oacc[nf][2] * i1, oacc[nf][3] * i1);
    }
}

// ---------------- launch ------------------------------------------------------
static inline void launch_gemm(const __half* A, const __half* B, float* Cf, __half* Ch,
                               const float* R, int M, int N, int K,
                               const int* cnt, const int* gi, const float* gw,
                               int epi, int gat, int nz, long aS, long bS, long cS) {
    dim3 grid(N / TN, (M + TM - 1) / TM, nz);
    gemm16_kernel<<<grid, 256, GEMM_SMEM_B>>>(A, B, Cf, Ch, R, M, N, K, cnt, gi, gw,
                                              epi, gat, nullptr, nullptr, nullptr,
                                              nullptr, 0, aS, bS, cS);
}

extern "C" void kernel_launch(void* const* d_in, const int* in_sizes, int n_in,
                              void* d_out, int out_size) {
    const float* x    = (const float*)d_in[0];
    const float* g1   = (const float*)d_in[1];
    const float* g2   = (const float*)d_in[2];
    const float* wq   = (const float*)d_in[3];
    const float* wk   = (const float*)d_in[4];
    const float* wv   = (const float*)d_in[5];
    const float* wo   = (const float*)d_in[6];
    const float* gate = (const float*)d_in[7];
    const float* w1   = (const float*)d_in[8];
    const float* w2   = (const float*)d_in[9];
    const float* w3   = (const float*)d_in[10];
    float* out = (float*)d_out;

    __half *xn16, *att16, *h16, *q16, *k16, *v16;
    __half *wq16, *wk16, *wv16, *wo16, *w1h, *w2h, *w3h;
    float *wgt;
    int *cnt, *idx;
    cudaGetSymbolAddress((void**)&xn16,  g_xn16);
    cudaGetSymbolAddress((void**)&att16, g_att16);
    cudaGetSymbolAddress((void**)&h16,   g_h16);
    cudaGetSymbolAddress((void**)&q16, g_q16);
    cudaGetSymbolAddress((void**)&k16, g_k16);
    cudaGetSymbolAddress((void**)&v16, g_v16);
    cudaGetSymbolAddress((void**)&cnt, g_cnt);
    cudaGetSymbolAddress((void**)&idx, g_idx);
    cudaGetSymbolAddress((void**)&wgt, g_wgt);
    cudaGetSymbolAddress((void**)&wq16, g_wq16);
    cudaGetSymbolAddress((void**)&wk16, g_wk16);
    cudaGetSymbolAddress((void**)&wv16, g_wv16);
    cudaGetSymbolAddress((void**)&wo16, g_wo16);
    cudaGetSymbolAddress((void**)&w1h, g_w1h);
    cudaGetSymbolAddress((void**)&w2h, g_w2h);
    cudaGetSymbolAddress((void**)&w3h, g_w3h);

    cudaFuncSetAttribute(flash16_kernel,
                         cudaFuncAttributeMaxDynamicSharedMemorySize, FLASH_SMEM_B);
    cudaFuncSetAttribute(gemm16_kernel,
                         cudaFuncAttributeMaxDynamicSharedMemorySize, GEMM_SMEM_B);
    cudaFuncSetAttribute(gemm16_dual_kernel,
                         cudaFuncAttributeMaxDynamicSharedMemorySize, DUAL_SMEM_B);

    convall_kernel<<<(10092544 + 255) / 256, 256>>>(wq, wk, wv, wo, w1, w2, w3);
    rmsnorm_kernel<<<TOKENS, 256>>>(x, g1, xn16, nullptr, 1);
    {   // fused q/k/v (fp16 outputs)
        dim3 grid(1536 / TN, TOKENS / TM, 1);
        gemm16_kernel<<<grid, 256, GEMM_SMEM_B>>>(xn16, wq16, nullptr, q16, nullptr,
                                                  TOKENS, 1536, DIM,
                                                  nullptr, nullptr, nullptr, 4, 0,
                                                  wk16, wv16, k16, v16, 1, 0, 0, 0);
    }
    int ropeN = TOKENS * NH * 32 + TOKENS * NKV * 32;
    rope16_kernel<<<(ropeN + 255) / 256, 256>>>(q16, k16);
    {
        dim3 grid(SEQ / 128, NH, 2);
        flash16_kernel<<<grid, 256, FLASH_SMEM_B>>>(q16, k16, v16, att16);
    }
    // out = x + att @ wo
    launch_gemm(att16, wo16, out, nullptr, x, TOKENS, DIM, DIM,
                nullptr, nullptr, nullptr, 1, 0, 1, 0, 0, 0);
    // rmsnorm2 + gate
    rmsnorm_kernel<<<TOKENS, 256>>>(out, g2, xn16, gate, 0);
    // fused w1+w3 -> h16 (one launch, all experts)
    {
        dim3 grid(HIDDEN / 64, TOKENS / 128, NE);
        gemm16_dual_kernel<<<grid, 256, DUAL_SMEM_B>>>(xn16, w1h, w3h, h16, cnt, idx,
                                                       (long)DIM * HIDDEN,
                                                       (long)TOKENS * HIDDEN);
    }
    // out[tok] += (h16 @ w2) * wgt
    launch_gemm(h16, w2h, out, nullptr, nullptr, TOKENS, DIM, HIDDEN,
                cnt, idx, wgt, 3, 0, NE, (long)TOKENS * HIDDEN, (long)HIDDEN * DIM, 0);
}